// round 1
// baseline (speedup 1.0000x reference)
#include <cuda_runtime.h>
#include <cuda_bf16.h>
#include <math.h>

// Problem constants (fixed by setup_inputs)
#define L_TOK   3072
#define DIM_C   1536
#define HEADS_C 12
#define HD_C    128
#define FS_C    384      // H*W frame size
#define W_C     24
#define NQBLK   48       // 3072/64
#define EPS_C   1e-6f

// ---------------- scratch ----------------
__device__ float g_q [L_TOK * DIM_C];
__device__ float g_k [L_TOK * DIM_C];
__device__ float g_v [L_TOK * DIM_C];
__device__ float g_ao[L_TOK * DIM_C];

// ---------------- GEMM: C = A @ W^T + bias  (A[M,K], W[N,K], row-major) ----
#define GBM 128
#define GBN 64
#define GBK 16

__global__ __launch_bounds__(256) void gemm_nt_bias(
    const float* __restrict__ A, const float* __restrict__ W,
    const float* __restrict__ bias, float* __restrict__ C,
    int M, int N, int K)
{
    __shared__ float As[GBK][GBM + 4];
    __shared__ float Ws[GBK][GBN + 4];
    const int bm = blockIdx.y * GBM;
    const int bn = blockIdx.x * GBN;
    const int tid = threadIdx.x;
    const int ty = tid >> 4, tx = tid & 15;

    float acc[8][4];
#pragma unroll
    for (int r = 0; r < 8; r++)
#pragma unroll
        for (int c = 0; c < 4; c++) acc[r][c] = 0.f;

    for (int k0 = 0; k0 < K; k0 += GBK) {
        // A tile 128x16 -> 512 float4, 2 per thread
#pragma unroll
        for (int j = 0; j < 2; j++) {
            int idx = tid + j * 256;
            int m  = idx >> 2;
            int k4 = (idx & 3) << 2;
            float4 v = *(const float4*)&A[(size_t)(bm + m) * K + k0 + k4];
            As[k4 + 0][m] = v.x; As[k4 + 1][m] = v.y;
            As[k4 + 2][m] = v.z; As[k4 + 3][m] = v.w;
        }
        { // W tile 64x16 -> 256 float4, 1 per thread
            int m  = tid >> 2;
            int k4 = (tid & 3) << 2;
            float4 v = *(const float4*)&W[(size_t)(bn + m) * K + k0 + k4];
            Ws[k4 + 0][m] = v.x; Ws[k4 + 1][m] = v.y;
            Ws[k4 + 2][m] = v.z; Ws[k4 + 3][m] = v.w;
        }
        __syncthreads();
#pragma unroll
        for (int kk = 0; kk < GBK; kk++) {
            float a[8], b[4];
#pragma unroll
            for (int r = 0; r < 8; r++) a[r] = As[kk][ty * 8 + r];
#pragma unroll
            for (int c = 0; c < 4; c++) b[c] = Ws[kk][tx * 4 + c];
#pragma unroll
            for (int r = 0; r < 8; r++)
#pragma unroll
                for (int c = 0; c < 4; c++) acc[r][c] += a[r] * b[c];
        }
        __syncthreads();
    }
#pragma unroll
    for (int r = 0; r < 8; r++) {
        int m = bm + ty * 8 + r;
#pragma unroll
        for (int c = 0; c < 4; c++) {
            int n = bn + tx * 4 + c;
            C[(size_t)m * N + n] = acc[r][c] + bias[n];
        }
    }
}

// ---------------- fused RMSNorm + RoPE for Q and K ----------------
__global__ __launch_bounds__(256) void normrope_kernel(
    float* __restrict__ q, float* __restrict__ k,
    const float* __restrict__ freqs,
    const float* __restrict__ nqw, const float* __restrict__ nkw)
{
    const int t = blockIdx.x;                  // token index
    const int f  = t / FS_C;
    const int rm = t % FS_C;
    const int hh = rm / W_C;
    const int ww = rm % W_C;
    const int tid = threadIdx.x;

    __shared__ float fr[64], fi[64];
    __shared__ float buf[DIM_C];
    __shared__ float red[8];

    if (tid < 64) {
        int c = tid;
        int row = (c < 22) ? f : ((c < 43) ? hh : ww);
        fr[c] = freqs[row * 128 + c * 2 + 0];
        fi[c] = freqs[row * 128 + c * 2 + 1];
    }

    for (int which = 0; which < 2; which++) {
        float* ptr = which ? k : q;
        const float* w = which ? nkw : nqw;

        float ss = 0.f;
        for (int i = tid; i < DIM_C; i += 256) {
            float v = ptr[(size_t)t * DIM_C + i];
            buf[i] = v;
            ss += v * v;
        }
        // block reduce (also orders buf/fr writes before use)
        __syncthreads();
        {
            int lane = tid & 31, wid = tid >> 5;
#pragma unroll
            for (int o = 16; o > 0; o >>= 1) ss += __shfl_xor_sync(0xffffffffu, ss, o);
            if (lane == 0) red[wid] = ss;
        }
        __syncthreads();
        float tot;
        {
            float v = (tid < 8) ? red[tid] : 0.f;
            if (tid < 32) {
#pragma unroll
                for (int o = 4; o > 0; o >>= 1) v += __shfl_xor_sync(0xffffffffu, v, o);
                if (tid == 0) red[0] = v;
            }
        }
        __syncthreads();
        tot = red[0];
        float rn = rsqrtf(tot * (1.0f / DIM_C) + EPS_C);

        // RoPE over 768 pairs
        for (int p = tid; p < 768; p += 256) {
            int c = p & 63;
            float a = buf[2 * p]     * rn * w[2 * p];
            float b = buf[2 * p + 1] * rn * w[2 * p + 1];
            ptr[(size_t)t * DIM_C + 2 * p]     = a * fr[c] - b * fi[c];
            ptr[(size_t)t * DIM_C + 2 * p + 1] = a * fi[c] + b * fr[c];
        }
        __syncthreads();   // protect buf/red before next iteration
    }
}

// ---------------- flash attention (frame-block causal, no per-elem mask) ----
#define QS_STRIDE 68
#define VS_STRIDE 132
#define PS_STRIDE 72
#define ATTN_SMEM_FLOATS (128 * QS_STRIDE + 128 * QS_STRIDE + 64 * PS_STRIDE)
#define ATTN_SMEM_BYTES  (ATTN_SMEM_FLOATS * 4)

__global__ __launch_bounds__(256) void attn_kernel(
    const float* __restrict__ Q, const float* __restrict__ K,
    const float* __restrict__ V, float* __restrict__ O)
{
    extern __shared__ float smem[];
    float* Qs  = smem;                      // [128][68] transposed: Qs[d*68 + q]
    float* KVs = Qs + 128 * QS_STRIDE;      // K: [d*68 + k]; later V: [k*132 + d]
    float* Ps  = KVs + 128 * QS_STRIDE;     // [64][72]

    const int qb = blockIdx.x, h = blockIdx.y;
    const int q0 = qb * 64;
    const int qf = q0 / FS_C;
    const int tid = threadIdx.x;
    const int ty = tid >> 4, tx = tid & 15;
    const float scale = 0.08838834764831844f;   // 1/sqrt(128)

    for (int i = tid; i < 64 * 128; i += 256) {
        int r = i >> 7, c = i & 127;
        Qs[c * QS_STRIDE + r] = Q[(size_t)(q0 + r) * DIM_C + h * HD_C + c];
    }

    float mrow[4], lrow[4], acc[4][8];
#pragma unroll
    for (int r = 0; r < 4; r++) {
        mrow[r] = -1e30f; lrow[r] = 0.f;
#pragma unroll
        for (int c = 0; c < 8; c++) acc[r][c] = 0.f;
    }

    const int sinkT     = (qf >= 5) ? 6 : 0;
    const int mainFirst = (qf >= 5) ? (qf - 4) * 6 : 0;
    const int mainT     = (qf >= 5) ? 30 : (qf + 1) * 6;
    const int nt = sinkT + mainT;

    for (int t = 0; t < nt; t++) {
        const int kt = (t < sinkT) ? t : mainFirst + (t - sinkT);
        const int k0 = kt * 64;

        __syncthreads();   // prior tile fully consumed
        for (int i = tid; i < 64 * 128; i += 256) {
            int r = i >> 7, c = i & 127;
            KVs[c * QS_STRIDE + r] = K[(size_t)(k0 + r) * DIM_C + h * HD_C + c];
        }
        __syncthreads();

        // S = Q K^T  (4x4 microtile per thread)
        float s[4][4];
#pragma unroll
        for (int r = 0; r < 4; r++)
#pragma unroll
            for (int c = 0; c < 4; c++) s[r][c] = 0.f;

#pragma unroll 4
        for (int kk = 0; kk < 128; kk++) {
            float4 a = *(const float4*)&Qs [kk * QS_STRIDE + ty * 4];
            float4 b = *(const float4*)&KVs[kk * QS_STRIDE + tx * 4];
            float av[4] = {a.x, a.y, a.z, a.w};
            float bv[4] = {b.x, b.y, b.z, b.w};
#pragma unroll
            for (int r = 0; r < 4; r++)
#pragma unroll
                for (int c = 0; c < 4; c++) s[r][c] += av[r] * bv[c];
        }

        // online softmax per row
#pragma unroll
        for (int r = 0; r < 4; r++) {
#pragma unroll
            for (int c = 0; c < 4; c++) s[r][c] *= scale;
            float rmax = fmaxf(fmaxf(s[r][0], s[r][1]), fmaxf(s[r][2], s[r][3]));
#pragma unroll
            for (int o = 8; o > 0; o >>= 1)
                rmax = fmaxf(rmax, __shfl_xor_sync(0xffffffffu, rmax, o));
            float mnew = fmaxf(mrow[r], rmax);
            float alpha = __expf(mrow[r] - mnew);
            mrow[r] = mnew;
            float rs = 0.f;
#pragma unroll
            for (int c = 0; c < 4; c++) {
                float p = __expf(s[r][c] - mnew);
                Ps[(ty * 4 + r) * PS_STRIDE + tx * 4 + c] = p;
                rs += p;
            }
#pragma unroll
            for (int o = 8; o > 0; o >>= 1)
                rs += __shfl_xor_sync(0xffffffffu, rs, o);
            lrow[r] = lrow[r] * alpha + rs;
#pragma unroll
            for (int c = 0; c < 8; c++) acc[r][c] *= alpha;
        }
        __syncthreads();   // Ps visible; done reading K from KVs

        // load V (row-major)
        for (int i = tid; i < 64 * 128; i += 256) {
            int r = i >> 7, c = i & 127;
            KVs[r * VS_STRIDE + c] = V[(size_t)(k0 + r) * DIM_C + h * HD_C + c];
        }
        __syncthreads();

        // O += P V
#pragma unroll 4
        for (int j = 0; j < 64; j++) {
            float4 v0 = *(const float4*)&KVs[j * VS_STRIDE + tx * 8];
            float4 v1 = *(const float4*)&KVs[j * VS_STRIDE + tx * 8 + 4];
#pragma unroll
            for (int r = 0; r < 4; r++) {
                float p = Ps[(ty * 4 + r) * PS_STRIDE + j];
                acc[r][0] += p * v0.x; acc[r][1] += p * v0.y;
                acc[r][2] += p * v0.z; acc[r][3] += p * v0.w;
                acc[r][4] += p * v1.x; acc[r][5] += p * v1.y;
                acc[r][6] += p * v1.z; acc[r][7] += p * v1.w;
            }
        }
    }

#pragma unroll
    for (int r = 0; r < 4; r++) {
        float inv = 1.f / lrow[r];
#pragma unroll
        for (int c = 0; c < 8; c++) {
            O[(size_t)(q0 + ty * 4 + r) * DIM_C + h * HD_C + tx * 8 + c] = acc[r][c] * inv;
        }
    }
}

// ---------------- launch ----------------
extern "C" void kernel_launch(void* const* d_in, const int* in_sizes, int n_in,
                              void* d_out, int out_size)
{
    const float* x     = (const float*)d_in[0];
    const float* freqs = (const float*)d_in[3];
    const float* wq    = (const float*)d_in[4];
    const float* bq    = (const float*)d_in[5];
    const float* wk    = (const float*)d_in[6];
    const float* bk    = (const float*)d_in[7];
    const float* wv    = (const float*)d_in[8];
    const float* bv    = (const float*)d_in[9];
    const float* wo    = (const float*)d_in[10];
    const float* bo    = (const float*)d_in[11];
    const float* nqw   = (const float*)d_in[12];
    const float* nkw   = (const float*)d_in[13];
    float* out = (float*)d_out;

    float *gq, *gk, *gv, *gao;
    cudaGetSymbolAddress((void**)&gq,  g_q);
    cudaGetSymbolAddress((void**)&gk,  g_k);
    cudaGetSymbolAddress((void**)&gv,  g_v);
    cudaGetSymbolAddress((void**)&gao, g_ao);

    cudaFuncSetAttribute(attn_kernel,
                         cudaFuncAttributeMaxDynamicSharedMemorySize,
                         ATTN_SMEM_BYTES);

    dim3 ggrid(DIM_C / GBN, L_TOK / GBM);   // (24, 24)
    gemm_nt_bias<<<ggrid, 256>>>(x, wq, bq, gq, L_TOK, DIM_C, DIM_C);
    gemm_nt_bias<<<ggrid, 256>>>(x, wk, bk, gk, L_TOK, DIM_C, DIM_C);
    gemm_nt_bias<<<ggrid, 256>>>(x, wv, bv, gv, L_TOK, DIM_C, DIM_C);

    normrope_kernel<<<L_TOK, 256>>>(gq, gk, freqs, nqw, nkw);

    attn_kernel<<<dim3(NQBLK, HEADS_C), 256, ATTN_SMEM_BYTES>>>(gq, gk, gv, gao);

    gemm_nt_bias<<<ggrid, 256>>>(gao, wo, bo, out, L_TOK, DIM_C, DIM_C);
}

// round 2
// speedup vs baseline: 1.4355x; 1.4355x over previous
#include <cuda_runtime.h>
#include <cuda_bf16.h>
#include <math.h>
#include <stdint.h>

// Problem constants (fixed by setup_inputs)
#define L_TOK   3072
#define DIM_C   1536
#define HEADS_C 12
#define HD_C    128
#define FS_C    384      // H*W frame size
#define W_C     24
#define NQBLK   48       // 3072/64
#define EPS_C   1e-6f

// ---------------- scratch ----------------
__device__ float g_q [L_TOK * DIM_C];
__device__ float g_k [L_TOK * DIM_C];
__device__ float g_v [L_TOK * DIM_C];
__device__ float g_ao[L_TOK * DIM_C];

// =====================================================================
// tf32 tensor-core GEMM: C = A @ W^T + bias   (A[M,K], W[N,K] row-major)
// block tile 128x128x16, 8 warps (4M x 2N), warp tile 32x64
// =====================================================================
#define TBM 128
#define TBN 128
#define TBK 16
#define SPAD 17

__device__ __forceinline__ uint32_t f2tf32(float x) {
    uint32_t r;
    asm("cvt.rna.tf32.f32 %0, %1;" : "=r"(r) : "f"(x));
    return r;
}

__device__ __forceinline__ void mma16n8k8(float c[4],
                                          const uint32_t a[4],
                                          const uint32_t b[2]) {
    asm volatile(
        "mma.sync.aligned.m16n8k8.row.col.f32.tf32.tf32.f32 "
        "{%0,%1,%2,%3}, {%4,%5,%6,%7}, {%8,%9}, {%0,%1,%2,%3};"
        : "+f"(c[0]), "+f"(c[1]), "+f"(c[2]), "+f"(c[3])
        : "r"(a[0]), "r"(a[1]), "r"(a[2]), "r"(a[3]),
          "r"(b[0]), "r"(b[1]));
}

__global__ __launch_bounds__(256) void gemm_tf32_nt_bias(
    const float* __restrict__ A, const float* __restrict__ W,
    const float* __restrict__ bias, float* __restrict__ C,
    int M, int N, int K)
{
    __shared__ uint32_t As[TBM * SPAD];
    __shared__ uint32_t Bs[TBN * SPAD];

    const int bm = blockIdx.y * TBM;
    const int bn = blockIdx.x * TBN;
    const int tid  = threadIdx.x;
    const int warp = tid >> 5;
    const int lane = tid & 31;
    const int wm = (warp >> 1) * 32;   // warp row offset in block (4 warps)
    const int wn = (warp & 1) * 64;    // warp col offset in block (2 warps)
    const int g  = lane >> 2;          // group id 0..7
    const int tg = lane & 3;           // thread-in-group 0..3

    float c[2][8][4];
#pragma unroll
    for (int i = 0; i < 2; i++)
#pragma unroll
        for (int j = 0; j < 8; j++)
#pragma unroll
            for (int t = 0; t < 4; t++) c[i][j][t] = 0.f;

    // gmem load mapping: each thread loads 2 float4 per tile
    const int lr = tid >> 2;            // 0..63
    const int lc = (tid & 3) << 2;      // 0,4,8,12

    float4 ra0, ra1, rb0, rb1;
    ra0 = *(const float4*)&A[(size_t)(bm + lr)      * K + lc];
    ra1 = *(const float4*)&A[(size_t)(bm + lr + 64) * K + lc];
    rb0 = *(const float4*)&W[(size_t)(bn + lr)      * K + lc];
    rb1 = *(const float4*)&W[(size_t)(bn + lr + 64) * K + lc];

    for (int k0 = 0; k0 < K; k0 += TBK) {
        __syncthreads();   // previous compute done before overwrite
        {
            uint32_t* pa0 = &As[lr * SPAD + lc];
            pa0[0] = f2tf32(ra0.x); pa0[1] = f2tf32(ra0.y);
            pa0[2] = f2tf32(ra0.z); pa0[3] = f2tf32(ra0.w);
            uint32_t* pa1 = &As[(lr + 64) * SPAD + lc];
            pa1[0] = f2tf32(ra1.x); pa1[1] = f2tf32(ra1.y);
            pa1[2] = f2tf32(ra1.z); pa1[3] = f2tf32(ra1.w);
            uint32_t* pb0 = &Bs[lr * SPAD + lc];
            pb0[0] = f2tf32(rb0.x); pb0[1] = f2tf32(rb0.y);
            pb0[2] = f2tf32(rb0.z); pb0[3] = f2tf32(rb0.w);
            uint32_t* pb1 = &Bs[(lr + 64) * SPAD + lc];
            pb1[0] = f2tf32(rb1.x); pb1[1] = f2tf32(rb1.y);
            pb1[2] = f2tf32(rb1.z); pb1[3] = f2tf32(rb1.w);
        }
        __syncthreads();

        // prefetch next tile while tensor cores work
        if (k0 + TBK < K) {
            int kn = k0 + TBK + lc;
            ra0 = *(const float4*)&A[(size_t)(bm + lr)      * K + kn];
            ra1 = *(const float4*)&A[(size_t)(bm + lr + 64) * K + kn];
            rb0 = *(const float4*)&W[(size_t)(bn + lr)      * K + kn];
            rb1 = *(const float4*)&W[(size_t)(bn + lr + 64) * K + kn];
        }

#pragma unroll
        for (int ks = 0; ks < 2; ks++) {
            const int kk = ks * 8;
            uint32_t af[2][4];
#pragma unroll
            for (int i = 0; i < 2; i++) {
                int r = wm + i * 16 + g;
                af[i][0] = As[r       * SPAD + kk + tg];
                af[i][1] = As[(r + 8) * SPAD + kk + tg];
                af[i][2] = As[r       * SPAD + kk + tg + 4];
                af[i][3] = As[(r + 8) * SPAD + kk + tg + 4];
            }
            uint32_t bf[8][2];
#pragma unroll
            for (int j = 0; j < 8; j++) {
                int r = wn + j * 8 + g;
                bf[j][0] = Bs[r * SPAD + kk + tg];
                bf[j][1] = Bs[r * SPAD + kk + tg + 4];
            }
#pragma unroll
            for (int i = 0; i < 2; i++)
#pragma unroll
                for (int j = 0; j < 8; j++)
                    mma16n8k8(c[i][j], af[i], bf[j]);
        }
    }

    // epilogue with bias
#pragma unroll
    for (int i = 0; i < 2; i++) {
        int row0 = bm + wm + i * 16 + g;
#pragma unroll
        for (int j = 0; j < 8; j++) {
            int col = bn + wn + j * 8 + tg * 2;
            float b0 = bias[col], b1 = bias[col + 1];
            float2 v0 = make_float2(c[i][j][0] + b0, c[i][j][1] + b1);
            float2 v1 = make_float2(c[i][j][2] + b0, c[i][j][3] + b1);
            *(float2*)&C[(size_t)row0       * N + col] = v0;
            *(float2*)&C[(size_t)(row0 + 8) * N + col] = v1;
        }
    }
}

// ---------------- fused RMSNorm + RoPE for Q and K ----------------
__global__ __launch_bounds__(256) void normrope_kernel(
    float* __restrict__ q, float* __restrict__ k,
    const float* __restrict__ freqs,
    const float* __restrict__ nqw, const float* __restrict__ nkw)
{
    const int t = blockIdx.x;                  // token index
    const int f  = t / FS_C;
    const int rm = t % FS_C;
    const int hh = rm / W_C;
    const int ww = rm % W_C;
    const int tid = threadIdx.x;

    __shared__ float fr[64], fi[64];
    __shared__ float buf[DIM_C];
    __shared__ float red[8];

    if (tid < 64) {
        int c = tid;
        int row = (c < 22) ? f : ((c < 43) ? hh : ww);
        fr[c] = freqs[row * 128 + c * 2 + 0];
        fi[c] = freqs[row * 128 + c * 2 + 1];
    }

    for (int which = 0; which < 2; which++) {
        float* ptr = which ? k : q;
        const float* w = which ? nkw : nqw;

        float ss = 0.f;
        for (int i = tid; i < DIM_C; i += 256) {
            float v = ptr[(size_t)t * DIM_C + i];
            buf[i] = v;
            ss += v * v;
        }
        __syncthreads();
        {
            int lane = tid & 31, wid = tid >> 5;
#pragma unroll
            for (int o = 16; o > 0; o >>= 1) ss += __shfl_xor_sync(0xffffffffu, ss, o);
            if (lane == 0) red[wid] = ss;
        }
        __syncthreads();
        float tot;
        {
            float v = (tid < 8) ? red[tid] : 0.f;
            if (tid < 32) {
#pragma unroll
                for (int o = 4; o > 0; o >>= 1) v += __shfl_xor_sync(0xffffffffu, v, o);
                if (tid == 0) red[0] = v;
            }
        }
        __syncthreads();
        tot = red[0];
        float rn = rsqrtf(tot * (1.0f / DIM_C) + EPS_C);

        for (int p = tid; p < 768; p += 256) {
            int c = p & 63;
            float a = buf[2 * p]     * rn * w[2 * p];
            float b = buf[2 * p + 1] * rn * w[2 * p + 1];
            ptr[(size_t)t * DIM_C + 2 * p]     = a * fr[c] - b * fi[c];
            ptr[(size_t)t * DIM_C + 2 * p + 1] = a * fi[c] + b * fr[c];
        }
        __syncthreads();
    }
}

// ---------------- flash attention (frame-block causal, no per-elem mask) ----
#define QS_STRIDE 68
#define VS_STRIDE 132
#define PS_STRIDE 72
#define ATTN_SMEM_FLOATS (128 * QS_STRIDE + 128 * QS_STRIDE + 64 * PS_STRIDE)
#define ATTN_SMEM_BYTES  (ATTN_SMEM_FLOATS * 4)

__global__ __launch_bounds__(256) void attn_kernel(
    const float* __restrict__ Q, const float* __restrict__ K,
    const float* __restrict__ V, float* __restrict__ O)
{
    extern __shared__ float smem[];
    float* Qs  = smem;                      // [128][68] transposed: Qs[d*68 + q]
    float* KVs = Qs + 128 * QS_STRIDE;      // K: [d*68 + k]; later V: [k*132 + d]
    float* Ps  = KVs + 128 * QS_STRIDE;     // [64][72]

    const int qb = blockIdx.x, h = blockIdx.y;
    const int q0 = qb * 64;
    const int qf = q0 / FS_C;
    const int tid = threadIdx.x;
    const int ty = tid >> 4, tx = tid & 15;
    const float scale = 0.08838834764831844f;   // 1/sqrt(128)

    for (int i = tid; i < 64 * 128; i += 256) {
        int r = i >> 7, c = i & 127;
        Qs[c * QS_STRIDE + r] = Q[(size_t)(q0 + r) * DIM_C + h * HD_C + c];
    }

    float mrow[4], lrow[4], acc[4][8];
#pragma unroll
    for (int r = 0; r < 4; r++) {
        mrow[r] = -1e30f; lrow[r] = 0.f;
#pragma unroll
        for (int c = 0; c < 8; c++) acc[r][c] = 0.f;
    }

    const int sinkT     = (qf >= 5) ? 6 : 0;
    const int mainFirst = (qf >= 5) ? (qf - 4) * 6 : 0;
    const int mainT     = (qf >= 5) ? 30 : (qf + 1) * 6;
    const int nt = sinkT + mainT;

    for (int t = 0; t < nt; t++) {
        const int kt = (t < sinkT) ? t : mainFirst + (t - sinkT);
        const int k0 = kt * 64;

        __syncthreads();
        for (int i = tid; i < 64 * 128; i += 256) {
            int r = i >> 7, c = i & 127;
            KVs[c * QS_STRIDE + r] = K[(size_t)(k0 + r) * DIM_C + h * HD_C + c];
        }
        __syncthreads();

        float s[4][4];
#pragma unroll
        for (int r = 0; r < 4; r++)
#pragma unroll
            for (int c = 0; c < 4; c++) s[r][c] = 0.f;

#pragma unroll 4
        for (int kk = 0; kk < 128; kk++) {
            float4 a = *(const float4*)&Qs [kk * QS_STRIDE + ty * 4];
            float4 b = *(const float4*)&KVs[kk * QS_STRIDE + tx * 4];
            float av[4] = {a.x, a.y, a.z, a.w};
            float bv[4] = {b.x, b.y, b.z, b.w};
#pragma unroll
            for (int r = 0; r < 4; r++)
#pragma unroll
                for (int c = 0; c < 4; c++) s[r][c] += av[r] * bv[c];
        }

#pragma unroll
        for (int r = 0; r < 4; r++) {
#pragma unroll
            for (int c = 0; c < 4; c++) s[r][c] *= scale;
            float rmax = fmaxf(fmaxf(s[r][0], s[r][1]), fmaxf(s[r][2], s[r][3]));
#pragma unroll
            for (int o = 8; o > 0; o >>= 1)
                rmax = fmaxf(rmax, __shfl_xor_sync(0xffffffffu, rmax, o));
            float mnew = fmaxf(mrow[r], rmax);
            float alpha = __expf(mrow[r] - mnew);
            mrow[r] = mnew;
            float rs = 0.f;
#pragma unroll
            for (int c = 0; c < 4; c++) {
                float p = __expf(s[r][c] - mnew);
                Ps[(ty * 4 + r) * PS_STRIDE + tx * 4 + c] = p;
                rs += p;
            }
#pragma unroll
            for (int o = 8; o > 0; o >>= 1)
                rs += __shfl_xor_sync(0xffffffffu, rs, o);
            lrow[r] = lrow[r] * alpha + rs;
#pragma unroll
            for (int c = 0; c < 8; c++) acc[r][c] *= alpha;
        }
        __syncthreads();

        for (int i = tid; i < 64 * 128; i += 256) {
            int r = i >> 7, c = i & 127;
            KVs[r * VS_STRIDE + c] = V[(size_t)(k0 + r) * DIM_C + h * HD_C + c];
        }
        __syncthreads();

#pragma unroll 4
        for (int j = 0; j < 64; j++) {
            float4 v0 = *(const float4*)&KVs[j * VS_STRIDE + tx * 8];
            float4 v1 = *(const float4*)&KVs[j * VS_STRIDE + tx * 8 + 4];
#pragma unroll
            for (int r = 0; r < 4; r++) {
                float p = Ps[(ty * 4 + r) * PS_STRIDE + j];
                acc[r][0] += p * v0.x; acc[r][1] += p * v0.y;
                acc[r][2] += p * v0.z; acc[r][3] += p * v0.w;
                acc[r][4] += p * v1.x; acc[r][5] += p * v1.y;
                acc[r][6] += p * v1.z; acc[r][7] += p * v1.w;
            }
        }
    }

#pragma unroll
    for (int r = 0; r < 4; r++) {
        float inv = 1.f / lrow[r];
#pragma unroll
        for (int c = 0; c < 8; c++) {
            O[(size_t)(q0 + ty * 4 + r) * DIM_C + h * HD_C + tx * 8 + c] = acc[r][c] * inv;
        }
    }
}

// ---------------- launch ----------------
extern "C" void kernel_launch(void* const* d_in, const int* in_sizes, int n_in,
                              void* d_out, int out_size)
{
    const float* x     = (const float*)d_in[0];
    const float* freqs = (const float*)d_in[3];
    const float* wq    = (const float*)d_in[4];
    const float* bq    = (const float*)d_in[5];
    const float* wk    = (const float*)d_in[6];
    const float* bk    = (const float*)d_in[7];
    const float* wv    = (const float*)d_in[8];
    const float* bv    = (const float*)d_in[9];
    const float* wo    = (const float*)d_in[10];
    const float* bo    = (const float*)d_in[11];
    const float* nqw   = (const float*)d_in[12];
    const float* nkw   = (const float*)d_in[13];
    float* out = (float*)d_out;

    float *gq, *gk, *gv, *gao;
    cudaGetSymbolAddress((void**)&gq,  g_q);
    cudaGetSymbolAddress((void**)&gk,  g_k);
    cudaGetSymbolAddress((void**)&gv,  g_v);
    cudaGetSymbolAddress((void**)&gao, g_ao);

    cudaFuncSetAttribute(attn_kernel,
                         cudaFuncAttributeMaxDynamicSharedMemorySize,
                         ATTN_SMEM_BYTES);

    dim3 ggrid(DIM_C / TBN, L_TOK / TBM);   // (12, 24)
    gemm_tf32_nt_bias<<<ggrid, 256>>>(x, wq, bq, gq, L_TOK, DIM_C, DIM_C);
    gemm_tf32_nt_bias<<<ggrid, 256>>>(x, wk, bk, gk, L_TOK, DIM_C, DIM_C);
    gemm_tf32_nt_bias<<<ggrid, 256>>>(x, wv, bv, gv, L_TOK, DIM_C, DIM_C);

    normrope_kernel<<<L_TOK, 256>>>(gq, gk, freqs, nqw, nkw);

    attn_kernel<<<dim3(NQBLK, HEADS_C), 256, ATTN_SMEM_BYTES>>>(gq, gk, gv, gao);

    gemm_tf32_nt_bias<<<ggrid, 256>>>(gao, wo, bo, out, L_TOK, DIM_C, DIM_C);
}

// round 3
// speedup vs baseline: 3.6785x; 2.5625x over previous
#include <cuda_runtime.h>
#include <cuda_fp16.h>
#include <cuda_bf16.h>
#include <math.h>
#include <stdint.h>

#define L_TOK   3072
#define DIM_C   1536
#define HEADS_C 12
#define HD_C    128
#define FS_C    384
#define W_C     24
#define EPS_C   1e-6f

// ---------------- scratch ----------------
__device__ float g_q [L_TOK * DIM_C];
__device__ float g_k [L_TOK * DIM_C];
__device__ float g_v [L_TOK * DIM_C];
__device__ float g_ao[L_TOK * DIM_C];
// fragment-layout fp16 buffers (uint4 = 8 halves = one lane's 16x16-tile fragment)
__device__ uint4 g_xhi[L_TOK * DIM_C / 8];
__device__ uint4 g_xlo[L_TOK * DIM_C / 8];
__device__ uint4 g_whi[DIM_C * DIM_C / 8];
__device__ uint4 g_wlo[DIM_C * DIM_C / 8];
__device__ uint4 g_qA [L_TOK * DIM_C / 8];
__device__ uint4 g_kB [L_TOK * DIM_C / 8];
__device__ uint4 g_vHi[L_TOK * DIM_C / 8];
__device__ uint4 g_vLo[L_TOK * DIM_C / 8];

union U8h { uint4 v; __half h[8]; };

__device__ __forceinline__ void mma16816(float c[4], const uint32_t a[4],
                                         uint32_t b0, uint32_t b1) {
    asm volatile(
        "mma.sync.aligned.m16n8k16.row.col.f32.f16.f16.f32 "
        "{%0,%1,%2,%3}, {%4,%5,%6,%7}, {%8,%9}, {%0,%1,%2,%3};"
        : "+f"(c[0]), "+f"(c[1]), "+f"(c[2]), "+f"(c[3])
        : "r"(a[0]), "r"(a[1]), "r"(a[2]), "r"(a[3]), "r"(b0), "r"(b1));
}

// ============== operand pre-permute kernels ==============
// A-operand frag layout: tile(mt,kt), lane(g=lane>>2,tg=lane&3), half s:
//   reg=s>>1, hb=s&1: row = mt*16+g+((reg&1)<<3); col = kt*16+((reg&2)<<2)+2*tg+hb
__global__ __launch_bounds__(256) void splitA_kernel(
    const float* __restrict__ A, uint4* __restrict__ hi, uint4* __restrict__ lo,
    int K, int tileK)
{
    int gid = blockIdx.x * 256 + threadIdx.x;
    int tile = gid >> 5, lane = gid & 31;
    int mt = tile / tileK, kt = tile - mt * tileK;
    int g = lane >> 2, tg = lane & 3;
    U8h H, L;
#pragma unroll
    for (int s = 0; s < 8; s++) {
        int reg = s >> 1, hb = s & 1;
        int row = mt * 16 + g + ((reg & 1) << 3);
        int col = kt * 16 + ((reg & 2) << 2) + 2 * tg + hb;
        float v = A[(size_t)row * K + col];
        __half a = __float2half_rn(v);
        H.h[s] = a;
        L.h[s] = __float2half_rn(v - __half2float(a));
    }
    hi[tile * 32 + lane] = H.v;
    lo[tile * 32 + lane] = L.v;
}

// B-operand frag layout (W[N,K] row-major, NT): storage tile(nt2,kt):
//   j=s>>2, reg=(s>>1)&1, hb=s&1: n = nt2*16+j*8+g; k = kt*16+reg*8+2*tg+hb
__global__ __launch_bounds__(256) void splitB_kernel(
    const float* __restrict__ W, uint4* __restrict__ hi, uint4* __restrict__ lo,
    int K, int tileK)
{
    int gid = blockIdx.x * 256 + threadIdx.x;
    int tile = gid >> 5, lane = gid & 31;
    int nt2 = tile / tileK, kt = tile - nt2 * tileK;
    int g = lane >> 2, tg = lane & 3;
    U8h H, L;
#pragma unroll
    for (int s = 0; s < 8; s++) {
        int j = s >> 2, reg = (s >> 1) & 1, hb = s & 1;
        int n = nt2 * 16 + j * 8 + g;
        int k = kt * 16 + reg * 8 + 2 * tg + hb;
        float v = W[(size_t)n * K + k];
        __half a = __float2half_rn(v);
        H.h[s] = a;
        L.h[s] = __float2half_rn(v - __half2float(a));
    }
    hi[tile * 32 + lane] = H.v;
    lo[tile * 32 + lane] = L.v;
}

// Q per head -> A-frag fp16 (single).  tile = h*1536 + mt*8 + kt
__global__ __launch_bounds__(256) void convQ_kernel(
    const float* __restrict__ Q, uint4* __restrict__ out)
{
    int gid = blockIdx.x * 256 + threadIdx.x;
    int tile = gid >> 5, lane = gid & 31;
    int h = tile / 1536, r = tile - h * 1536;
    int mt = r >> 3, kt = r & 7;
    int g = lane >> 2, tg = lane & 3;
    U8h H;
#pragma unroll
    for (int s = 0; s < 8; s++) {
        int reg = s >> 1, hb = s & 1;
        int row = mt * 16 + g + ((reg & 1) << 3);
        int col = h * HD_C + kt * 16 + ((reg & 2) << 2) + 2 * tg + hb;
        H.h[s] = __float2half_rn(Q[(size_t)row * DIM_C + col]);
    }
    out[tile * 32 + lane] = H.v;
}

// K per head -> B-frag fp16 (n = key, k = dim).  tile = h*1536 + nt2*8 + kt
__global__ __launch_bounds__(256) void convK_kernel(
    const float* __restrict__ Kmat, uint4* __restrict__ out)
{
    int gid = blockIdx.x * 256 + threadIdx.x;
    int tile = gid >> 5, lane = gid & 31;
    int h = tile / 1536, r = tile - h * 1536;
    int nt2 = r >> 3, kt = r & 7;
    int g = lane >> 2, tg = lane & 3;
    U8h H;
#pragma unroll
    for (int s = 0; s < 8; s++) {
        int j = s >> 2, reg = (s >> 1) & 1, hb = s & 1;
        int key = nt2 * 16 + j * 8 + g;
        int dim = h * HD_C + kt * 16 + reg * 8 + 2 * tg + hb;
        H.h[s] = __float2half_rn(Kmat[(size_t)key * DIM_C + dim]);
    }
    out[tile * 32 + lane] = H.v;
}

// V per head -> B-frag hi/lo (n = dim(128), k = key(3072)). tile = h*1536 + nt2*192 + kt
__global__ __launch_bounds__(256) void convV_kernel(
    const float* __restrict__ Vmat, uint4* __restrict__ hi, uint4* __restrict__ lo)
{
    int gid = blockIdx.x * 256 + threadIdx.x;
    int tile = gid >> 5, lane = gid & 31;
    int h = tile / 1536, r = tile - h * 1536;
    int nt2 = r / 192, kt = r - nt2 * 192;
    int g = lane >> 2, tg = lane & 3;
    U8h H, L;
#pragma unroll
    for (int s = 0; s < 8; s++) {
        int j = s >> 2, reg = (s >> 1) & 1, hb = s & 1;
        int dim = nt2 * 16 + j * 8 + g;
        int key = kt * 16 + reg * 8 + 2 * tg + hb;
        float v = Vmat[(size_t)key * DIM_C + h * HD_C + dim];
        __half a = __float2half_rn(v);
        H.h[s] = a;
        L.h[s] = __float2half_rn(v - __half2float(a));
    }
    hi[tile * 32 + lane] = H.v;
    lo[tile * 32 + lane] = L.v;
}

// ============== fp16x2 GEMM: C = A @ W^T + bias ==============
// block 128x128, k-chunk 32, 3 passes (hi*hi + hi*lo + lo*hi)
__global__ __launch_bounds__(256) void gemm_fp16x2(
    const uint4* __restrict__ Ahi, const uint4* __restrict__ Alo,
    const uint4* __restrict__ Bhi, const uint4* __restrict__ Blo,
    const float* __restrict__ bias, float* __restrict__ C,
    int M, int N, int K)
{
    const int tileK = K >> 4;
    __shared__ uint4 As[2][8][2][32];
    __shared__ uint4 Bs[2][8][2][32];
    const int bmt  = blockIdx.y * 8;
    const int bnt2 = blockIdx.x * 8;
    const int tid = threadIdx.x, warp = tid >> 5, lane = tid & 31;
    const int g = lane >> 2, tg = lane & 3;
    const int mtb = (warp >> 1) * 2, nt2b = (warp & 1) * 4;

    float c[2][8][4];
#pragma unroll
    for (int i = 0; i < 2; i++)
#pragma unroll
        for (int j = 0; j < 8; j++)
#pragma unroll
            for (int t = 0; t < 4; t++) c[i][j][t] = 0.f;

    uint4 pa[4], pb[4];
    const int nk = tileK >> 1;

    // prefetch chunk 0
#pragma unroll
    for (int j = 0; j < 4; j++) {
        int idx = tid + j * 256;
        int hl = idx >> 9, rem = idx & 511;
        int mt = rem >> 6, ks = (rem >> 5) & 1, ln = rem & 31;
        pa[j] = (hl ? Alo : Ahi)[((size_t)(bmt + mt) * tileK + ks) * 32 + ln];
        pb[j] = (hl ? Blo : Bhi)[((size_t)(bnt2 + mt) * tileK + ks) * 32 + ln];
    }

    for (int kc = 0; kc < nk; kc++) {
        __syncthreads();
#pragma unroll
        for (int j = 0; j < 4; j++) {
            int idx = tid + j * 256;
            int hl = idx >> 9, rem = idx & 511;
            int mt = rem >> 6, ks = (rem >> 5) & 1, ln = rem & 31;
            As[hl][mt][ks][ln] = pa[j];
            Bs[hl][mt][ks][ln] = pb[j];
        }
        __syncthreads();
        if (kc + 1 < nk) {
#pragma unroll
            for (int j = 0; j < 4; j++) {
                int idx = tid + j * 256;
                int hl = idx >> 9, rem = idx & 511;
                int mt = rem >> 6, ks = (rem >> 5) & 1, ln = rem & 31;
                int ktg = (kc + 1) * 2 + ks;
                pa[j] = (hl ? Alo : Ahi)[((size_t)(bmt + mt) * tileK + ktg) * 32 + ln];
                pb[j] = (hl ? Blo : Bhi)[((size_t)(bnt2 + mt) * tileK + ktg) * 32 + ln];
            }
        }
        const int psel[3][2] = {{0,0},{0,1},{1,0}};
#pragma unroll
        for (int p = 0; p < 3; p++) {
            const int pA = psel[p][0], pB = psel[p][1];
#pragma unroll
            for (int ks = 0; ks < 2; ks++) {
                uint4 a0 = As[pA][mtb][ks][lane];
                uint4 a1 = As[pA][mtb + 1][ks][lane];
                uint32_t A0[4] = {a0.x, a0.y, a0.z, a0.w};
                uint32_t A1[4] = {a1.x, a1.y, a1.z, a1.w};
#pragma unroll
                for (int j = 0; j < 4; j++) {
                    uint4 b = Bs[pB][nt2b + j][ks][lane];
                    mma16816(c[0][j*2],   A0, b.x, b.y);
                    mma16816(c[0][j*2+1], A0, b.z, b.w);
                    mma16816(c[1][j*2],   A1, b.x, b.y);
                    mma16816(c[1][j*2+1], A1, b.z, b.w);
                }
            }
        }
    }

#pragma unroll
    for (int i = 0; i < 2; i++) {
        int row0 = (bmt + mtb + i) * 16 + g;
#pragma unroll
        for (int nt = 0; nt < 8; nt++) {
            int col = ((bnt2 + nt2b) * 2 + nt) * 8 + 2 * tg;
            float b0 = bias[col], b1 = bias[col + 1];
            float2 v0 = make_float2(c[i][nt][0] + b0, c[i][nt][1] + b1);
            float2 v1 = make_float2(c[i][nt][2] + b0, c[i][nt][3] + b1);
            *(float2*)&C[(size_t)row0 * N + col] = v0;
            *(float2*)&C[(size_t)(row0 + 8) * N + col] = v1;
        }
    }
}

// ---------------- fused RMSNorm + RoPE (unchanged, fp32) ----------------
__global__ __launch_bounds__(256) void normrope_kernel(
    float* __restrict__ q, float* __restrict__ k,
    const float* __restrict__ freqs,
    const float* __restrict__ nqw, const float* __restrict__ nkw)
{
    const int t = blockIdx.x;
    const int f  = t / FS_C;
    const int rm = t % FS_C;
    const int hh = rm / W_C;
    const int ww = rm % W_C;
    const int tid = threadIdx.x;

    __shared__ float fr[64], fi[64];
    __shared__ float buf[DIM_C];
    __shared__ float red[8];

    if (tid < 64) {
        int c = tid;
        int row = (c < 22) ? f : ((c < 43) ? hh : ww);
        fr[c] = freqs[row * 128 + c * 2 + 0];
        fi[c] = freqs[row * 128 + c * 2 + 1];
    }

    for (int which = 0; which < 2; which++) {
        float* ptr = which ? k : q;
        const float* w = which ? nkw : nqw;

        float ss = 0.f;
        for (int i = tid; i < DIM_C; i += 256) {
            float v = ptr[(size_t)t * DIM_C + i];
            buf[i] = v;
            ss += v * v;
        }
        __syncthreads();
        {
            int lane = tid & 31, wid = tid >> 5;
#pragma unroll
            for (int o = 16; o > 0; o >>= 1) ss += __shfl_xor_sync(0xffffffffu, ss, o);
            if (lane == 0) red[wid] = ss;
        }
        __syncthreads();
        {
            float v = (tid < 8) ? red[tid] : 0.f;
            if (tid < 32) {
#pragma unroll
                for (int o = 4; o > 0; o >>= 1) v += __shfl_xor_sync(0xffffffffu, v, o);
                if (tid == 0) red[0] = v;
            }
        }
        __syncthreads();
        float rn = rsqrtf(red[0] * (1.0f / DIM_C) + EPS_C);

        for (int p = tid; p < 768; p += 256) {
            int c = p & 63;
            float a = buf[2 * p]     * rn * w[2 * p];
            float b = buf[2 * p + 1] * rn * w[2 * p + 1];
            ptr[(size_t)t * DIM_C + 2 * p]     = a * fr[c] - b * fi[c];
            ptr[(size_t)t * DIM_C + 2 * p + 1] = a * fi[c] + b * fr[c];
        }
        __syncthreads();
    }
}

// ============== tensor-core flash attention ==============
// block = 128 queries x one head; 8 warps, each warp one m16 slab.
__global__ __launch_bounds__(256) void attn_fp16(
    const uint4* __restrict__ qA, const uint4* __restrict__ kB,
    const uint4* __restrict__ vHi, const uint4* __restrict__ vLo,
    float* __restrict__ O)
{
    __shared__ uint4 Ks[1024];   // [nt2 4][kt 8][lane 32]
    __shared__ uint4 Vh[1024];   // [nt2 8][j 4][lane 32]
    __shared__ uint4 Vl[1024];

    const int qb = blockIdx.x, h = blockIdx.y;
    const int tid = threadIdx.x, wid = tid >> 5, lane = tid & 31;
    const int g = lane >> 2, tg = lane & 3;
    const int mt = qb * 8 + wid;
    const float scale = 0.08838834764831844f;

    uint32_t qf_[8][4];
#pragma unroll
    for (int kt = 0; kt < 8; kt++) {
        uint4 qv = qA[((size_t)(h * 192 + mt) * 8 + kt) * 32 + lane];
        qf_[kt][0] = qv.x; qf_[kt][1] = qv.y; qf_[kt][2] = qv.z; qf_[kt][3] = qv.w;
    }

    float oacc[16][4];
#pragma unroll
    for (int i = 0; i < 16; i++)
#pragma unroll
        for (int j = 0; j < 4; j++) oacc[i][j] = 0.f;
    float m0 = -1e30f, m1 = -1e30f, l0 = 0.f, l1 = 0.f;

    const int qfr   = qb / 3;
    const int sinkT = (qfr >= 5) ? 6 : 0;
    const int mainF = (qfr >= 5) ? (qfr - 4) * 6 : 0;
    const int mainT = (qfr >= 5) ? 30 : (qfr + 1) * 6;
    const int ntile = sinkT + mainT;

    for (int t = 0; t < ntile; t++) {
        const int kt0 = (t < sinkT) ? t : mainF + (t - sinkT);

        __syncthreads();
        {
            const uint4* kbase = kB + ((size_t)(h * 192 + kt0 * 4) * 8) * 32;
#pragma unroll
            for (int j = 0; j < 4; j++) {
                int idx = tid + j * 256;
                Ks[idx] = kbase[idx];
            }
#pragma unroll
            for (int j = 0; j < 4; j++) {
                int idx = tid + j * 256;
                int nt2 = idx >> 7, rem = idx & 127, jj = rem >> 5, ln = rem & 31;
                size_t a = ((size_t)(h * 8 + nt2) * 192 + kt0 * 4 + jj) * 32 + ln;
                Vh[idx] = vHi[a];
                Vl[idx] = vLo[a];
            }
        }
        __syncthreads();

        float sacc[8][4];
#pragma unroll
        for (int i = 0; i < 8; i++)
#pragma unroll
            for (int j = 0; j < 4; j++) sacc[i][j] = 0.f;

#pragma unroll
        for (int kt = 0; kt < 8; kt++) {
#pragma unroll
            for (int n2 = 0; n2 < 4; n2++) {
                uint4 b = Ks[(n2 * 8 + kt) * 32 + lane];
                mma16816(sacc[n2*2],   qf_[kt], b.x, b.y);
                mma16816(sacc[n2*2+1], qf_[kt], b.z, b.w);
            }
        }

        float rm0 = -1e30f, rm1 = -1e30f;
#pragma unroll
        for (int nt = 0; nt < 8; nt++) {
            sacc[nt][0] *= scale; sacc[nt][1] *= scale;
            sacc[nt][2] *= scale; sacc[nt][3] *= scale;
            rm0 = fmaxf(rm0, fmaxf(sacc[nt][0], sacc[nt][1]));
            rm1 = fmaxf(rm1, fmaxf(sacc[nt][2], sacc[nt][3]));
        }
        rm0 = fmaxf(rm0, __shfl_xor_sync(0xffffffffu, rm0, 1));
        rm0 = fmaxf(rm0, __shfl_xor_sync(0xffffffffu, rm0, 2));
        rm1 = fmaxf(rm1, __shfl_xor_sync(0xffffffffu, rm1, 1));
        rm1 = fmaxf(rm1, __shfl_xor_sync(0xffffffffu, rm1, 2));

        float mn0 = fmaxf(m0, rm0), mn1 = fmaxf(m1, rm1);
        float al0 = __expf(m0 - mn0), al1 = __expf(m1 - mn1);
        m0 = mn0; m1 = mn1;

        float rs0 = 0.f, rs1 = 0.f;
        uint32_t ph0[8], ph1[8];
#pragma unroll
        for (int nt = 0; nt < 8; nt++) {
            float e0 = __expf(sacc[nt][0] - mn0);
            float e1 = __expf(sacc[nt][1] - mn0);
            float e2 = __expf(sacc[nt][2] - mn1);
            float e3 = __expf(sacc[nt][3] - mn1);
            rs0 += e0 + e1; rs1 += e2 + e3;
            __half2 p0 = __floats2half2_rn(e0, e1);
            __half2 p1 = __floats2half2_rn(e2, e3);
            ph0[nt] = *(uint32_t*)&p0;
            ph1[nt] = *(uint32_t*)&p1;
        }
        rs0 += __shfl_xor_sync(0xffffffffu, rs0, 1);
        rs0 += __shfl_xor_sync(0xffffffffu, rs0, 2);
        rs1 += __shfl_xor_sync(0xffffffffu, rs1, 1);
        rs1 += __shfl_xor_sync(0xffffffffu, rs1, 2);
        l0 = l0 * al0 + rs0;
        l1 = l1 * al1 + rs1;

#pragma unroll
        for (int nt = 0; nt < 16; nt++) {
            oacc[nt][0] *= al0; oacc[nt][1] *= al0;
            oacc[nt][2] *= al1; oacc[nt][3] *= al1;
        }

#pragma unroll
        for (int ks = 0; ks < 4; ks++) {
            uint32_t A_[4] = {ph0[2*ks], ph1[2*ks], ph0[2*ks+1], ph1[2*ks+1]};
#pragma unroll
            for (int n2 = 0; n2 < 8; n2++) {
                uint4 bh = Vh[(n2 * 4 + ks) * 32 + lane];
                mma16816(oacc[n2*2],   A_, bh.x, bh.y);
                mma16816(oacc[n2*2+1], A_, bh.z, bh.w);
                uint4 bl = Vl[(n2 * 4 + ks) * 32 + lane];
                mma16816(oacc[n2*2],   A_, bl.x, bl.y);
                mma16816(oacc[n2*2+1], A_, bl.z, bl.w);
            }
        }
    }

    float inv0 = 1.f / l0, inv1 = 1.f / l1;
    int row0 = mt * 16 + g, row1 = row0 + 8;
#pragma unroll
    for (int nt = 0; nt < 16; nt++) {
        int col = h * HD_C + nt * 8 + 2 * tg;
        float2 v0 = make_float2(oacc[nt][0] * inv0, oacc[nt][1] * inv0);
        float2 v1 = make_float2(oacc[nt][2] * inv1, oacc[nt][3] * inv1);
        *(float2*)&O[(size_t)row0 * DIM_C + col] = v0;
        *(float2*)&O[(size_t)row1 * DIM_C + col] = v1;
    }
}

// ---------------- launch ----------------
extern "C" void kernel_launch(void* const* d_in, const int* in_sizes, int n_in,
                              void* d_out, int out_size)
{
    const float* x     = (const float*)d_in[0];
    const float* freqs = (const float*)d_in[3];
    const float* wq    = (const float*)d_in[4];
    const float* bq    = (const float*)d_in[5];
    const float* wk    = (const float*)d_in[6];
    const float* bk    = (const float*)d_in[7];
    const float* wv    = (const float*)d_in[8];
    const float* bv    = (const float*)d_in[9];
    const float* wo    = (const float*)d_in[10];
    const float* bo    = (const float*)d_in[11];
    const float* nqw   = (const float*)d_in[12];
    const float* nkw   = (const float*)d_in[13];
    float* out = (float*)d_out;

    float *gq, *gk, *gv, *gao;
    uint4 *xhi, *xlo, *whi, *wlo, *qA, *kB, *vHi, *vLo;
    cudaGetSymbolAddress((void**)&gq,  g_q);
    cudaGetSymbolAddress((void**)&gk,  g_k);
    cudaGetSymbolAddress((void**)&gv,  g_v);
    cudaGetSymbolAddress((void**)&gao, g_ao);
    cudaGetSymbolAddress((void**)&xhi, g_xhi);
    cudaGetSymbolAddress((void**)&xlo, g_xlo);
    cudaGetSymbolAddress((void**)&whi, g_whi);
    cudaGetSymbolAddress((void**)&wlo, g_wlo);
    cudaGetSymbolAddress((void**)&qA,  g_qA);
    cudaGetSymbolAddress((void**)&kB,  g_kB);
    cudaGetSymbolAddress((void**)&vHi, g_vHi);
    cudaGetSymbolAddress((void**)&vLo, g_vLo);

    const int blkX = L_TOK * DIM_C / 8 / 256;   // 2304 (x / conv kernels)
    const int blkW = DIM_C * DIM_C / 8 / 256;   // 1152
    dim3 ggrid(DIM_C / 128, L_TOK / 128);       // (12, 24)

    splitA_kernel<<<blkX, 256>>>(x, xhi, xlo, DIM_C, DIM_C / 16);

    splitB_kernel<<<blkW, 256>>>(wq, whi, wlo, DIM_C, DIM_C / 16);
    gemm_fp16x2<<<ggrid, 256>>>(xhi, xlo, whi, wlo, bq, gq, L_TOK, DIM_C, DIM_C);

    splitB_kernel<<<blkW, 256>>>(wk, whi, wlo, DIM_C, DIM_C / 16);
    gemm_fp16x2<<<ggrid, 256>>>(xhi, xlo, whi, wlo, bk, gk, L_TOK, DIM_C, DIM_C);

    splitB_kernel<<<blkW, 256>>>(wv, whi, wlo, DIM_C, DIM_C / 16);
    gemm_fp16x2<<<ggrid, 256>>>(xhi, xlo, whi, wlo, bv, gv, L_TOK, DIM_C, DIM_C);

    normrope_kernel<<<L_TOK, 256>>>(gq, gk, freqs, nqw, nkw);

    convQ_kernel<<<blkX, 256>>>(gq, qA);
    convK_kernel<<<blkX, 256>>>(gk, kB);
    convV_kernel<<<blkX, 256>>>(gv, vHi, vLo);

    attn_fp16<<<dim3(L_TOK / 128, HEADS_C), 256>>>(qA, kB, vHi, vLo, gao);

    splitA_kernel<<<blkX, 256>>>(gao, xhi, xlo, DIM_C, DIM_C / 16);
    splitB_kernel<<<blkW, 256>>>(wo, whi, wlo, DIM_C, DIM_C / 16);
    gemm_fp16x2<<<ggrid, 256>>>(xhi, xlo, whi, wlo, bo, out, L_TOK, DIM_C, DIM_C);
}

// round 5
// speedup vs baseline: 4.0646x; 1.1050x over previous
#include <cuda_runtime.h>
#include <cuda_fp16.h>
#include <cuda_bf16.h>
#include <math.h>
#include <stdint.h>

#define L_TOK   3072
#define DIM_C   1536
#define HEADS_C 12
#define HD_C    128
#define FS_C    384
#define W_C     24
#define EPS_C   1e-6f
#define TILEK   96          // K=1536 -> 96 k16-tiles
#define MT_CNT  192         // 3072/16 m-tiles
#define WTSZ    (DIM_C * DIM_C / 8)   // uint4 per weight frag buffer

// ---------------- scratch ----------------
__device__ float g_q [L_TOK * DIM_C];
__device__ float g_k [L_TOK * DIM_C];
__device__ float g_v [L_TOK * DIM_C];
// frag-packed fp16 buffers (uint4 = one lane's 16x16-tile fragment)
__device__ uint4 g_xhi[L_TOK * DIM_C / 8];   // x A-frags; later attention-O A-frags
__device__ uint4 g_xlo[L_TOK * DIM_C / 8];
__device__ uint4 g_whi[4 * WTSZ];            // wq, wk, wv, wo B-frags
__device__ uint4 g_wlo[4 * WTSZ];
__device__ uint4 g_qA [L_TOK * DIM_C / 8];
__device__ uint4 g_kB [L_TOK * DIM_C / 8];
__device__ uint4 g_vHi[L_TOK * DIM_C / 8];
__device__ uint4 g_vLo[L_TOK * DIM_C / 8];

union U8h { uint4 v; __half h[8]; };

__device__ __forceinline__ uint32_t smem_u32(const void* p) {
    uint32_t a;
    asm("{ .reg .u64 t; cvta.to.shared.u64 t, %1; cvt.u32.u64 %0, t; }"
        : "=r"(a) : "l"(p));
    return a;
}
__device__ __forceinline__ void cp16(uint32_t dst, const void* src) {
    asm volatile("cp.async.cg.shared.global [%0], [%1], 16;"
                 :: "r"(dst), "l"(src) : "memory");
}
#define CP_COMMIT() asm volatile("cp.async.commit_group;" ::: "memory")
#define CP_WAIT(n)  asm volatile("cp.async.wait_group %0;" :: "n"(n) : "memory")

__device__ __forceinline__ void mma16816(float c[4], const uint32_t a[4],
                                         uint32_t b0, uint32_t b1) {
    asm volatile(
        "mma.sync.aligned.m16n8k16.row.col.f32.f16.f16.f32 "
        "{%0,%1,%2,%3}, {%4,%5,%6,%7}, {%8,%9}, {%0,%1,%2,%3};"
        : "+f"(c[0]), "+f"(c[1]), "+f"(c[2]), "+f"(c[3])
        : "r"(a[0]), "r"(a[1]), "r"(a[2]), "r"(a[3]), "r"(b0), "r"(b1));
}

// ============== operand pre-permute kernels ==============
// A-frag: tile(mt,kt): row = mt*16+g+((reg&1)<<3); col = kt*16+((reg&2)<<2)+2tg+hb
__global__ __launch_bounds__(256) void splitA_kernel(
    const float* __restrict__ A, uint4* __restrict__ hi, uint4* __restrict__ lo)
{
    int gid = blockIdx.x * 256 + threadIdx.x;
    int tile = gid >> 5, lane = gid & 31;
    int mt = tile / TILEK, kt = tile - mt * TILEK;
    int g = lane >> 2, tg = lane & 3;
    U8h H, L;
#pragma unroll
    for (int s = 0; s < 8; s++) {
        int reg = s >> 1, hb = s & 1;
        int row = mt * 16 + g + ((reg & 1) << 3);
        int col = kt * 16 + ((reg & 2) << 2) + 2 * tg + hb;
        float v = A[(size_t)row * DIM_C + col];
        __half a = __float2half_rn(v);
        H.h[s] = a;
        L.h[s] = __float2half_rn(v - __half2float(a));
    }
    hi[tile * 32 + lane] = H.v;
    lo[tile * 32 + lane] = L.v;
}

// all 4 weights -> B-frags in one launch. tile(nt2,kt): n=nt2*16+j*8+g, k=kt*16+reg*8+2tg+hb
__global__ __launch_bounds__(256) void splitW4_kernel(
    const float* __restrict__ w0, const float* __restrict__ w1,
    const float* __restrict__ w2, const float* __restrict__ w3,
    uint4* __restrict__ hi, uint4* __restrict__ lo)
{
    int gid = blockIdx.x * 256 + threadIdx.x;
    int tile = gid >> 5, lane = gid & 31;
    int widx = tile / (TILEK * TILEK);
    int r = tile - widx * (TILEK * TILEK);
    int nt2 = r / TILEK, kt = r - nt2 * TILEK;
    const float* W = (widx == 0) ? w0 : (widx == 1) ? w1 : (widx == 2) ? w2 : w3;
    int g = lane >> 2, tg = lane & 3;
    U8h H, L;
#pragma unroll
    for (int s = 0; s < 8; s++) {
        int j = s >> 2, reg = (s >> 1) & 1, hb = s & 1;
        int n = nt2 * 16 + j * 8 + g;
        int k = kt * 16 + reg * 8 + 2 * tg + hb;
        float v = W[(size_t)n * DIM_C + k];
        __half a = __float2half_rn(v);
        H.h[s] = a;
        L.h[s] = __float2half_rn(v - __half2float(a));
    }
    hi[tile * 32 + lane] = H.v;
    lo[tile * 32 + lane] = L.v;
}

// ============== GEMM: C = A @ W^T + bias (3-pass hi/lo, cp.async) ==============
// CTA tile 128x256, warp tile 64x64, chunk = 2 k16. stage = 3072 uint4 (48KB).
#define NSTAGE 3
#define STG_U4 3072
#define GEMM_SMEM (NSTAGE * STG_U4 * 16)

__global__ __launch_bounds__(256, 1) void gemm_fp16x3(
    const uint4* __restrict__ Ahi, const uint4* __restrict__ Alo,
    const uint4* __restrict__ Bhi, const uint4* __restrict__ Blo,
    const float* __restrict__ bias, float* __restrict__ C, int N)
{
    extern __shared__ uint4 sm[];
    const int tid = threadIdx.x, wid = tid >> 5, lane = tid & 31;
    const int g = lane >> 2, tg = lane & 3;
    const int bm8  = blockIdx.y * 8;    // m16-tile base
    const int bn16 = blockIdx.x * 16;   // n16-tile base
    const int wmt = (wid >> 2) * 4;     // warp m-tile offset within CTA
    const int wnt = (wid & 3) * 4;      // warp n16-tile offset

    float c[4][8][4];
#pragma unroll
    for (int i = 0; i < 4; i++)
#pragma unroll
        for (int j = 0; j < 8; j++)
#pragma unroll
            for (int t = 0; t < 4; t++) c[i][j][t] = 0.f;

    // per-stage load: A 4/thread, B 8/thread
    const int aln = tid & 31, akt = (tid >> 5) & 1, amt = (tid >> 6) & 3;
    // A: idx = tid + a*256 : lane=idx&31, kt=(idx>>5)&1, mt=(idx>>6)&7, hl=idx>>9
    // B: idx = tid + b*256 : lane, kt, nt=(idx>>6)&15, hl=idx>>10
    (void)aln; (void)akt; (void)amt;

#define LOAD_STAGE(slot, chunk) do {                                           \
    uint4* st = sm + (slot) * STG_U4;                                          \
    const int k2 = (chunk) * 2;                                                \
_Pragma("unroll")                                                              \
    for (int a = 0; a < 4; a++) {                                              \
        int idx = tid + a * 256;                                               \
        int ln = idx & 31, kt = (idx >> 5) & 1, mt = (idx >> 6) & 7;           \
        int hl = idx >> 9;                                                     \
        const uint4* src = (hl ? Alo : Ahi)                                    \
            + ((size_t)(bm8 + mt) * TILEK + k2 + kt) * 32 + ln;                \
        cp16(smem_u32(st + hl * 512 + mt * 64 + kt * 32 + ln), src);           \
    }                                                                          \
_Pragma("unroll")                                                              \
    for (int b = 0; b < 8; b++) {                                              \
        int idx = tid + b * 256;                                               \
        int ln = idx & 31, kt = (idx >> 5) & 1, nt = (idx >> 6) & 15;          \
        int hl = idx >> 10;                                                    \
        const uint4* src = (hl ? Blo : Bhi)                                    \
            + ((size_t)(bn16 + nt) * TILEK + k2 + kt) * 32 + ln;               \
        cp16(smem_u32(st + 1024 + hl * 1024 + nt * 64 + kt * 32 + ln), src);   \
    }                                                                          \
    CP_COMMIT();                                                               \
} while (0)

    const int NC = TILEK / 2;   // 48 chunks
    LOAD_STAGE(0, 0);
    LOAD_STAGE(1, 1);

    for (int ck = 0; ck < NC; ck++) {
        const int slot = ck % 3;
        if (ck + 2 < NC) { CP_WAIT(1); } else { CP_WAIT(0); }
        __syncthreads();
        if (ck + 2 < NC) LOAD_STAGE((ck + 2) % 3, ck + 2);

        const uint4* st = sm + slot * STG_U4;
#pragma unroll
        for (int kt = 0; kt < 2; kt++) {
            uint4 Ah[4], Al[4], Bh[4], Bl[4];
#pragma unroll
            for (int i = 0; i < 4; i++) {
                Ah[i] = st[(wmt + i) * 64 + kt * 32 + lane];
                Al[i] = st[512 + (wmt + i) * 64 + kt * 32 + lane];
            }
#pragma unroll
            for (int j = 0; j < 4; j++) {
                Bh[j] = st[1024 + (wnt + j) * 64 + kt * 32 + lane];
                Bl[j] = st[2048 + (wnt + j) * 64 + kt * 32 + lane];
            }
#pragma unroll
            for (int i = 0; i < 4; i++) {
                uint32_t ah[4] = {Ah[i].x, Ah[i].y, Ah[i].z, Ah[i].w};
                uint32_t al[4] = {Al[i].x, Al[i].y, Al[i].z, Al[i].w};
#pragma unroll
                for (int j = 0; j < 4; j++) {
                    mma16816(c[i][j*2],   ah, Bh[j].x, Bh[j].y);
                    mma16816(c[i][j*2+1], ah, Bh[j].z, Bh[j].w);
                    mma16816(c[i][j*2],   ah, Bl[j].x, Bl[j].y);
                    mma16816(c[i][j*2+1], ah, Bl[j].z, Bl[j].w);
                    mma16816(c[i][j*2],   al, Bh[j].x, Bh[j].y);
                    mma16816(c[i][j*2+1], al, Bh[j].z, Bh[j].w);
                }
            }
        }
        __syncthreads();
    }

    // epilogue
#pragma unroll
    for (int i = 0; i < 4; i++) {
        int row0 = (bm8 + wmt + i) * 16 + g;
#pragma unroll
        for (int j = 0; j < 8; j++) {
            int col = (bn16 + wnt + (j >> 1)) * 16 + (j & 1) * 8 + 2 * tg;
            float b0 = bias[col], b1 = bias[col + 1];
            float2 v0 = make_float2(c[i][j][0] + b0, c[i][j][1] + b1);
            float2 v1 = make_float2(c[i][j][2] + b0, c[i][j][3] + b1);
            *(float2*)&C[(size_t)row0 * N + col] = v0;
            *(float2*)&C[(size_t)(row0 + 8) * N + col] = v1;
        }
    }
}

// ---------------- fused RMSNorm + RoPE ----------------
__global__ __launch_bounds__(256) void normrope_kernel(
    float* __restrict__ q, float* __restrict__ k,
    const float* __restrict__ freqs,
    const float* __restrict__ nqw, const float* __restrict__ nkw)
{
    const int t = blockIdx.x;
    const int f  = t / FS_C;
    const int rm = t % FS_C;
    const int hh = rm / W_C;
    const int ww = rm % W_C;
    const int tid = threadIdx.x;

    __shared__ float fr[64], fi[64];
    __shared__ float buf[DIM_C];
    __shared__ float red[8];

    if (tid < 64) {
        int c = tid;
        int row = (c < 22) ? f : ((c < 43) ? hh : ww);
        fr[c] = freqs[row * 128 + c * 2 + 0];
        fi[c] = freqs[row * 128 + c * 2 + 1];
    }

    for (int which = 0; which < 2; which++) {
        float* ptr = which ? k : q;
        const float* w = which ? nkw : nqw;

        float ss = 0.f;
        for (int i = tid; i < DIM_C; i += 256) {
            float v = ptr[(size_t)t * DIM_C + i];
            buf[i] = v;
            ss += v * v;
        }
        __syncthreads();
        {
            int lane = tid & 31, wd = tid >> 5;
#pragma unroll
            for (int o = 16; o > 0; o >>= 1) ss += __shfl_xor_sync(0xffffffffu, ss, o);
            if (lane == 0) red[wd] = ss;
        }
        __syncthreads();
        {
            float v = (tid < 8) ? red[tid] : 0.f;
            if (tid < 32) {
#pragma unroll
                for (int o = 4; o > 0; o >>= 1) v += __shfl_xor_sync(0xffffffffu, v, o);
                if (tid == 0) red[0] = v;
            }
        }
        __syncthreads();
        float rn = rsqrtf(red[0] * (1.0f / DIM_C) + EPS_C);

        for (int p = tid; p < 768; p += 256) {
            int c = p & 63;
            float a = buf[2 * p]     * rn * w[2 * p];
            float b = buf[2 * p + 1] * rn * w[2 * p + 1];
            ptr[(size_t)t * DIM_C + 2 * p]     = a * fr[c] - b * fi[c];
            ptr[(size_t)t * DIM_C + 2 * p + 1] = a * fi[c] + b * fr[c];
        }
        __syncthreads();
    }
}

// ================= attention fragment conversions =================
__global__ __launch_bounds__(256) void convQ_kernel(
    const float* __restrict__ Q, uint4* __restrict__ out)
{
    int gid = blockIdx.x * 256 + threadIdx.x;
    int tile = gid >> 5, lane = gid & 31;
    int h = tile / 1536, r = tile - h * 1536;
    int mt = r >> 3, kt = r & 7;
    int g = lane >> 2, tg = lane & 3;
    U8h H;
#pragma unroll
    for (int s = 0; s < 8; s++) {
        int reg = s >> 1, hb = s & 1;
        int row = mt * 16 + g + ((reg & 1) << 3);
        int col = h * HD_C + kt * 16 + ((reg & 2) << 2) + 2 * tg + hb;
        H.h[s] = __float2half_rn(Q[(size_t)row * DIM_C + col]);
    }
    out[tile * 32 + lane] = H.v;
}

__global__ __launch_bounds__(256) void convK_kernel(
    const float* __restrict__ Kmat, uint4* __restrict__ out)
{
    int gid = blockIdx.x * 256 + threadIdx.x;
    int tile = gid >> 5, lane = gid & 31;
    int h = tile / 1536, r = tile - h * 1536;
    int nt2 = r >> 3, kt = r & 7;
    int g = lane >> 2, tg = lane & 3;
    U8h H;
#pragma unroll
    for (int s = 0; s < 8; s++) {
        int j = s >> 2, reg = (s >> 1) & 1, hb = s & 1;
        int key = nt2 * 16 + j * 8 + g;
        int dim = h * HD_C + kt * 16 + reg * 8 + 2 * tg + hb;
        H.h[s] = __float2half_rn(Kmat[(size_t)key * DIM_C + dim]);
    }
    out[tile * 32 + lane] = H.v;
}

__global__ __launch_bounds__(256) void convV_kernel(
    const float* __restrict__ Vmat, uint4* __restrict__ hi, uint4* __restrict__ lo)
{
    int gid = blockIdx.x * 256 + threadIdx.x;
    int tile = gid >> 5, lane = gid & 31;
    int h = tile / 1536, r = tile - h * 1536;
    int nt2 = r / 192, kt = r - nt2 * 192;
    int g = lane >> 2, tg = lane & 3;
    U8h H, L;
#pragma unroll
    for (int s = 0; s < 8; s++) {
        int j = s >> 2, reg = (s >> 1) & 1, hb = s & 1;
        int dim = nt2 * 16 + j * 8 + g;
        int key = kt * 16 + reg * 8 + 2 * tg + hb;
        float v = Vmat[(size_t)key * DIM_C + h * HD_C + dim];
        __half a = __float2half_rn(v);
        H.h[s] = a;
        L.h[s] = __float2half_rn(v - __half2float(a));
    }
    hi[tile * 32 + lane] = H.v;
    lo[tile * 32 + lane] = L.v;
}

// ================= tensor-core flash attention =================
// Epilogue packs O directly into out-projection A-frag layout (hi/lo).
__global__ __launch_bounds__(256) void attn_fp16(
    const uint4* __restrict__ qA, const uint4* __restrict__ kB,
    const uint4* __restrict__ vHi, const uint4* __restrict__ vLo,
    uint4* __restrict__ aHi, uint4* __restrict__ aLo)
{
    __shared__ uint4 Ks[1024];
    __shared__ uint4 Vh[1024];
    __shared__ uint4 Vl[1024];

    const int qb = blockIdx.x, h = blockIdx.y;
    const int tid = threadIdx.x, wid = tid >> 5, lane = tid & 31;
    const int mt = qb * 8 + wid;
    const float scale = 0.08838834764831844f;

    uint32_t qf_[8][4];
#pragma unroll
    for (int kt = 0; kt < 8; kt++) {
        uint4 qv = qA[((size_t)(h * 192 + mt) * 8 + kt) * 32 + lane];
        qf_[kt][0] = qv.x; qf_[kt][1] = qv.y; qf_[kt][2] = qv.z; qf_[kt][3] = qv.w;
    }

    float oacc[16][4];
#pragma unroll
    for (int i = 0; i < 16; i++)
#pragma unroll
        for (int j = 0; j < 4; j++) oacc[i][j] = 0.f;
    float m0 = -1e30f, m1 = -1e30f, l0 = 0.f, l1 = 0.f;

    const int qfr   = qb / 3;
    const int sinkT = (qfr >= 5) ? 6 : 0;
    const int mainF = (qfr >= 5) ? (qfr - 4) * 6 : 0;
    const int mainT = (qfr >= 5) ? 30 : (qfr + 1) * 6;
    const int ntile = sinkT + mainT;

    for (int t = 0; t < ntile; t++) {
        const int kt0 = (t < sinkT) ? t : mainF + (t - sinkT);

        __syncthreads();
        {
            const uint4* kbase = kB + ((size_t)(h * 192 + kt0 * 4) * 8) * 32;
#pragma unroll
            for (int j = 0; j < 4; j++) {
                int idx = tid + j * 256;
                Ks[idx] = kbase[idx];
            }
#pragma unroll
            for (int j = 0; j < 4; j++) {
                int idx = tid + j * 256;
                int nt2 = idx >> 7, rem = idx & 127, jj = rem >> 5, ln = rem & 31;
                size_t a = ((size_t)(h * 8 + nt2) * 192 + kt0 * 4 + jj) * 32 + ln;
                Vh[idx] = vHi[a];
                Vl[idx] = vLo[a];
            }
        }
        __syncthreads();

        float sacc[8][4];
#pragma unroll
        for (int i = 0; i < 8; i++)
#pragma unroll
            for (int j = 0; j < 4; j++) sacc[i][j] = 0.f;

#pragma unroll
        for (int kt = 0; kt < 8; kt++) {
#pragma unroll
            for (int n2 = 0; n2 < 4; n2++) {
                uint4 b = Ks[(n2 * 8 + kt) * 32 + lane];
                mma16816(sacc[n2*2],   qf_[kt], b.x, b.y);
                mma16816(sacc[n2*2+1], qf_[kt], b.z, b.w);
            }
        }

        float rm0 = -1e30f, rm1 = -1e30f;
#pragma unroll
        for (int nt = 0; nt < 8; nt++) {
            sacc[nt][0] *= scale; sacc[nt][1] *= scale;
            sacc[nt][2] *= scale; sacc[nt][3] *= scale;
            rm0 = fmaxf(rm0, fmaxf(sacc[nt][0], sacc[nt][1]));
            rm1 = fmaxf(rm1, fmaxf(sacc[nt][2], sacc[nt][3]));
        }
        rm0 = fmaxf(rm0, __shfl_xor_sync(0xffffffffu, rm0, 1));
        rm0 = fmaxf(rm0, __shfl_xor_sync(0xffffffffu, rm0, 2));
        rm1 = fmaxf(rm1, __shfl_xor_sync(0xffffffffu, rm1, 1));
        rm1 = fmaxf(rm1, __shfl_xor_sync(0xffffffffu, rm1, 2));

        float mn0 = fmaxf(m0, rm0), mn1 = fmaxf(m1, rm1);
        float al0 = __expf(m0 - mn0), al1 = __expf(m1 - mn1);
        m0 = mn0; m1 = mn1;

        float rs0 = 0.f, rs1 = 0.f;
        uint32_t ph0[8], ph1[8];
#pragma unroll
        for (int nt = 0; nt < 8; nt++) {
            float e0 = __expf(sacc[nt][0] - mn0);
            float e1 = __expf(sacc[nt][1] - mn0);
            float e2 = __expf(sacc[nt][2] - mn1);
            float e3 = __expf(sacc[nt][3] - mn1);
            rs0 += e0 + e1; rs1 += e2 + e3;
            __half2 p0 = __floats2half2_rn(e0, e1);
            __half2 p1 = __floats2half2_rn(e2, e3);
            ph0[nt] = *(uint32_t*)&p0;
            ph1[nt] = *(uint32_t*)&p1;
        }
        rs0 += __shfl_xor_sync(0xffffffffu, rs0, 1);
        rs0 += __shfl_xor_sync(0xffffffffu, rs0, 2);
        rs1 += __shfl_xor_sync(0xffffffffu, rs1, 1);
        rs1 += __shfl_xor_sync(0xffffffffu, rs1, 2);
        l0 = l0 * al0 + rs0;
        l1 = l1 * al1 + rs1;

#pragma unroll
        for (int nt = 0; nt < 16; nt++) {
            oacc[nt][0] *= al0; oacc[nt][1] *= al0;
            oacc[nt][2] *= al1; oacc[nt][3] *= al1;
        }

#pragma unroll
        for (int ks = 0; ks < 4; ks++) {
            uint32_t A_[4] = {ph0[2*ks], ph1[2*ks], ph0[2*ks+1], ph1[2*ks+1]};
#pragma unroll
            for (int n2 = 0; n2 < 8; n2++) {
                uint4 bh = Vh[(n2 * 4 + ks) * 32 + lane];
                mma16816(oacc[n2*2],   A_, bh.x, bh.y);
                mma16816(oacc[n2*2+1], A_, bh.z, bh.w);
                uint4 bl = Vl[(n2 * 4 + ks) * 32 + lane];
                mma16816(oacc[n2*2],   A_, bl.x, bl.y);
                mma16816(oacc[n2*2+1], A_, bl.z, bl.w);
            }
        }
    }

    // epilogue: C-frag layout == A-frag layout; pack hi/lo directly.
    float inv0 = 1.f / l0, inv1 = 1.f / l1;
#pragma unroll
    for (int nt2 = 0; nt2 < 8; nt2++) {
        float v00 = oacc[nt2*2][0]   * inv0, v01 = oacc[nt2*2][1]   * inv0;
        float v02 = oacc[nt2*2][2]   * inv1, v03 = oacc[nt2*2][3]   * inv1;
        float v10 = oacc[nt2*2+1][0] * inv0, v11 = oacc[nt2*2+1][1] * inv0;
        float v12 = oacc[nt2*2+1][2] * inv1, v13 = oacc[nt2*2+1][3] * inv1;
        __half h00 = __float2half_rn(v00), h01 = __float2half_rn(v01);
        __half h02 = __float2half_rn(v02), h03 = __float2half_rn(v03);
        __half h10 = __float2half_rn(v10), h11 = __float2half_rn(v11);
        __half h12 = __float2half_rn(v12), h13 = __float2half_rn(v13);
        U8h H, L;
        H.h[0] = h00; H.h[1] = h01; H.h[2] = h02; H.h[3] = h03;
        H.h[4] = h10; H.h[5] = h11; H.h[6] = h12; H.h[7] = h13;
        L.h[0] = __float2half_rn(v00 - __half2float(h00));
        L.h[1] = __float2half_rn(v01 - __half2float(h01));
        L.h[2] = __float2half_rn(v02 - __half2float(h02));
        L.h[3] = __float2half_rn(v03 - __half2float(h03));
        L.h[4] = __float2half_rn(v10 - __half2float(h10));
        L.h[5] = __float2half_rn(v11 - __half2float(h11));
        L.h[6] = __float2half_rn(v12 - __half2float(h12));
        L.h[7] = __float2half_rn(v13 - __half2float(h13));
        size_t tt = ((size_t)mt * TILEK + h * 8 + nt2) * 32 + lane;
        aHi[tt] = H.v;
        aLo[tt] = L.v;
    }
}

// ---------------- launch ----------------
extern "C" void kernel_launch(void* const* d_in, const int* in_sizes, int n_in,
                              void* d_out, int out_size)
{
    const float* x     = (const float*)d_in[0];
    const float* freqs = (const float*)d_in[3];
    const float* wq    = (const float*)d_in[4];
    const float* bq    = (const float*)d_in[5];
    const float* wk    = (const float*)d_in[6];
    const float* bk    = (const float*)d_in[7];
    const float* wv    = (const float*)d_in[8];
    const float* bv    = (const float*)d_in[9];
    const float* wo    = (const float*)d_in[10];
    const float* bo    = (const float*)d_in[11];
    const float* nqw   = (const float*)d_in[12];
    const float* nkw   = (const float*)d_in[13];
    float* out = (float*)d_out;

    float *gq, *gk, *gv;
    uint4 *xhi, *xlo, *whi, *wlo, *qA, *kB, *vHi, *vLo;
    cudaGetSymbolAddress((void**)&gq,  g_q);
    cudaGetSymbolAddress((void**)&gk,  g_k);
    cudaGetSymbolAddress((void**)&gv,  g_v);
    cudaGetSymbolAddress((void**)&xhi, g_xhi);
    cudaGetSymbolAddress((void**)&xlo, g_xlo);
    cudaGetSymbolAddress((void**)&whi, g_whi);
    cudaGetSymbolAddress((void**)&wlo, g_wlo);
    cudaGetSymbolAddress((void**)&qA,  g_qA);
    cudaGetSymbolAddress((void**)&kB,  g_kB);
    cudaGetSymbolAddress((void**)&vHi, g_vHi);
    cudaGetSymbolAddress((void**)&vLo, g_vLo);

    cudaFuncSetAttribute(gemm_fp16x3,
                         cudaFuncAttributeMaxDynamicSharedMemorySize, GEMM_SMEM);

    const int blkA = L_TOK * DIM_C / 8 / 256;       // 2304
    const int blkW = 4 * DIM_C * DIM_C / 8 / 256;   // 4608
    dim3 ggrid(DIM_C / 256, L_TOK / 128);           // (6, 24)

    splitA_kernel<<<blkA, 256>>>(x, xhi, xlo);
    splitW4_kernel<<<blkW, 256>>>(wq, wk, wv, wo, whi, wlo);

    gemm_fp16x3<<<ggrid, 256, GEMM_SMEM>>>(xhi, xlo, whi,             wlo,             bq, gq, DIM_C);
    gemm_fp16x3<<<ggrid, 256, GEMM_SMEM>>>(xhi, xlo, whi + WTSZ,      wlo + WTSZ,      bk, gk, DIM_C);
    gemm_fp16x3<<<ggrid, 256, GEMM_SMEM>>>(xhi, xlo, whi + 2 * WTSZ,  wlo + 2 * WTSZ,  bv, gv, DIM_C);

    normrope_kernel<<<L_TOK, 256>>>(gq, gk, freqs, nqw, nkw);

    convQ_kernel<<<blkA, 256>>>(gq, qA);
    convK_kernel<<<blkA, 256>>>(gk, kB);
    convV_kernel<<<blkA, 256>>>(gv, vHi, vLo);

    // attention writes its output directly into xhi/xlo as out-proj A-frags
    attn_fp16<<<dim3(L_TOK / 128, HEADS_C), 256>>>(qA, kB, vHi, vLo, xhi, xlo);

    gemm_fp16x3<<<ggrid, 256, GEMM_SMEM>>>(xhi, xlo, whi + 3 * WTSZ,  wlo + 3 * WTSZ,  bo, out, DIM_C);
}

// round 6
// speedup vs baseline: 4.4888x; 1.1044x over previous
#include <cuda_runtime.h>
#include <cuda_fp16.h>
#include <cuda_bf16.h>
#include <math.h>
#include <stdint.h>

#define L_TOK   3072
#define DIM_C   1536
#define HEADS_C 12
#define HD_C    128
#define FS_C    384
#define W_C     24
#define EPS_C   1e-6f
#define TILEK   96
#define WTSZ    (DIM_C * DIM_C / 8)

// ---------------- scratch ----------------
__device__ float g_q [L_TOK * DIM_C];
__device__ float g_k [L_TOK * DIM_C];
__device__ float g_v [L_TOK * DIM_C];
__device__ uint4 g_xhi[L_TOK * DIM_C / 8];
__device__ uint4 g_xlo[L_TOK * DIM_C / 8];
__device__ uint4 g_whi[4 * WTSZ];
__device__ uint4 g_wlo[4 * WTSZ];
__device__ uint4 g_qA [L_TOK * DIM_C / 8];
__device__ uint4 g_kB [L_TOK * DIM_C / 8];
__device__ uint4 g_vHi[L_TOK * DIM_C / 8];
__device__ uint4 g_vLo[L_TOK * DIM_C / 8];

// LPT ordering: heaviest q-blocks first (qb15-23: 36 tiles, then 30,24,18,12,6)
__device__ __constant__ int QBMAP[24] =
    {15,16,17,18,19,20,21,22,23, 12,13,14, 9,10,11, 6,7,8, 3,4,5, 0,1,2};

union U8h { uint4 v; __half h[8]; };

__device__ __forceinline__ uint32_t smem_u32(const void* p) {
    uint32_t a;
    asm("{ .reg .u64 t; cvta.to.shared.u64 t, %1; cvt.u32.u64 %0, t; }"
        : "=r"(a) : "l"(p));
    return a;
}
__device__ __forceinline__ void cp16(uint32_t dst, const void* src) {
    asm volatile("cp.async.cg.shared.global [%0], [%1], 16;"
                 :: "r"(dst), "l"(src) : "memory");
}
#define CP_COMMIT() asm volatile("cp.async.commit_group;" ::: "memory")
#define CP_WAIT(n)  asm volatile("cp.async.wait_group %0;" :: "n"(n) : "memory")

__device__ __forceinline__ void mma16816(float c[4], const uint32_t a[4],
                                         uint32_t b0, uint32_t b1) {
    asm volatile(
        "mma.sync.aligned.m16n8k16.row.col.f32.f16.f16.f32 "
        "{%0,%1,%2,%3}, {%4,%5,%6,%7}, {%8,%9}, {%0,%1,%2,%3};"
        : "+f"(c[0]), "+f"(c[1]), "+f"(c[2]), "+f"(c[3])
        : "r"(a[0]), "r"(a[1]), "r"(a[2]), "r"(a[3]), "r"(b0), "r"(b1));
}

// ============== operand pre-permute kernels ==============
__global__ __launch_bounds__(256) void splitA_kernel(
    const float* __restrict__ A, uint4* __restrict__ hi, uint4* __restrict__ lo)
{
    int gid = blockIdx.x * 256 + threadIdx.x;
    int tile = gid >> 5, lane = gid & 31;
    int mt = tile / TILEK, kt = tile - mt * TILEK;
    int g = lane >> 2, tg = lane & 3;
    U8h H, L;
#pragma unroll
    for (int s = 0; s < 8; s++) {
        int reg = s >> 1, hb = s & 1;
        int row = mt * 16 + g + ((reg & 1) << 3);
        int col = kt * 16 + ((reg & 2) << 2) + 2 * tg + hb;
        float v = A[(size_t)row * DIM_C + col];
        __half a = __float2half_rn(v);
        H.h[s] = a;
        L.h[s] = __float2half_rn(v - __half2float(a));
    }
    hi[tile * 32 + lane] = H.v;
    lo[tile * 32 + lane] = L.v;
}

__global__ __launch_bounds__(256) void splitW4_kernel(
    const float* __restrict__ w0, const float* __restrict__ w1,
    const float* __restrict__ w2, const float* __restrict__ w3,
    uint4* __restrict__ hi, uint4* __restrict__ lo)
{
    int gid = blockIdx.x * 256 + threadIdx.x;
    int tile = gid >> 5, lane = gid & 31;
    int widx = tile / (TILEK * TILEK);
    int r = tile - widx * (TILEK * TILEK);
    int nt2 = r / TILEK, kt = r - nt2 * TILEK;
    const float* W = (widx == 0) ? w0 : (widx == 1) ? w1 : (widx == 2) ? w2 : w3;
    int g = lane >> 2, tg = lane & 3;
    U8h H, L;
#pragma unroll
    for (int s = 0; s < 8; s++) {
        int j = s >> 2, reg = (s >> 1) & 1, hb = s & 1;
        int n = nt2 * 16 + j * 8 + g;
        int k = kt * 16 + reg * 8 + 2 * tg + hb;
        float v = W[(size_t)n * DIM_C + k];
        __half a = __float2half_rn(v);
        H.h[s] = a;
        L.h[s] = __float2half_rn(v - __half2float(a));
    }
    hi[tile * 32 + lane] = H.v;
    lo[tile * 32 + lane] = L.v;
}

// ============== GEMM (3-pass hi/lo, cp.async, 1 sync/chunk) ==============
#define NSTAGE 3
#define STG_U4 3072
#define GEMM_SMEM (NSTAGE * STG_U4 * 16)

__global__ __launch_bounds__(256, 1) void gemm_fp16x3(
    const uint4* __restrict__ Ahi, const uint4* __restrict__ Alo,
    const uint4* __restrict__ Bhi, const uint4* __restrict__ Blo,
    const float* __restrict__ bias, float* __restrict__ C, int N)
{
    extern __shared__ uint4 sm[];
    const int tid = threadIdx.x, wid = tid >> 5, lane = tid & 31;
    const int g = lane >> 2, tg = lane & 3;
    const int bm8  = blockIdx.y * 8;
    const int bn16 = blockIdx.x * 16;
    const int wmt = (wid >> 2) * 4;
    const int wnt = (wid & 3) * 4;

    float c[4][8][4];
#pragma unroll
    for (int i = 0; i < 4; i++)
#pragma unroll
        for (int j = 0; j < 8; j++)
#pragma unroll
            for (int t = 0; t < 4; t++) c[i][j][t] = 0.f;

#define LOAD_STAGE(slot, chunk) do {                                           \
    uint4* st = sm + (slot) * STG_U4;                                          \
    const int k2 = (chunk) * 2;                                                \
_Pragma("unroll")                                                              \
    for (int a = 0; a < 4; a++) {                                              \
        int idx = tid + a * 256;                                               \
        int ln = idx & 31, kt = (idx >> 5) & 1, mt = (idx >> 6) & 7;           \
        int hl = idx >> 9;                                                     \
        const uint4* src = (hl ? Alo : Ahi)                                    \
            + ((size_t)(bm8 + mt) * TILEK + k2 + kt) * 32 + ln;                \
        cp16(smem_u32(st + hl * 512 + mt * 64 + kt * 32 + ln), src);           \
    }                                                                          \
_Pragma("unroll")                                                              \
    for (int b = 0; b < 8; b++) {                                              \
        int idx = tid + b * 256;                                               \
        int ln = idx & 31, kt = (idx >> 5) & 1, nt = (idx >> 6) & 15;          \
        int hl = idx >> 10;                                                    \
        const uint4* src = (hl ? Blo : Bhi)                                    \
            + ((size_t)(bn16 + nt) * TILEK + k2 + kt) * 32 + ln;               \
        cp16(smem_u32(st + 1024 + hl * 1024 + nt * 64 + kt * 32 + ln), src);   \
    }                                                                          \
    CP_COMMIT();                                                               \
} while (0)

    const int NC = TILEK / 2;   // 48
    LOAD_STAGE(0, 0);
    LOAD_STAGE(1, 1);

    for (int ck = 0; ck < NC; ck++) {
        const int slot = ck % 3;
        if (ck + 2 < NC) { CP_WAIT(1); } else { CP_WAIT(0); }
        __syncthreads();
        if (ck + 2 < NC) LOAD_STAGE((ck + 2) % 3, ck + 2);

        const uint4* st = sm + slot * STG_U4;
#pragma unroll
        for (int kt = 0; kt < 2; kt++) {
            uint4 Ah[4], Al[4], Bh[4], Bl[4];
#pragma unroll
            for (int i = 0; i < 4; i++) {
                Ah[i] = st[(wmt + i) * 64 + kt * 32 + lane];
                Al[i] = st[512 + (wmt + i) * 64 + kt * 32 + lane];
            }
#pragma unroll
            for (int j = 0; j < 4; j++) {
                Bh[j] = st[1024 + (wnt + j) * 64 + kt * 32 + lane];
                Bl[j] = st[2048 + (wnt + j) * 64 + kt * 32 + lane];
            }
#pragma unroll
            for (int i = 0; i < 4; i++) {
                uint32_t ah[4] = {Ah[i].x, Ah[i].y, Ah[i].z, Ah[i].w};
                uint32_t al[4] = {Al[i].x, Al[i].y, Al[i].z, Al[i].w};
#pragma unroll
                for (int j = 0; j < 4; j++) {
                    mma16816(c[i][j*2],   ah, Bh[j].x, Bh[j].y);
                    mma16816(c[i][j*2+1], ah, Bh[j].z, Bh[j].w);
                    mma16816(c[i][j*2],   ah, Bl[j].x, Bl[j].y);
                    mma16816(c[i][j*2+1], ah, Bl[j].z, Bl[j].w);
                    mma16816(c[i][j*2],   al, Bh[j].x, Bh[j].y);
                    mma16816(c[i][j*2+1], al, Bh[j].z, Bh[j].w);
                }
            }
        }
        // no trailing sync: next iteration's top-of-loop sync orders slot reuse
    }

#pragma unroll
    for (int i = 0; i < 4; i++) {
        int row0 = (bm8 + wmt + i) * 16 + g;
#pragma unroll
        for (int j = 0; j < 8; j++) {
            int col = (bn16 + wnt + (j >> 1)) * 16 + (j & 1) * 8 + 2 * tg;
            float b0 = bias[col], b1 = bias[col + 1];
            float2 v0 = make_float2(c[i][j][0] + b0, c[i][j][1] + b1);
            float2 v1 = make_float2(c[i][j][2] + b0, c[i][j][3] + b1);
            *(float2*)&C[(size_t)row0 * N + col] = v0;
            *(float2*)&C[(size_t)(row0 + 8) * N + col] = v1;
        }
    }
}

// ---------------- fused RMSNorm + RoPE: q and k processed concurrently ------
__global__ __launch_bounds__(256) void normrope_kernel(
    float* __restrict__ q, float* __restrict__ k,
    const float* __restrict__ freqs,
    const float* __restrict__ nqw, const float* __restrict__ nkw)
{
    const int t = blockIdx.x;
    const int f  = t / FS_C;
    const int rm = t % FS_C;
    const int hh = rm / W_C;
    const int ww = rm % W_C;
    const int tid = threadIdx.x;
    const int grp = tid >> 7;           // 0 = q, 1 = k
    const int gt  = tid & 127;          // thread within group

    __shared__ float fr[64], fi[64];
    __shared__ float red[8];

    if (tid < 64) {
        int c = tid;
        int row = (c < 22) ? f : ((c < 43) ? hh : ww);
        fr[c] = freqs[row * 128 + c * 2 + 0];
        fi[c] = freqs[row * 128 + c * 2 + 1];
    }

    float* ptr = grp ? k : q;
    const float* w = grp ? nkw : nqw;

    // each thread owns 12 consecutive floats of its row
    float v[12], wv[12];
    const int c0 = gt * 12;
#pragma unroll
    for (int j = 0; j < 3; j++) {
        float4 a = *(const float4*)&ptr[(size_t)t * DIM_C + c0 + j * 4];
        float4 b = *(const float4*)&w[c0 + j * 4];
        v[j*4+0] = a.x; v[j*4+1] = a.y; v[j*4+2] = a.z; v[j*4+3] = a.w;
        wv[j*4+0] = b.x; wv[j*4+1] = b.y; wv[j*4+2] = b.z; wv[j*4+3] = b.w;
    }
    float ss = 0.f;
#pragma unroll
    for (int j = 0; j < 12; j++) ss += v[j] * v[j];
    {
        int lane = tid & 31, wd = tid >> 5;
#pragma unroll
        for (int o = 16; o > 0; o >>= 1) ss += __shfl_xor_sync(0xffffffffu, ss, o);
        if (lane == 0) red[wd] = ss;
    }
    __syncthreads();
    float tot = red[grp * 4 + 0] + red[grp * 4 + 1]
              + red[grp * 4 + 2] + red[grp * 4 + 3];
    float rn = rsqrtf(tot * (1.0f / DIM_C) + EPS_C);

    // 6 RoPE pairs per thread, contiguous: pairs p = gt*6 .. gt*6+5
#pragma unroll
    for (int j = 0; j < 6; j++) {
        int p = gt * 6 + j;
        int c = p & 63;
        float a = v[2*j]     * rn * wv[2*j];
        float b = v[2*j + 1] * rn * wv[2*j + 1];
        float2 o = make_float2(a * fr[c] - b * fi[c], a * fi[c] + b * fr[c]);
        *(float2*)&ptr[(size_t)t * DIM_C + 2 * p] = o;
    }
}

// ================= attention fragment conversions =================
__global__ __launch_bounds__(256) void convQ_kernel(
    const float* __restrict__ Q, uint4* __restrict__ out)
{
    int gid = blockIdx.x * 256 + threadIdx.x;
    int tile = gid >> 5, lane = gid & 31;
    int h = tile / 1536, r = tile - h * 1536;
    int mt = r >> 3, kt = r & 7;
    int g = lane >> 2, tg = lane & 3;
    U8h H;
#pragma unroll
    for (int s = 0; s < 8; s++) {
        int reg = s >> 1, hb = s & 1;
        int row = mt * 16 + g + ((reg & 1) << 3);
        int col = h * HD_C + kt * 16 + ((reg & 2) << 2) + 2 * tg + hb;
        H.h[s] = __float2half_rn(Q[(size_t)row * DIM_C + col]);
    }
    out[tile * 32 + lane] = H.v;
}

__global__ __launch_bounds__(256) void convK_kernel(
    const float* __restrict__ Kmat, uint4* __restrict__ out)
{
    int gid = blockIdx.x * 256 + threadIdx.x;
    int tile = gid >> 5, lane = gid & 31;
    int h = tile / 1536, r = tile - h * 1536;
    int nt2 = r >> 3, kt = r & 7;
    int g = lane >> 2, tg = lane & 3;
    U8h H;
#pragma unroll
    for (int s = 0; s < 8; s++) {
        int j = s >> 2, reg = (s >> 1) & 1, hb = s & 1;
        int key = nt2 * 16 + j * 8 + g;
        int dim = h * HD_C + kt * 16 + reg * 8 + 2 * tg + hb;
        H.h[s] = __float2half_rn(Kmat[(size_t)key * DIM_C + dim]);
    }
    out[tile * 32 + lane] = H.v;
}

__global__ __launch_bounds__(256) void convV_kernel(
    const float* __restrict__ Vmat, uint4* __restrict__ hi, uint4* __restrict__ lo)
{
    int gid = blockIdx.x * 256 + threadIdx.x;
    int tile = gid >> 5, lane = gid & 31;
    int h = tile / 1536, r = tile - h * 1536;
    int nt2 = r / 192, kt = r - nt2 * 192;
    int g = lane >> 2, tg = lane & 3;
    U8h H, L;
#pragma unroll
    for (int s = 0; s < 8; s++) {
        int j = s >> 2, reg = (s >> 1) & 1, hb = s & 1;
        int dim = nt2 * 16 + j * 8 + g;
        int key = kt * 16 + reg * 8 + 2 * tg + hb;
        float v = Vmat[(size_t)key * DIM_C + h * HD_C + dim];
        __half a = __float2half_rn(v);
        H.h[s] = a;
        L.h[s] = __float2half_rn(v - __half2float(a));
    }
    hi[tile * 32 + lane] = H.v;
    lo[tile * 32 + lane] = L.v;
}

// ================= tensor-core flash attention (LPT-ordered) =================
__global__ __launch_bounds__(256) void attn_fp16(
    const uint4* __restrict__ qA, const uint4* __restrict__ kB,
    const uint4* __restrict__ vHi, const uint4* __restrict__ vLo,
    uint4* __restrict__ aHi, uint4* __restrict__ aLo)
{
    __shared__ uint4 Ks[1024];
    __shared__ uint4 Vh[1024];
    __shared__ uint4 Vl[1024];

    const int bi = blockIdx.x;
    const int h  = bi % HEADS_C;
    const int qb = QBMAP[bi / HEADS_C];
    const int tid = threadIdx.x, wid = tid >> 5, lane = tid & 31;
    const int mt = qb * 8 + wid;
    const float scale = 0.08838834764831844f;

    uint32_t qf_[8][4];
#pragma unroll
    for (int kt = 0; kt < 8; kt++) {
        uint4 qv = qA[((size_t)(h * 192 + mt) * 8 + kt) * 32 + lane];
        qf_[kt][0] = qv.x; qf_[kt][1] = qv.y; qf_[kt][2] = qv.z; qf_[kt][3] = qv.w;
    }

    float oacc[16][4];
#pragma unroll
    for (int i = 0; i < 16; i++)
#pragma unroll
        for (int j = 0; j < 4; j++) oacc[i][j] = 0.f;
    float m0 = -1e30f, m1 = -1e30f, l0 = 0.f, l1 = 0.f;

    const int qfr   = qb / 3;
    const int sinkT = (qfr >= 5) ? 6 : 0;
    const int mainF = (qfr >= 5) ? (qfr - 4) * 6 : 0;
    const int mainT = (qfr >= 5) ? 30 : (qfr + 1) * 6;
    const int ntile = sinkT + mainT;

    for (int t = 0; t < ntile; t++) {
        const int kt0 = (t < sinkT) ? t : mainF + (t - sinkT);

        __syncthreads();
        {
            const uint4* kbase = kB + ((size_t)(h * 192 + kt0 * 4) * 8) * 32;
#pragma unroll
            for (int j = 0; j < 4; j++) {
                int idx = tid + j * 256;
                Ks[idx] = kbase[idx];
            }
#pragma unroll
            for (int j = 0; j < 4; j++) {
                int idx = tid + j * 256;
                int nt2 = idx >> 7, rem = idx & 127, jj = rem >> 5, ln = rem & 31;
                size_t a = ((size_t)(h * 8 + nt2) * 192 + kt0 * 4 + jj) * 32 + ln;
                Vh[idx] = vHi[a];
                Vl[idx] = vLo[a];
            }
        }
        __syncthreads();

        float sacc[8][4];
#pragma unroll
        for (int i = 0; i < 8; i++)
#pragma unroll
            for (int j = 0; j < 4; j++) sacc[i][j] = 0.f;

#pragma unroll
        for (int kt = 0; kt < 8; kt++) {
#pragma unroll
            for (int n2 = 0; n2 < 4; n2++) {
                uint4 b = Ks[(n2 * 8 + kt) * 32 + lane];
                mma16816(sacc[n2*2],   qf_[kt], b.x, b.y);
                mma16816(sacc[n2*2+1], qf_[kt], b.z, b.w);
            }
        }

        float rm0 = -1e30f, rm1 = -1e30f;
#pragma unroll
        for (int nt = 0; nt < 8; nt++) {
            sacc[nt][0] *= scale; sacc[nt][1] *= scale;
            sacc[nt][2] *= scale; sacc[nt][3] *= scale;
            rm0 = fmaxf(rm0, fmaxf(sacc[nt][0], sacc[nt][1]));
            rm1 = fmaxf(rm1, fmaxf(sacc[nt][2], sacc[nt][3]));
        }
        rm0 = fmaxf(rm0, __shfl_xor_sync(0xffffffffu, rm0, 1));
        rm0 = fmaxf(rm0, __shfl_xor_sync(0xffffffffu, rm0, 2));
        rm1 = fmaxf(rm1, __shfl_xor_sync(0xffffffffu, rm1, 1));
        rm1 = fmaxf(rm1, __shfl_xor_sync(0xffffffffu, rm1, 2));

        float mn0 = fmaxf(m0, rm0), mn1 = fmaxf(m1, rm1);
        float al0 = __expf(m0 - mn0), al1 = __expf(m1 - mn1);
        m0 = mn0; m1 = mn1;

        float rs0 = 0.f, rs1 = 0.f;
        uint32_t ph0[8], ph1[8];
#pragma unroll
        for (int nt = 0; nt < 8; nt++) {
            float e0 = __expf(sacc[nt][0] - mn0);
            float e1 = __expf(sacc[nt][1] - mn0);
            float e2 = __expf(sacc[nt][2] - mn1);
            float e3 = __expf(sacc[nt][3] - mn1);
            rs0 += e0 + e1; rs1 += e2 + e3;
            __half2 p0 = __floats2half2_rn(e0, e1);
            __half2 p1 = __floats2half2_rn(e2, e3);
            ph0[nt] = *(uint32_t*)&p0;
            ph1[nt] = *(uint32_t*)&p1;
        }
        rs0 += __shfl_xor_sync(0xffffffffu, rs0, 1);
        rs0 += __shfl_xor_sync(0xffffffffu, rs0, 2);
        rs1 += __shfl_xor_sync(0xffffffffu, rs1, 1);
        rs1 += __shfl_xor_sync(0xffffffffu, rs1, 2);
        l0 = l0 * al0 + rs0;
        l1 = l1 * al1 + rs1;

#pragma unroll
        for (int nt = 0; nt < 16; nt++) {
            oacc[nt][0] *= al0; oacc[nt][1] *= al0;
            oacc[nt][2] *= al1; oacc[nt][3] *= al1;
        }

#pragma unroll
        for (int ks = 0; ks < 4; ks++) {
            uint32_t A_[4] = {ph0[2*ks], ph1[2*ks], ph0[2*ks+1], ph1[2*ks+1]};
#pragma unroll
            for (int n2 = 0; n2 < 8; n2++) {
                uint4 bh = Vh[(n2 * 4 + ks) * 32 + lane];
                mma16816(oacc[n2*2],   A_, bh.x, bh.y);
                mma16816(oacc[n2*2+1], A_, bh.z, bh.w);
                uint4 bl = Vl[(n2 * 4 + ks) * 32 + lane];
                mma16816(oacc[n2*2],   A_, bl.x, bl.y);
                mma16816(oacc[n2*2+1], A_, bl.z, bl.w);
            }
        }
    }

    float inv0 = 1.f / l0, inv1 = 1.f / l1;
#pragma unroll
    for (int nt2 = 0; nt2 < 8; nt2++) {
        float v00 = oacc[nt2*2][0]   * inv0, v01 = oacc[nt2*2][1]   * inv0;
        float v02 = oacc[nt2*2][2]   * inv1, v03 = oacc[nt2*2][3]   * inv1;
        float v10 = oacc[nt2*2+1][0] * inv0, v11 = oacc[nt2*2+1][1] * inv0;
        float v12 = oacc[nt2*2+1][2] * inv1, v13 = oacc[nt2*2+1][3] * inv1;
        __half h00 = __float2half_rn(v00), h01 = __float2half_rn(v01);
        __half h02 = __float2half_rn(v02), h03 = __float2half_rn(v03);
        __half h10 = __float2half_rn(v10), h11 = __float2half_rn(v11);
        __half h12 = __float2half_rn(v12), h13 = __float2half_rn(v13);
        U8h H, L;
        H.h[0] = h00; H.h[1] = h01; H.h[2] = h02; H.h[3] = h03;
        H.h[4] = h10; H.h[5] = h11; H.h[6] = h12; H.h[7] = h13;
        L.h[0] = __float2half_rn(v00 - __half2float(h00));
        L.h[1] = __float2half_rn(v01 - __half2float(h01));
        L.h[2] = __float2half_rn(v02 - __half2float(h02));
        L.h[3] = __float2half_rn(v03 - __half2float(h03));
        L.h[4] = __float2half_rn(v10 - __half2float(h10));
        L.h[5] = __float2half_rn(v11 - __half2float(h11));
        L.h[6] = __float2half_rn(v12 - __half2float(h12));
        L.h[7] = __float2half_rn(v13 - __half2float(h13));
        size_t tt = ((size_t)mt * TILEK + h * 8 + nt2) * 32 + lane;
        aHi[tt] = H.v;
        aLo[tt] = L.v;
    }
}

// ---------------- launch ----------------
extern "C" void kernel_launch(void* const* d_in, const int* in_sizes, int n_in,
                              void* d_out, int out_size)
{
    const float* x     = (const float*)d_in[0];
    const float* freqs = (const float*)d_in[3];
    const float* wq    = (const float*)d_in[4];
    const float* bq    = (const float*)d_in[5];
    const float* wk    = (const float*)d_in[6];
    const float* bk    = (const float*)d_in[7];
    const float* wv    = (const float*)d_in[8];
    const float* bv    = (const float*)d_in[9];
    const float* wo    = (const float*)d_in[10];
    const float* bo    = (const float*)d_in[11];
    const float* nqw   = (const float*)d_in[12];
    const float* nkw   = (const float*)d_in[13];
    float* out = (float*)d_out;

    float *gq, *gk, *gv;
    uint4 *xhi, *xlo, *whi, *wlo, *qA, *kB, *vHi, *vLo;
    cudaGetSymbolAddress((void**)&gq,  g_q);
    cudaGetSymbolAddress((void**)&gk,  g_k);
    cudaGetSymbolAddress((void**)&gv,  g_v);
    cudaGetSymbolAddress((void**)&xhi, g_xhi);
    cudaGetSymbolAddress((void**)&xlo, g_xlo);
    cudaGetSymbolAddress((void**)&whi, g_whi);
    cudaGetSymbolAddress((void**)&wlo, g_wlo);
    cudaGetSymbolAddress((void**)&qA,  g_qA);
    cudaGetSymbolAddress((void**)&kB,  g_kB);
    cudaGetSymbolAddress((void**)&vHi, g_vHi);
    cudaGetSymbolAddress((void**)&vLo, g_vLo);

    cudaFuncSetAttribute(gemm_fp16x3,
                         cudaFuncAttributeMaxDynamicSharedMemorySize, GEMM_SMEM);

    const int blkA = L_TOK * DIM_C / 8 / 256;       // 2304
    const int blkW = 4 * DIM_C * DIM_C / 8 / 256;   // 4608
    dim3 ggrid(DIM_C / 256, L_TOK / 128);           // (6, 24)

    splitA_kernel<<<blkA, 256>>>(x, xhi, xlo);
    splitW4_kernel<<<blkW, 256>>>(wq, wk, wv, wo, whi, wlo);

    gemm_fp16x3<<<ggrid, 256, GEMM_SMEM>>>(xhi, xlo, whi,             wlo,             bq, gq, DIM_C);
    gemm_fp16x3<<<ggrid, 256, GEMM_SMEM>>>(xhi, xlo, whi + WTSZ,      wlo + WTSZ,      bk, gk, DIM_C);
    gemm_fp16x3<<<ggrid, 256, GEMM_SMEM>>>(xhi, xlo, whi + 2 * WTSZ,  wlo + 2 * WTSZ,  bv, gv, DIM_C);

    normrope_kernel<<<L_TOK, 256>>>(gq, gk, freqs, nqw, nkw);

    convQ_kernel<<<blkA, 256>>>(gq, qA);
    convK_kernel<<<blkA, 256>>>(gk, kB);
    convV_kernel<<<blkA, 256>>>(gv, vHi, vLo);

    attn_fp16<<<(L_TOK / 128) * HEADS_C, 256>>>(qA, kB, vHi, vLo, xhi, xlo);

    gemm_fp16x3<<<ggrid, 256, GEMM_SMEM>>>(xhi, xlo, whi + 3 * WTSZ,  wlo + 3 * WTSZ,  bo, out, DIM_C);
}

// round 7
// speedup vs baseline: 4.5027x; 1.0031x over previous
#include <cuda_runtime.h>
#include <cuda_fp16.h>
#include <cuda_bf16.h>
#include <math.h>
#include <stdint.h>

#define L_TOK   3072
#define DIM_C   1536
#define HEADS_C 12
#define HD_C    128
#define FS_C    384
#define W_C     24
#define EPS_C   1e-6f
#define TILEK   96
#define WTSZ    (DIM_C * DIM_C / 8)

// ---------------- scratch ----------------
__device__ float g_q [L_TOK * DIM_C];
__device__ float g_k [L_TOK * DIM_C];
__device__ float g_v [L_TOK * DIM_C];
__device__ uint4 g_xhi[L_TOK * DIM_C / 8];
__device__ uint4 g_xlo[L_TOK * DIM_C / 8];
__device__ uint4 g_whi[4 * WTSZ];
__device__ uint4 g_wlo[4 * WTSZ];
__device__ uint4 g_qA [L_TOK * DIM_C / 8];
__device__ uint4 g_kB [L_TOK * DIM_C / 8];
__device__ uint4 g_vHi[L_TOK * DIM_C / 8];
__device__ uint4 g_vLo[L_TOK * DIM_C / 8];

__device__ __constant__ int QBMAP[24] =
    {15,16,17,18,19,20,21,22,23, 12,13,14, 9,10,11, 6,7,8, 3,4,5, 0,1,2};

union U8h { uint4 v; __half h[8]; };

__device__ __forceinline__ uint32_t smem_u32(const void* p) {
    uint32_t a;
    asm("{ .reg .u64 t; cvta.to.shared.u64 t, %1; cvt.u32.u64 %0, t; }"
        : "=r"(a) : "l"(p));
    return a;
}
__device__ __forceinline__ void cp16(uint32_t dst, const void* src) {
    asm volatile("cp.async.cg.shared.global [%0], [%1], 16;"
                 :: "r"(dst), "l"(src) : "memory");
}
#define CP_COMMIT() asm volatile("cp.async.commit_group;" ::: "memory")
#define CP_WAIT(n)  asm volatile("cp.async.wait_group %0;" :: "n"(n) : "memory")

__device__ __forceinline__ void mma16816(float c[4], const uint32_t a[4],
                                         uint32_t b0, uint32_t b1) {
    asm volatile(
        "mma.sync.aligned.m16n8k16.row.col.f32.f16.f16.f32 "
        "{%0,%1,%2,%3}, {%4,%5,%6,%7}, {%8,%9}, {%0,%1,%2,%3};"
        : "+f"(c[0]), "+f"(c[1]), "+f"(c[2]), "+f"(c[3])
        : "r"(a[0]), "r"(a[1]), "r"(a[2]), "r"(a[3]), "r"(b0), "r"(b1));
}

// ============== operand pre-permute kernels ==============
__global__ __launch_bounds__(256) void splitA_kernel(
    const float* __restrict__ A, uint4* __restrict__ hi, uint4* __restrict__ lo)
{
    int gid = blockIdx.x * 256 + threadIdx.x;
    int tile = gid >> 5, lane = gid & 31;
    int mt = tile / TILEK, kt = tile - mt * TILEK;
    int g = lane >> 2, tg = lane & 3;
    U8h H, L;
#pragma unroll
    for (int s = 0; s < 8; s++) {
        int reg = s >> 1, hb = s & 1;
        int row = mt * 16 + g + ((reg & 1) << 3);
        int col = kt * 16 + ((reg & 2) << 2) + 2 * tg + hb;
        float v = A[(size_t)row * DIM_C + col];
        __half a = __float2half_rn(v);
        H.h[s] = a;
        L.h[s] = __float2half_rn(v - __half2float(a));
    }
    hi[tile * 32 + lane] = H.v;
    lo[tile * 32 + lane] = L.v;
}

__global__ __launch_bounds__(256) void splitW4_kernel(
    const float* __restrict__ w0, const float* __restrict__ w1,
    const float* __restrict__ w2, const float* __restrict__ w3,
    uint4* __restrict__ hi, uint4* __restrict__ lo)
{
    int gid = blockIdx.x * 256 + threadIdx.x;
    int tile = gid >> 5, lane = gid & 31;
    int widx = tile / (TILEK * TILEK);
    int r = tile - widx * (TILEK * TILEK);
    int nt2 = r / TILEK, kt = r - nt2 * TILEK;
    const float* W = (widx == 0) ? w0 : (widx == 1) ? w1 : (widx == 2) ? w2 : w3;
    int g = lane >> 2, tg = lane & 3;
    U8h H, L;
#pragma unroll
    for (int s = 0; s < 8; s++) {
        int j = s >> 2, reg = (s >> 1) & 1, hb = s & 1;
        int n = nt2 * 16 + j * 8 + g;
        int k = kt * 16 + reg * 8 + 2 * tg + hb;
        float v = W[(size_t)n * DIM_C + k];
        __half a = __float2half_rn(v);
        H.h[s] = a;
        L.h[s] = __float2half_rn(v - __half2float(a));
    }
    hi[tile * 32 + lane] = H.v;
    lo[tile * 32 + lane] = L.v;
}

// ============== GEMM: 3-stage, chunk = 3 k16, optional 3rd pass ==============
// stage layout (uint4): A_hi[0,768) A_lo[768,1536) B_hi[1536,3072) B_lo[3072,4608)
#define STG_U4 4608
#define NC_CH  32
#define GEMM_SMEM (3 * STG_U4 * 16)   // 221184 B

__global__ __launch_bounds__(256, 1) void gemm_fp16p(
    const uint4* __restrict__ Ahi, const uint4* __restrict__ Alo,
    const uint4* __restrict__ Bhi, const uint4* __restrict__ Blo,
    const float* __restrict__ bias, float* __restrict__ C, int N, int npass3)
{
    extern __shared__ uint4 sm[];
    const int tid = threadIdx.x, wid = tid >> 5, lane = tid & 31;
    const int g = lane >> 2, tg = lane & 3;
    const int bm8  = blockIdx.y * 8;
    const int bn16 = blockIdx.x * 16;
    const int wmt = (wid >> 2) * 4;
    const int wnt = (wid & 3) * 4;

    float c[4][8][4];
#pragma unroll
    for (int i = 0; i < 4; i++)
#pragma unroll
        for (int j = 0; j < 8; j++)
#pragma unroll
            for (int t = 0; t < 4; t++) c[i][j][t] = 0.f;

#define LOAD_STAGE(slot, chunk) do {                                           \
    uint4* st = sm + (slot) * STG_U4;                                          \
    const int k3 = (chunk) * 3;                                                \
_Pragma("unroll")                                                              \
    for (int a = 0; a < 6; a++) {                                              \
        int idx = tid + a * 256;                                               \
        int hl = idx >= 768; int rem = idx - hl * 768;                         \
        int mt = rem / 96; int r2 = rem - mt * 96;                             \
        int kt = r2 >> 5, ln = r2 & 31;                                        \
        if (!hl || npass3) {                                                   \
            const uint4* src = (hl ? Alo : Ahi)                                \
                + ((size_t)(bm8 + mt) * TILEK + k3 + kt) * 32 + ln;            \
            cp16(smem_u32(st + hl * 768 + (mt * 3 + kt) * 32 + ln), src);      \
        }                                                                      \
    }                                                                          \
_Pragma("unroll")                                                              \
    for (int b = 0; b < 12; b++) {                                             \
        int idx = tid + b * 256;                                               \
        int hl = idx >= 1536; int rem = idx - hl * 1536;                       \
        int nt = rem / 96; int r2 = rem - nt * 96;                             \
        int kt = r2 >> 5, ln = r2 & 31;                                        \
        const uint4* src = (hl ? Blo : Bhi)                                    \
            + ((size_t)(bn16 + nt) * TILEK + k3 + kt) * 32 + ln;               \
        cp16(smem_u32(st + 1536 + hl * 1536 + (nt * 3 + kt) * 32 + ln), src);  \
    }                                                                          \
    CP_COMMIT();                                                               \
} while (0)

    LOAD_STAGE(0, 0);
    LOAD_STAGE(1, 1);

    for (int ck = 0; ck < NC_CH; ck++) {
        const int slot = ck % 3;
        if (ck + 2 < NC_CH) { CP_WAIT(1); } else { CP_WAIT(0); }
        __syncthreads();
        if (ck + 2 < NC_CH) LOAD_STAGE((ck + 2) % 3, ck + 2);

        const uint4* st = sm + slot * STG_U4;
#pragma unroll
        for (int kt = 0; kt < 3; kt++) {
            uint4 Ah[4], Al[4], Bh[4], Bl[4];
#pragma unroll
            for (int i = 0; i < 4; i++) {
                Ah[i] = st[((wmt + i) * 3 + kt) * 32 + lane];
                if (npass3) Al[i] = st[768 + ((wmt + i) * 3 + kt) * 32 + lane];
            }
#pragma unroll
            for (int j = 0; j < 4; j++) {
                Bh[j] = st[1536 + ((wnt + j) * 3 + kt) * 32 + lane];
                Bl[j] = st[3072 + ((wnt + j) * 3 + kt) * 32 + lane];
            }
#pragma unroll
            for (int i = 0; i < 4; i++) {
                uint32_t ah[4] = {Ah[i].x, Ah[i].y, Ah[i].z, Ah[i].w};
#pragma unroll
                for (int j = 0; j < 4; j++) {
                    mma16816(c[i][j*2],   ah, Bh[j].x, Bh[j].y);
                    mma16816(c[i][j*2+1], ah, Bh[j].z, Bh[j].w);
                    mma16816(c[i][j*2],   ah, Bl[j].x, Bl[j].y);
                    mma16816(c[i][j*2+1], ah, Bl[j].z, Bl[j].w);
                }
                if (npass3) {
                    uint32_t al[4] = {Al[i].x, Al[i].y, Al[i].z, Al[i].w};
#pragma unroll
                    for (int j = 0; j < 4; j++) {
                        mma16816(c[i][j*2],   al, Bh[j].x, Bh[j].y);
                        mma16816(c[i][j*2+1], al, Bh[j].z, Bh[j].w);
                    }
                }
            }
        }
    }

#pragma unroll
    for (int i = 0; i < 4; i++) {
        int row0 = (bm8 + wmt + i) * 16 + g;
#pragma unroll
        for (int j = 0; j < 8; j++) {
            int col = (bn16 + wnt + (j >> 1)) * 16 + (j & 1) * 8 + 2 * tg;
            float b0 = bias[col], b1 = bias[col + 1];
            float2 v0 = make_float2(c[i][j][0] + b0, c[i][j][1] + b1);
            float2 v1 = make_float2(c[i][j][2] + b0, c[i][j][3] + b1);
            *(float2*)&C[(size_t)row0 * N + col] = v0;
            *(float2*)&C[(size_t)(row0 + 8) * N + col] = v1;
        }
    }
}

// ---------------- fused RMSNorm + RoPE -> frag-layout fp16 Q / K ------------
__global__ __launch_bounds__(256) void normrope_kernel(
    const float* __restrict__ q, const float* __restrict__ k,
    const float* __restrict__ freqs,
    const float* __restrict__ nqw, const float* __restrict__ nkw,
    uint4* __restrict__ qA, uint4* __restrict__ kB)
{
    const int t = blockIdx.x;
    const int f  = t / FS_C;
    const int rm = t % FS_C;
    const int hh = rm / W_C;
    const int ww = rm % W_C;
    const int tid = threadIdx.x;
    const int grp = tid >> 7;           // 0 = q, 1 = k
    const int gt  = tid & 127;

    __shared__ float fr[64], fi[64];
    __shared__ float red[8];

    if (tid < 64) {
        int c = tid;
        int row = (c < 22) ? f : ((c < 43) ? hh : ww);
        fr[c] = freqs[row * 128 + c * 2 + 0];
        fi[c] = freqs[row * 128 + c * 2 + 1];
    }

    const float* ptr = grp ? k : q;
    const float* w = grp ? nkw : nqw;
    uint4* frag = grp ? kB : qA;

    float v[12], wv[12];
    const int c0 = gt * 12;
#pragma unroll
    for (int j = 0; j < 3; j++) {
        float4 a = *(const float4*)&ptr[(size_t)t * DIM_C + c0 + j * 4];
        float4 b = *(const float4*)&w[c0 + j * 4];
        v[j*4+0] = a.x; v[j*4+1] = a.y; v[j*4+2] = a.z; v[j*4+3] = a.w;
        wv[j*4+0] = b.x; wv[j*4+1] = b.y; wv[j*4+2] = b.z; wv[j*4+3] = b.w;
    }
    float ss = 0.f;
#pragma unroll
    for (int j = 0; j < 12; j++) ss += v[j] * v[j];
    {
        int lane = tid & 31, wd = tid >> 5;
#pragma unroll
        for (int o = 16; o > 0; o >>= 1) ss += __shfl_xor_sync(0xffffffffu, ss, o);
        if (lane == 0) red[wd] = ss;
    }
    __syncthreads();
    float tot = red[grp * 4 + 0] + red[grp * 4 + 1]
              + red[grp * 4 + 2] + red[grp * 4 + 3];
    float rn = rsqrtf(tot * (1.0f / DIM_C) + EPS_C);

    // token -> frag row coords
    const int t16 = t >> 4;            // 16-token tile
    const int bit = (t >> 3) & 1;      // row/key sub-tile bit
    const int gg  = t & 7;

#pragma unroll
    for (int j = 0; j < 6; j++) {
        int p = gt * 6 + j;            // pair index 0..767
        int c = 2 * p;
        int cf = p & 63;
        float a = v[2*j]     * rn * wv[2*j];
        float b = v[2*j + 1] * rn * wv[2*j + 1];
        __half2 hv = __floats2half2_rn(a * fr[cf] - b * fi[cf],
                                       a * fi[cf] + b * fr[cf]);
        int h = c >> 7, ch = c & 127;
        int kt = ch >> 4, low = ch & 15;
        int colbit = low >> 3, tg = (low >> 1) & 3;
        int lane = gg * 4 + tg;
        int byteoff = grp ? (bit * 8 + colbit * 4) : (bit * 4 + colbit * 8);
        char* dst = (char*)frag
            + (size_t)(h * 1536 + t16 * 8 + kt) * 512 + lane * 16 + byteoff;
        *(__half2*)dst = hv;
    }
}

// ================= V fragment conversion =================
__global__ __launch_bounds__(256) void convV_kernel(
    const float* __restrict__ Vmat, uint4* __restrict__ hi, uint4* __restrict__ lo)
{
    int gid = blockIdx.x * 256 + threadIdx.x;
    int tile = gid >> 5, lane = gid & 31;
    int h = tile / 1536, r = tile - h * 1536;
    int nt2 = r / 192, kt = r - nt2 * 192;
    int g = lane >> 2, tg = lane & 3;
    U8h H, L;
#pragma unroll
    for (int s = 0; s < 8; s++) {
        int j = s >> 2, reg = (s >> 1) & 1, hb = s & 1;
        int dim = nt2 * 16 + j * 8 + g;
        int key = kt * 16 + reg * 8 + 2 * tg + hb;
        float v = Vmat[(size_t)key * DIM_C + h * HD_C + dim];
        __half a = __float2half_rn(v);
        H.h[s] = a;
        L.h[s] = __float2half_rn(v - __half2float(a));
    }
    hi[tile * 32 + lane] = H.v;
    lo[tile * 32 + lane] = L.v;
}

// ================= tensor-core flash attention (LPT-ordered) =================
__global__ __launch_bounds__(256) void attn_fp16(
    const uint4* __restrict__ qA, const uint4* __restrict__ kB,
    const uint4* __restrict__ vHi, const uint4* __restrict__ vLo,
    uint4* __restrict__ aHi, uint4* __restrict__ aLo)
{
    __shared__ uint4 Ks[1024];
    __shared__ uint4 Vh[1024];
    __shared__ uint4 Vl[1024];

    const int bi = blockIdx.x;
    const int h  = bi % HEADS_C;
    const int qb = QBMAP[bi / HEADS_C];
    const int tid = threadIdx.x, wid = tid >> 5, lane = tid & 31;
    const int mt = qb * 8 + wid;
    const float scale = 0.08838834764831844f;

    uint32_t qf_[8][4];
#pragma unroll
    for (int kt = 0; kt < 8; kt++) {
        uint4 qv = qA[((size_t)(h * 192 + mt) * 8 + kt) * 32 + lane];
        qf_[kt][0] = qv.x; qf_[kt][1] = qv.y; qf_[kt][2] = qv.z; qf_[kt][3] = qv.w;
    }

    float oacc[16][4];
#pragma unroll
    for (int i = 0; i < 16; i++)
#pragma unroll
        for (int j = 0; j < 4; j++) oacc[i][j] = 0.f;
    float m0 = -1e30f, m1 = -1e30f, l0 = 0.f, l1 = 0.f;

    const int qfr   = qb / 3;
    const int sinkT = (qfr >= 5) ? 6 : 0;
    const int mainF = (qfr >= 5) ? (qfr - 4) * 6 : 0;
    const int mainT = (qfr >= 5) ? 30 : (qfr + 1) * 6;
    const int ntile = sinkT + mainT;

    for (int t = 0; t < ntile; t++) {
        const int kt0 = (t < sinkT) ? t : mainF + (t - sinkT);

        __syncthreads();
        {
            const uint4* kbase = kB + ((size_t)(h * 192 + kt0 * 4) * 8) * 32;
#pragma unroll
            for (int j = 0; j < 4; j++) {
                int idx = tid + j * 256;
                Ks[idx] = kbase[idx];
            }
#pragma unroll
            for (int j = 0; j < 4; j++) {
                int idx = tid + j * 256;
                int nt2 = idx >> 7, rem = idx & 127, jj = rem >> 5, ln = rem & 31;
                size_t a = ((size_t)(h * 8 + nt2) * 192 + kt0 * 4 + jj) * 32 + ln;
                Vh[idx] = vHi[a];
                Vl[idx] = vLo[a];
            }
        }
        __syncthreads();

        float sacc[8][4];
#pragma unroll
        for (int i = 0; i < 8; i++)
#pragma unroll
            for (int j = 0; j < 4; j++) sacc[i][j] = 0.f;

#pragma unroll
        for (int kt = 0; kt < 8; kt++) {
#pragma unroll
            for (int n2 = 0; n2 < 4; n2++) {
                uint4 b = Ks[(n2 * 8 + kt) * 32 + lane];
                mma16816(sacc[n2*2],   qf_[kt], b.x, b.y);
                mma16816(sacc[n2*2+1], qf_[kt], b.z, b.w);
            }
        }

        float rm0 = -1e30f, rm1 = -1e30f;
#pragma unroll
        for (int nt = 0; nt < 8; nt++) {
            sacc[nt][0] *= scale; sacc[nt][1] *= scale;
            sacc[nt][2] *= scale; sacc[nt][3] *= scale;
            rm0 = fmaxf(rm0, fmaxf(sacc[nt][0], sacc[nt][1]));
            rm1 = fmaxf(rm1, fmaxf(sacc[nt][2], sacc[nt][3]));
        }
        rm0 = fmaxf(rm0, __shfl_xor_sync(0xffffffffu, rm0, 1));
        rm0 = fmaxf(rm0, __shfl_xor_sync(0xffffffffu, rm0, 2));
        rm1 = fmaxf(rm1, __shfl_xor_sync(0xffffffffu, rm1, 1));
        rm1 = fmaxf(rm1, __shfl_xor_sync(0xffffffffu, rm1, 2));

        float mn0 = fmaxf(m0, rm0), mn1 = fmaxf(m1, rm1);
        float al0 = __expf(m0 - mn0), al1 = __expf(m1 - mn1);
        m0 = mn0; m1 = mn1;

        float rs0 = 0.f, rs1 = 0.f;
        uint32_t ph0[8], ph1[8];
#pragma unroll
        for (int nt = 0; nt < 8; nt++) {
            float e0 = __expf(sacc[nt][0] - mn0);
            float e1 = __expf(sacc[nt][1] - mn0);
            float e2 = __expf(sacc[nt][2] - mn1);
            float e3 = __expf(sacc[nt][3] - mn1);
            rs0 += e0 + e1; rs1 += e2 + e3;
            __half2 p0 = __floats2half2_rn(e0, e1);
            __half2 p1 = __floats2half2_rn(e2, e3);
            ph0[nt] = *(uint32_t*)&p0;
            ph1[nt] = *(uint32_t*)&p1;
        }
        rs0 += __shfl_xor_sync(0xffffffffu, rs0, 1);
        rs0 += __shfl_xor_sync(0xffffffffu, rs0, 2);
        rs1 += __shfl_xor_sync(0xffffffffu, rs1, 1);
        rs1 += __shfl_xor_sync(0xffffffffu, rs1, 2);
        l0 = l0 * al0 + rs0;
        l1 = l1 * al1 + rs1;

#pragma unroll
        for (int nt = 0; nt < 16; nt++) {
            oacc[nt][0] *= al0; oacc[nt][1] *= al0;
            oacc[nt][2] *= al1; oacc[nt][3] *= al1;
        }

#pragma unroll
        for (int ks = 0; ks < 4; ks++) {
            uint32_t A_[4] = {ph0[2*ks], ph1[2*ks], ph0[2*ks+1], ph1[2*ks+1]};
#pragma unroll
            for (int n2 = 0; n2 < 8; n2++) {
                uint4 bh = Vh[(n2 * 4 + ks) * 32 + lane];
                mma16816(oacc[n2*2],   A_, bh.x, bh.y);
                mma16816(oacc[n2*2+1], A_, bh.z, bh.w);
                uint4 bl = Vl[(n2 * 4 + ks) * 32 + lane];
                mma16816(oacc[n2*2],   A_, bl.x, bl.y);
                mma16816(oacc[n2*2+1], A_, bl.z, bl.w);
            }
        }
    }

    float inv0 = 1.f / l0, inv1 = 1.f / l1;
#pragma unroll
    for (int nt2 = 0; nt2 < 8; nt2++) {
        float v00 = oacc[nt2*2][0]   * inv0, v01 = oacc[nt2*2][1]   * inv0;
        float v02 = oacc[nt2*2][2]   * inv1, v03 = oacc[nt2*2][3]   * inv1;
        float v10 = oacc[nt2*2+1][0] * inv0, v11 = oacc[nt2*2+1][1] * inv0;
        float v12 = oacc[nt2*2+1][2] * inv1, v13 = oacc[nt2*2+1][3] * inv1;
        __half h00 = __float2half_rn(v00), h01 = __float2half_rn(v01);
        __half h02 = __float2half_rn(v02), h03 = __float2half_rn(v03);
        __half h10 = __float2half_rn(v10), h11 = __float2half_rn(v11);
        __half h12 = __float2half_rn(v12), h13 = __float2half_rn(v13);
        U8h H, L;
        H.h[0] = h00; H.h[1] = h01; H.h[2] = h02; H.h[3] = h03;
        H.h[4] = h10; H.h[5] = h11; H.h[6] = h12; H.h[7] = h13;
        L.h[0] = __float2half_rn(v00 - __half2float(h00));
        L.h[1] = __float2half_rn(v01 - __half2float(h01));
        L.h[2] = __float2half_rn(v02 - __half2float(h02));
        L.h[3] = __float2half_rn(v03 - __half2float(h03));
        L.h[4] = __float2half_rn(v10 - __half2float(h10));
        L.h[5] = __float2half_rn(v11 - __half2float(h11));
        L.h[6] = __float2half_rn(v12 - __half2float(h12));
        L.h[7] = __float2half_rn(v13 - __half2float(h13));
        size_t tt = ((size_t)mt * TILEK + h * 8 + nt2) * 32 + lane;
        aHi[tt] = H.v;
        aLo[tt] = L.v;
    }
}

// ---------------- launch ----------------
extern "C" void kernel_launch(void* const* d_in, const int* in_sizes, int n_in,
                              void* d_out, int out_size)
{
    const float* x     = (const float*)d_in[0];
    const float* freqs = (const float*)d_in[3];
    const float* wq    = (const float*)d_in[4];
    const float* bq    = (const float*)d_in[5];
    const float* wk    = (const float*)d_in[6];
    const float* bk    = (const float*)d_in[7];
    const float* wv    = (const float*)d_in[8];
    const float* bv    = (const float*)d_in[9];
    const float* wo    = (const float*)d_in[10];
    const float* bo    = (const float*)d_in[11];
    const float* nqw   = (const float*)d_in[12];
    const float* nkw   = (const float*)d_in[13];
    float* out = (float*)d_out;

    float *gq, *gk, *gv;
    uint4 *xhi, *xlo, *whi, *wlo, *qA, *kB, *vHi, *vLo;
    cudaGetSymbolAddress((void**)&gq,  g_q);
    cudaGetSymbolAddress((void**)&gk,  g_k);
    cudaGetSymbolAddress((void**)&gv,  g_v);
    cudaGetSymbolAddress((void**)&xhi, g_xhi);
    cudaGetSymbolAddress((void**)&xlo, g_xlo);
    cudaGetSymbolAddress((void**)&whi, g_whi);
    cudaGetSymbolAddress((void**)&wlo, g_wlo);
    cudaGetSymbolAddress((void**)&qA,  g_qA);
    cudaGetSymbolAddress((void**)&kB,  g_kB);
    cudaGetSymbolAddress((void**)&vHi, g_vHi);
    cudaGetSymbolAddress((void**)&vLo, g_vLo);

    cudaFuncSetAttribute(gemm_fp16p,
                         cudaFuncAttributeMaxDynamicSharedMemorySize, GEMM_SMEM);

    const int blkA = L_TOK * DIM_C / 8 / 256;       // 2304
    const int blkW = 4 * DIM_C * DIM_C / 8 / 256;   // 4608
    dim3 ggrid(DIM_C / 256, L_TOK / 128);           // (6, 24)

    splitA_kernel<<<blkA, 256>>>(x, xhi, xlo);
    splitW4_kernel<<<blkW, 256>>>(wq, wk, wv, wo, whi, wlo);

    gemm_fp16p<<<ggrid, 256, GEMM_SMEM>>>(xhi, xlo, whi,            wlo,            bq, gq, DIM_C, 1);
    gemm_fp16p<<<ggrid, 256, GEMM_SMEM>>>(xhi, xlo, whi + WTSZ,     wlo + WTSZ,     bk, gk, DIM_C, 1);
    gemm_fp16p<<<ggrid, 256, GEMM_SMEM>>>(xhi, xlo, whi + 2 * WTSZ, wlo + 2 * WTSZ, bv, gv, DIM_C, 1);

    normrope_kernel<<<L_TOK, 256>>>(gq, gk, freqs, nqw, nkw, qA, kB);

    convV_kernel<<<blkA, 256>>>(gv, vHi, vLo);

    attn_fp16<<<(L_TOK / 128) * HEADS_C, 256>>>(qA, kB, vHi, vLo, xhi, xlo);

    // out-projection: 2-pass hi/lo (error budget analysis in theory note)
    gemm_fp16p<<<ggrid, 256, GEMM_SMEM>>>(xhi, xlo, whi + 3 * WTSZ, wlo + 3 * WTSZ, bo, out, DIM_C, 0);
}

// round 8
// speedup vs baseline: 4.7292x; 1.0503x over previous
#include <cuda_runtime.h>
#include <cuda_fp16.h>
#include <cuda_bf16.h>
#include <math.h>
#include <stdint.h>

#define L_TOK   3072
#define DIM_C   1536
#define HEADS_C 12
#define HD_C    128
#define FS_C    384
#define W_C     24
#define EPS_C   1e-6f
#define TILEK   96
#define WTSZ    (DIM_C * DIM_C / 8)

// ---------------- scratch ----------------
__device__ float g_q [L_TOK * DIM_C];
__device__ float g_k [L_TOK * DIM_C];
__device__ float g_v [L_TOK * DIM_C];
__device__ uint4 g_xhi[L_TOK * DIM_C / 8];
__device__ uint4 g_xlo[L_TOK * DIM_C / 8];
__device__ uint4 g_whi[4 * WTSZ];
__device__ uint4 g_wlo[4 * WTSZ];
__device__ uint4 g_qA [L_TOK * DIM_C / 8];
__device__ uint4 g_kB [L_TOK * DIM_C / 8];
__device__ uint4 g_vHi[L_TOK * DIM_C / 8];
__device__ uint4 g_vLo[L_TOK * DIM_C / 8];

__device__ __constant__ int QBMAP[24] =
    {15,16,17,18,19,20,21,22,23, 12,13,14, 9,10,11, 6,7,8, 3,4,5, 0,1,2};

union U8h { uint4 v; __half h[8]; };

__device__ __forceinline__ uint32_t smem_u32(const void* p) {
    uint32_t a;
    asm("{ .reg .u64 t; cvta.to.shared.u64 t, %1; cvt.u32.u64 %0, t; }"
        : "=r"(a) : "l"(p));
    return a;
}
__device__ __forceinline__ void cp16(uint32_t dst, const void* src) {
    asm volatile("cp.async.cg.shared.global [%0], [%1], 16;"
                 :: "r"(dst), "l"(src) : "memory");
}
#define CP_COMMIT() asm volatile("cp.async.commit_group;" ::: "memory")
#define CP_WAIT(n)  asm volatile("cp.async.wait_group %0;" :: "n"(n) : "memory")

__device__ __forceinline__ void mma16816(float c[4], const uint32_t a[4],
                                         uint32_t b0, uint32_t b1) {
    asm volatile(
        "mma.sync.aligned.m16n8k16.row.col.f32.f16.f16.f32 "
        "{%0,%1,%2,%3}, {%4,%5,%6,%7}, {%8,%9}, {%0,%1,%2,%3};"
        : "+f"(c[0]), "+f"(c[1]), "+f"(c[2]), "+f"(c[3])
        : "r"(a[0]), "r"(a[1]), "r"(a[2]), "r"(a[3]), "r"(b0), "r"(b1));
}

// ============== operand pre-permute kernels ==============
__global__ __launch_bounds__(256) void splitA_kernel(
    const float* __restrict__ A, uint4* __restrict__ hi, uint4* __restrict__ lo)
{
    int gid = blockIdx.x * 256 + threadIdx.x;
    int tile = gid >> 5, lane = gid & 31;
    int mt = tile / TILEK, kt = tile - mt * TILEK;
    int g = lane >> 2, tg = lane & 3;
    U8h H, L;
#pragma unroll
    for (int s = 0; s < 8; s++) {
        int reg = s >> 1, hb = s & 1;
        int row = mt * 16 + g + ((reg & 1) << 3);
        int col = kt * 16 + ((reg & 2) << 2) + 2 * tg + hb;
        float v = A[(size_t)row * DIM_C + col];
        __half a = __float2half_rn(v);
        H.h[s] = a;
        L.h[s] = __float2half_rn(v - __half2float(a));
    }
    hi[tile * 32 + lane] = H.v;
    lo[tile * 32 + lane] = L.v;
}

__global__ __launch_bounds__(256) void splitW4_kernel(
    const float* __restrict__ w0, const float* __restrict__ w1,
    const float* __restrict__ w2, const float* __restrict__ w3,
    uint4* __restrict__ hi, uint4* __restrict__ lo)
{
    int gid = blockIdx.x * 256 + threadIdx.x;
    int tile = gid >> 5, lane = gid & 31;
    int widx = tile / (TILEK * TILEK);
    int r = tile - widx * (TILEK * TILEK);
    int nt2 = r / TILEK, kt = r - nt2 * TILEK;
    const float* W = (widx == 0) ? w0 : (widx == 1) ? w1 : (widx == 2) ? w2 : w3;
    int g = lane >> 2, tg = lane & 3;
    U8h H, L;
#pragma unroll
    for (int s = 0; s < 8; s++) {
        int j = s >> 2, reg = (s >> 1) & 1, hb = s & 1;
        int n = nt2 * 16 + j * 8 + g;
        int k = kt * 16 + reg * 8 + 2 * tg + hb;
        float v = W[(size_t)n * DIM_C + k];
        __half a = __float2half_rn(v);
        H.h[s] = a;
        L.h[s] = __float2half_rn(v - __half2float(a));
    }
    hi[tile * 32 + lane] = H.v;
    lo[tile * 32 + lane] = L.v;
}

// ============== GEMM (R6 shape; compile-time pass count) ==============
#define STG_U4 3072
#define GEMM_SMEM (3 * STG_U4 * 16)

template<int NPASS3>
__global__ __launch_bounds__(256, 1) void gemm_fp16t(
    const uint4* __restrict__ Ahi, const uint4* __restrict__ Alo,
    const uint4* __restrict__ Bhi, const uint4* __restrict__ Blo,
    const float* __restrict__ bias, float* __restrict__ C, int N)
{
    extern __shared__ uint4 sm[];
    const int tid = threadIdx.x, wid = tid >> 5, lane = tid & 31;
    const int g = lane >> 2, tg = lane & 3;
    const int bm8  = blockIdx.y * 8;
    const int bn16 = blockIdx.x * 16;
    const int wmt = (wid >> 2) * 4;
    const int wnt = (wid & 3) * 4;

    float c[4][8][4];
#pragma unroll
    for (int i = 0; i < 4; i++)
#pragma unroll
        for (int j = 0; j < 8; j++)
#pragma unroll
            for (int t = 0; t < 4; t++) c[i][j][t] = 0.f;

#define LOAD_STAGE(slot, chunk) do {                                           \
    uint4* st = sm + (slot) * STG_U4;                                          \
    const int k2 = (chunk) * 2;                                                \
_Pragma("unroll")                                                              \
    for (int a = 0; a < 4; a++) {                                              \
        int idx = tid + a * 256;                                               \
        int ln = idx & 31, kt = (idx >> 5) & 1, mt = (idx >> 6) & 7;           \
        int hl = idx >> 9;                                                     \
        if (NPASS3 || hl == 0) {                                               \
            const uint4* src = (hl ? Alo : Ahi)                                \
                + ((size_t)(bm8 + mt) * TILEK + k2 + kt) * 32 + ln;            \
            cp16(smem_u32(st + hl * 512 + mt * 64 + kt * 32 + ln), src);       \
        }                                                                      \
    }                                                                          \
_Pragma("unroll")                                                              \
    for (int b = 0; b < 8; b++) {                                              \
        int idx = tid + b * 256;                                               \
        int ln = idx & 31, kt = (idx >> 5) & 1, nt = (idx >> 6) & 15;          \
        int hl = idx >> 10;                                                    \
        const uint4* src = (hl ? Blo : Bhi)                                    \
            + ((size_t)(bn16 + nt) * TILEK + k2 + kt) * 32 + ln;               \
        cp16(smem_u32(st + 1024 + hl * 1024 + nt * 64 + kt * 32 + ln), src);   \
    }                                                                          \
    CP_COMMIT();                                                               \
} while (0)

    const int NC = TILEK / 2;   // 48
    LOAD_STAGE(0, 0);
    LOAD_STAGE(1, 1);

    for (int ck = 0; ck < NC; ck++) {
        const int slot = ck % 3;
        if (ck + 2 < NC) { CP_WAIT(1); } else { CP_WAIT(0); }
        __syncthreads();
        if (ck + 2 < NC) LOAD_STAGE((ck + 2) % 3, ck + 2);

        const uint4* st = sm + slot * STG_U4;
#pragma unroll
        for (int kt = 0; kt < 2; kt++) {
            uint4 Ah[4], Al[4], Bh[4], Bl[4];
#pragma unroll
            for (int i = 0; i < 4; i++) {
                Ah[i] = st[(wmt + i) * 64 + kt * 32 + lane];
                if (NPASS3) Al[i] = st[512 + (wmt + i) * 64 + kt * 32 + lane];
            }
#pragma unroll
            for (int j = 0; j < 4; j++) {
                Bh[j] = st[1024 + (wnt + j) * 64 + kt * 32 + lane];
                Bl[j] = st[2048 + (wnt + j) * 64 + kt * 32 + lane];
            }
#pragma unroll
            for (int i = 0; i < 4; i++) {
                uint32_t ah[4] = {Ah[i].x, Ah[i].y, Ah[i].z, Ah[i].w};
#pragma unroll
                for (int j = 0; j < 4; j++) {
                    mma16816(c[i][j*2],   ah, Bh[j].x, Bh[j].y);
                    mma16816(c[i][j*2+1], ah, Bh[j].z, Bh[j].w);
                    mma16816(c[i][j*2],   ah, Bl[j].x, Bl[j].y);
                    mma16816(c[i][j*2+1], ah, Bl[j].z, Bl[j].w);
                }
                if (NPASS3) {
                    uint32_t al[4] = {Al[i].x, Al[i].y, Al[i].z, Al[i].w};
#pragma unroll
                    for (int j = 0; j < 4; j++) {
                        mma16816(c[i][j*2],   al, Bh[j].x, Bh[j].y);
                        mma16816(c[i][j*2+1], al, Bh[j].z, Bh[j].w);
                    }
                }
            }
        }
    }

#pragma unroll
    for (int i = 0; i < 4; i++) {
        int row0 = (bm8 + wmt + i) * 16 + g;
#pragma unroll
        for (int j = 0; j < 8; j++) {
            int col = (bn16 + wnt + (j >> 1)) * 16 + (j & 1) * 8 + 2 * tg;
            float b0 = bias[col], b1 = bias[col + 1];
            float2 v0 = make_float2(c[i][j][0] + b0, c[i][j][1] + b1);
            float2 v1 = make_float2(c[i][j][2] + b0, c[i][j][3] + b1);
            *(float2*)&C[(size_t)row0 * N + col] = v0;
            *(float2*)&C[(size_t)(row0 + 8) * N + col] = v1;
        }
    }
}

// ---------------- fused RMSNorm + RoPE -> frag-layout fp16 Q / K ------------
__global__ __launch_bounds__(256) void normrope_kernel(
    const float* __restrict__ q, const float* __restrict__ k,
    const float* __restrict__ freqs,
    const float* __restrict__ nqw, const float* __restrict__ nkw,
    uint4* __restrict__ qA, uint4* __restrict__ kB)
{
    const int t = blockIdx.x;
    const int f  = t / FS_C;
    const int rm = t % FS_C;
    const int hh = rm / W_C;
    const int ww = rm % W_C;
    const int tid = threadIdx.x;
    const int grp = tid >> 7;
    const int gt  = tid & 127;

    __shared__ float fr[64], fi[64];
    __shared__ float red[8];

    if (tid < 64) {
        int c = tid;
        int row = (c < 22) ? f : ((c < 43) ? hh : ww);
        fr[c] = freqs[row * 128 + c * 2 + 0];
        fi[c] = freqs[row * 128 + c * 2 + 1];
    }

    const float* ptr = grp ? k : q;
    const float* w = grp ? nkw : nqw;
    uint4* frag = grp ? kB : qA;

    float v[12], wv[12];
    const int c0 = gt * 12;
#pragma unroll
    for (int j = 0; j < 3; j++) {
        float4 a = *(const float4*)&ptr[(size_t)t * DIM_C + c0 + j * 4];
        float4 b = *(const float4*)&w[c0 + j * 4];
        v[j*4+0] = a.x; v[j*4+1] = a.y; v[j*4+2] = a.z; v[j*4+3] = a.w;
        wv[j*4+0] = b.x; wv[j*4+1] = b.y; wv[j*4+2] = b.z; wv[j*4+3] = b.w;
    }
    float ss = 0.f;
#pragma unroll
    for (int j = 0; j < 12; j++) ss += v[j] * v[j];
    {
        int lane = tid & 31, wd = tid >> 5;
#pragma unroll
        for (int o = 16; o > 0; o >>= 1) ss += __shfl_xor_sync(0xffffffffu, ss, o);
        if (lane == 0) red[wd] = ss;
    }
    __syncthreads();
    float tot = red[grp * 4 + 0] + red[grp * 4 + 1]
              + red[grp * 4 + 2] + red[grp * 4 + 3];
    float rn = rsqrtf(tot * (1.0f / DIM_C) + EPS_C);

    const int t16 = t >> 4;
    const int bit = (t >> 3) & 1;
    const int gg  = t & 7;

#pragma unroll
    for (int j = 0; j < 6; j++) {
        int p = gt * 6 + j;
        int c = 2 * p;
        int cf = p & 63;
        float a = v[2*j]     * rn * wv[2*j];
        float b = v[2*j + 1] * rn * wv[2*j + 1];
        __half2 hv = __floats2half2_rn(a * fr[cf] - b * fi[cf],
                                       a * fi[cf] + b * fr[cf]);
        int h = c >> 7, ch = c & 127;
        int kt = ch >> 4, low = ch & 15;
        int colbit = low >> 3, tg = (low >> 1) & 3;
        int lane = gg * 4 + tg;
        int byteoff = grp ? (bit * 8 + colbit * 4) : (bit * 4 + colbit * 8);
        char* dst = (char*)frag
            + (size_t)(h * 1536 + t16 * 8 + kt) * 512 + lane * 16 + byteoff;
        *(__half2*)dst = hv;
    }
}

// ================= V fragment conversion =================
__global__ __launch_bounds__(256) void convV_kernel(
    const float* __restrict__ Vmat, uint4* __restrict__ hi, uint4* __restrict__ lo)
{
    int gid = blockIdx.x * 256 + threadIdx.x;
    int tile = gid >> 5, lane = gid & 31;
    int h = tile / 1536, r = tile - h * 1536;
    int nt2 = r / 192, kt = r - nt2 * 192;
    int g = lane >> 2, tg = lane & 3;
    U8h H, L;
#pragma unroll
    for (int s = 0; s < 8; s++) {
        int j = s >> 2, reg = (s >> 1) & 1, hb = s & 1;
        int dim = nt2 * 16 + j * 8 + g;
        int key = kt * 16 + reg * 8 + 2 * tg + hb;
        float v = Vmat[(size_t)key * DIM_C + h * HD_C + dim];
        __half a = __float2half_rn(v);
        H.h[s] = a;
        L.h[s] = __float2half_rn(v - __half2float(a));
    }
    hi[tile * 32 + lane] = H.v;
    lo[tile * 32 + lane] = L.v;
}

// ================= tensor-core flash attention (LPT-ordered) =================
__global__ __launch_bounds__(256) void attn_fp16(
    const uint4* __restrict__ qA, const uint4* __restrict__ kB,
    const uint4* __restrict__ vHi, const uint4* __restrict__ vLo,
    uint4* __restrict__ aHi, uint4* __restrict__ aLo)
{
    __shared__ uint4 Ks[1024];
    __shared__ uint4 Vh[1024];
    __shared__ uint4 Vl[1024];

    const int bi = blockIdx.x;
    const int h  = bi % HEADS_C;
    const int qb = QBMAP[bi / HEADS_C];
    const int tid = threadIdx.x, wid = tid >> 5, lane = tid & 31;
    const int mt = qb * 8 + wid;
    const float scale = 0.08838834764831844f;

    uint32_t qf_[8][4];
#pragma unroll
    for (int kt = 0; kt < 8; kt++) {
        uint4 qv = qA[((size_t)(h * 192 + mt) * 8 + kt) * 32 + lane];
        qf_[kt][0] = qv.x; qf_[kt][1] = qv.y; qf_[kt][2] = qv.z; qf_[kt][3] = qv.w;
    }

    float oacc[16][4];
#pragma unroll
    for (int i = 0; i < 16; i++)
#pragma unroll
        for (int j = 0; j < 4; j++) oacc[i][j] = 0.f;
    float m0 = -1e30f, m1 = -1e30f, l0 = 0.f, l1 = 0.f;

    const int qfr   = qb / 3;
    const int sinkT = (qfr >= 5) ? 6 : 0;
    const int mainF = (qfr >= 5) ? (qfr - 4) * 6 : 0;
    const int mainT = (qfr >= 5) ? 30 : (qfr + 1) * 6;
    const int ntile = sinkT + mainT;

    for (int t = 0; t < ntile; t++) {
        const int kt0 = (t < sinkT) ? t : mainF + (t - sinkT);

        __syncthreads();
        {
            const uint4* kbase = kB + ((size_t)(h * 192 + kt0 * 4) * 8) * 32;
#pragma unroll
            for (int j = 0; j < 4; j++) {
                int idx = tid + j * 256;
                Ks[idx] = kbase[idx];
            }
#pragma unroll
            for (int j = 0; j < 4; j++) {
                int idx = tid + j * 256;
                int nt2 = idx >> 7, rem = idx & 127, jj = rem >> 5, ln = rem & 31;
                size_t a = ((size_t)(h * 8 + nt2) * 192 + kt0 * 4 + jj) * 32 + ln;
                Vh[idx] = vHi[a];
                Vl[idx] = vLo[a];
            }
        }
        __syncthreads();

        float sacc[8][4];
#pragma unroll
        for (int i = 0; i < 8; i++)
#pragma unroll
            for (int j = 0; j < 4; j++) sacc[i][j] = 0.f;

#pragma unroll
        for (int kt = 0; kt < 8; kt++) {
#pragma unroll
            for (int n2 = 0; n2 < 4; n2++) {
                uint4 b = Ks[(n2 * 8 + kt) * 32 + lane];
                mma16816(sacc[n2*2],   qf_[kt], b.x, b.y);
                mma16816(sacc[n2*2+1], qf_[kt], b.z, b.w);
            }
        }

        float rm0 = -1e30f, rm1 = -1e30f;
#pragma unroll
        for (int nt = 0; nt < 8; nt++) {
            sacc[nt][0] *= scale; sacc[nt][1] *= scale;
            sacc[nt][2] *= scale; sacc[nt][3] *= scale;
            rm0 = fmaxf(rm0, fmaxf(sacc[nt][0], sacc[nt][1]));
            rm1 = fmaxf(rm1, fmaxf(sacc[nt][2], sacc[nt][3]));
        }
        rm0 = fmaxf(rm0, __shfl_xor_sync(0xffffffffu, rm0, 1));
        rm0 = fmaxf(rm0, __shfl_xor_sync(0xffffffffu, rm0, 2));
        rm1 = fmaxf(rm1, __shfl_xor_sync(0xffffffffu, rm1, 1));
        rm1 = fmaxf(rm1, __shfl_xor_sync(0xffffffffu, rm1, 2));

        float mn0 = fmaxf(m0, rm0), mn1 = fmaxf(m1, rm1);
        float al0 = __expf(m0 - mn0), al1 = __expf(m1 - mn1);
        m0 = mn0; m1 = mn1;

        float rs0 = 0.f, rs1 = 0.f;
        uint32_t ph0[8], ph1[8];
#pragma unroll
        for (int nt = 0; nt < 8; nt++) {
            float e0 = __expf(sacc[nt][0] - mn0);
            float e1 = __expf(sacc[nt][1] - mn0);
            float e2 = __expf(sacc[nt][2] - mn1);
            float e3 = __expf(sacc[nt][3] - mn1);
            rs0 += e0 + e1; rs1 += e2 + e3;
            __half2 p0 = __floats2half2_rn(e0, e1);
            __half2 p1 = __floats2half2_rn(e2, e3);
            ph0[nt] = *(uint32_t*)&p0;
            ph1[nt] = *(uint32_t*)&p1;
        }
        rs0 += __shfl_xor_sync(0xffffffffu, rs0, 1);
        rs0 += __shfl_xor_sync(0xffffffffu, rs0, 2);
        rs1 += __shfl_xor_sync(0xffffffffu, rs1, 1);
        rs1 += __shfl_xor_sync(0xffffffffu, rs1, 2);
        l0 = l0 * al0 + rs0;
        l1 = l1 * al1 + rs1;

#pragma unroll
        for (int nt = 0; nt < 16; nt++) {
            oacc[nt][0] *= al0; oacc[nt][1] *= al0;
            oacc[nt][2] *= al1; oacc[nt][3] *= al1;
        }

#pragma unroll
        for (int ks = 0; ks < 4; ks++) {
            uint32_t A_[4] = {ph0[2*ks], ph1[2*ks], ph0[2*ks+1], ph1[2*ks+1]};
#pragma unroll
            for (int n2 = 0; n2 < 8; n2++) {
                uint4 bh = Vh[(n2 * 4 + ks) * 32 + lane];
                mma16816(oacc[n2*2],   A_, bh.x, bh.y);
                mma16816(oacc[n2*2+1], A_, bh.z, bh.w);
                uint4 bl = Vl[(n2 * 4 + ks) * 32 + lane];
                mma16816(oacc[n2*2],   A_, bl.x, bl.y);
                mma16816(oacc[n2*2+1], A_, bl.z, bl.w);
            }
        }
    }

    float inv0 = 1.f / l0, inv1 = 1.f / l1;
#pragma unroll
    for (int nt2 = 0; nt2 < 8; nt2++) {
        float v00 = oacc[nt2*2][0]   * inv0, v01 = oacc[nt2*2][1]   * inv0;
        float v02 = oacc[nt2*2][2]   * inv1, v03 = oacc[nt2*2][3]   * inv1;
        float v10 = oacc[nt2*2+1][0] * inv0, v11 = oacc[nt2*2+1][1] * inv0;
        float v12 = oacc[nt2*2+1][2] * inv1, v13 = oacc[nt2*2+1][3] * inv1;
        __half h00 = __float2half_rn(v00), h01 = __float2half_rn(v01);
        __half h02 = __float2half_rn(v02), h03 = __float2half_rn(v03);
        __half h10 = __float2half_rn(v10), h11 = __float2half_rn(v11);
        __half h12 = __float2half_rn(v12), h13 = __float2half_rn(v13);
        U8h H, L;
        H.h[0] = h00; H.h[1] = h01; H.h[2] = h02; H.h[3] = h03;
        H.h[4] = h10; H.h[5] = h11; H.h[6] = h12; H.h[7] = h13;
        L.h[0] = __float2half_rn(v00 - __half2float(h00));
        L.h[1] = __float2half_rn(v01 - __half2float(h01));
        L.h[2] = __float2half_rn(v02 - __half2float(h02));
        L.h[3] = __float2half_rn(v03 - __half2float(h03));
        L.h[4] = __float2half_rn(v10 - __half2float(h10));
        L.h[5] = __float2half_rn(v11 - __half2float(h11));
        L.h[6] = __float2half_rn(v12 - __half2float(h12));
        L.h[7] = __float2half_rn(v13 - __half2float(h13));
        size_t tt = ((size_t)mt * TILEK + h * 8 + nt2) * 32 + lane;
        aHi[tt] = H.v;
        aLo[tt] = L.v;
    }
}

// ---------------- launch ----------------
extern "C" void kernel_launch(void* const* d_in, const int* in_sizes, int n_in,
                              void* d_out, int out_size)
{
    const float* x     = (const float*)d_in[0];
    const float* freqs = (const float*)d_in[3];
    const float* wq    = (const float*)d_in[4];
    const float* bq    = (const float*)d_in[5];
    const float* wk    = (const float*)d_in[6];
    const float* bk    = (const float*)d_in[7];
    const float* wv    = (const float*)d_in[8];
    const float* bv    = (const float*)d_in[9];
    const float* wo    = (const float*)d_in[10];
    const float* bo    = (const float*)d_in[11];
    const float* nqw   = (const float*)d_in[12];
    const float* nkw   = (const float*)d_in[13];
    float* out = (float*)d_out;

    float *gq, *gk, *gv;
    uint4 *xhi, *xlo, *whi, *wlo, *qA, *kB, *vHi, *vLo;
    cudaGetSymbolAddress((void**)&gq,  g_q);
    cudaGetSymbolAddress((void**)&gk,  g_k);
    cudaGetSymbolAddress((void**)&gv,  g_v);
    cudaGetSymbolAddress((void**)&xhi, g_xhi);
    cudaGetSymbolAddress((void**)&xlo, g_xlo);
    cudaGetSymbolAddress((void**)&whi, g_whi);
    cudaGetSymbolAddress((void**)&wlo, g_wlo);
    cudaGetSymbolAddress((void**)&qA,  g_qA);
    cudaGetSymbolAddress((void**)&kB,  g_kB);
    cudaGetSymbolAddress((void**)&vHi, g_vHi);
    cudaGetSymbolAddress((void**)&vLo, g_vLo);

    cudaFuncSetAttribute(gemm_fp16t<1>,
                         cudaFuncAttributeMaxDynamicSharedMemorySize, GEMM_SMEM);
    cudaFuncSetAttribute(gemm_fp16t<0>,
                         cudaFuncAttributeMaxDynamicSharedMemorySize, GEMM_SMEM);

    const int blkA = L_TOK * DIM_C / 8 / 256;       // 2304
    const int blkW = 4 * DIM_C * DIM_C / 8 / 256;   // 4608
    dim3 ggrid(DIM_C / 256, L_TOK / 128);           // (6, 24)

    splitA_kernel<<<blkA, 256>>>(x, xhi, xlo);
    splitW4_kernel<<<blkW, 256>>>(wq, wk, wv, wo, whi, wlo);

    gemm_fp16t<1><<<ggrid, 256, GEMM_SMEM>>>(xhi, xlo, whi,            wlo,            bq, gq, DIM_C);
    gemm_fp16t<1><<<ggrid, 256, GEMM_SMEM>>>(xhi, xlo, whi + WTSZ,     wlo + WTSZ,     bk, gk, DIM_C);
    gemm_fp16t<1><<<ggrid, 256, GEMM_SMEM>>>(xhi, xlo, whi + 2 * WTSZ, wlo + 2 * WTSZ, bv, gv, DIM_C);

    normrope_kernel<<<L_TOK, 256>>>(gq, gk, freqs, nqw, nkw, qA, kB);

    convV_kernel<<<blkA, 256>>>(gv, vHi, vLo);

    attn_fp16<<<(L_TOK / 128) * HEADS_C, 256>>>(qA, kB, vHi, vLo, xhi, xlo);

    // out-projection: compile-time 2-pass hi/lo
    gemm_fp16t<0><<<ggrid, 256, GEMM_SMEM>>>(xhi, xlo, whi + 3 * WTSZ, wlo + 3 * WTSZ, bo, out, DIM_C);
}

// round 9
// speedup vs baseline: 4.8908x; 1.0342x over previous
#include <cuda_runtime.h>
#include <cuda_fp16.h>
#include <cuda_bf16.h>
#include <math.h>
#include <stdint.h>

#define L_TOK   3072
#define DIM_C   1536
#define QKV_N   4608
#define HEADS_C 12
#define HD_C    128
#define FS_C    384
#define W_C     24
#define EPS_C   1e-6f
#define TILEK   96
#define WTSZ    (DIM_C * DIM_C / 8)

// ---------------- scratch ----------------
__device__ float g_qkv[L_TOK * QKV_N];       // fused q|k|v projection output
__device__ float g_bias[QKV_N];
__device__ uint4 g_xhi[L_TOK * DIM_C / 8];
__device__ uint4 g_xlo[L_TOK * DIM_C / 8];
__device__ uint4 g_whi[4 * WTSZ];
__device__ uint4 g_wlo[4 * WTSZ];
__device__ uint4 g_qA [L_TOK * DIM_C / 8];
__device__ uint4 g_kB [L_TOK * DIM_C / 8];
__device__ uint4 g_vHi[L_TOK * DIM_C / 8];
__device__ uint4 g_vLo[L_TOK * DIM_C / 8];

__device__ __constant__ int QBMAP[24] =
    {15,16,17,18,19,20,21,22,23, 12,13,14, 9,10,11, 6,7,8, 3,4,5, 0,1,2};

union U8h { uint4 v; __half h[8]; };

__device__ __forceinline__ uint32_t smem_u32(const void* p) {
    uint32_t a;
    asm("{ .reg .u64 t; cvta.to.shared.u64 t, %1; cvt.u32.u64 %0, t; }"
        : "=r"(a) : "l"(p));
    return a;
}
__device__ __forceinline__ void cp16(uint32_t dst, const void* src) {
    asm volatile("cp.async.cg.shared.global [%0], [%1], 16;"
                 :: "r"(dst), "l"(src) : "memory");
}
#define CP_COMMIT() asm volatile("cp.async.commit_group;" ::: "memory")
#define CP_WAIT(n)  asm volatile("cp.async.wait_group %0;" :: "n"(n) : "memory")

__device__ __forceinline__ void mma16816(float c[4], const uint32_t a[4],
                                         uint32_t b0, uint32_t b1) {
    asm volatile(
        "mma.sync.aligned.m16n8k16.row.col.f32.f16.f16.f32 "
        "{%0,%1,%2,%3}, {%4,%5,%6,%7}, {%8,%9}, {%0,%1,%2,%3};"
        : "+f"(c[0]), "+f"(c[1]), "+f"(c[2]), "+f"(c[3])
        : "r"(a[0]), "r"(a[1]), "r"(a[2]), "r"(a[3]), "r"(b0), "r"(b1));
}

// ============== bias concat ==============
__global__ void concat_bias(const float* __restrict__ bq,
                            const float* __restrict__ bk,
                            const float* __restrict__ bv,
                            float* __restrict__ out)
{
    int i = blockIdx.x * 256 + threadIdx.x;
    if (i < QKV_N)
        out[i] = (i < 1536) ? bq[i] : (i < 3072 ? bk[i - 1536] : bv[i - 3072]);
}

// ============== operand pre-permute kernels ==============
__global__ __launch_bounds__(256) void splitA_kernel(
    const float* __restrict__ A, uint4* __restrict__ hi, uint4* __restrict__ lo)
{
    int gid = blockIdx.x * 256 + threadIdx.x;
    int tile = gid >> 5, lane = gid & 31;
    int mt = tile / TILEK, kt = tile - mt * TILEK;
    int g = lane >> 2, tg = lane & 3;
    U8h H, L;
#pragma unroll
    for (int s2 = 0; s2 < 4; s2++) {       // pairs (hb=0,1) are consecutive cols
        int reg = s2;
        int row = mt * 16 + g + ((reg & 1) << 3);
        int col = kt * 16 + ((reg & 2) << 2) + 2 * tg;
        float2 v = *(const float2*)&A[(size_t)row * DIM_C + col];
        __half ax = __float2half_rn(v.x), ay = __float2half_rn(v.y);
        H.h[s2 * 2]     = ax;
        H.h[s2 * 2 + 1] = ay;
        L.h[s2 * 2]     = __float2half_rn(v.x - __half2float(ax));
        L.h[s2 * 2 + 1] = __float2half_rn(v.y - __half2float(ay));
    }
    hi[tile * 32 + lane] = H.v;
    lo[tile * 32 + lane] = L.v;
}

__global__ __launch_bounds__(256) void splitW4_kernel(
    const float* __restrict__ w0, const float* __restrict__ w1,
    const float* __restrict__ w2, const float* __restrict__ w3,
    uint4* __restrict__ hi, uint4* __restrict__ lo)
{
    int gid = blockIdx.x * 256 + threadIdx.x;
    int tile = gid >> 5, lane = gid & 31;
    int widx = tile / (TILEK * TILEK);
    int r = tile - widx * (TILEK * TILEK);
    int nt2 = r / TILEK, kt = r - nt2 * TILEK;
    const float* W = (widx == 0) ? w0 : (widx == 1) ? w1 : (widx == 2) ? w2 : w3;
    int g = lane >> 2, tg = lane & 3;
    U8h H, L;
#pragma unroll
    for (int s2 = 0; s2 < 4; s2++) {
        int j = s2 >> 1, reg = s2 & 1;
        int n = nt2 * 16 + j * 8 + g;
        int k = kt * 16 + reg * 8 + 2 * tg;
        float2 v = *(const float2*)&W[(size_t)n * DIM_C + k];
        __half ax = __float2half_rn(v.x), ay = __float2half_rn(v.y);
        H.h[s2 * 2]     = ax;
        H.h[s2 * 2 + 1] = ay;
        L.h[s2 * 2]     = __float2half_rn(v.x - __half2float(ax));
        L.h[s2 * 2 + 1] = __float2half_rn(v.y - __half2float(ay));
    }
    hi[tile * 32 + lane] = H.v;
    lo[tile * 32 + lane] = L.v;
}

// ============== GEMM (R6 shape; compile-time pass count) ==============
#define STG_U4 3072
#define GEMM_SMEM (3 * STG_U4 * 16)

template<int NPASS3>
__global__ __launch_bounds__(256, 1) void gemm_fp16t(
    const uint4* __restrict__ Ahi, const uint4* __restrict__ Alo,
    const uint4* __restrict__ Bhi, const uint4* __restrict__ Blo,
    const float* __restrict__ bias, float* __restrict__ C, int N)
{
    extern __shared__ uint4 sm[];
    const int tid = threadIdx.x, wid = tid >> 5, lane = tid & 31;
    const int g = lane >> 2, tg = lane & 3;
    const int bm8  = blockIdx.y * 8;
    const int bn16 = blockIdx.x * 16;
    const int wmt = (wid >> 2) * 4;
    const int wnt = (wid & 3) * 4;

    float c[4][8][4];
#pragma unroll
    for (int i = 0; i < 4; i++)
#pragma unroll
        for (int j = 0; j < 8; j++)
#pragma unroll
            for (int t = 0; t < 4; t++) c[i][j][t] = 0.f;

#define LOAD_STAGE(slot, chunk) do {                                           \
    uint4* st = sm + (slot) * STG_U4;                                          \
    const int k2 = (chunk) * 2;                                                \
_Pragma("unroll")                                                              \
    for (int a = 0; a < 4; a++) {                                              \
        int idx = tid + a * 256;                                               \
        int ln = idx & 31, kt = (idx >> 5) & 1, mt = (idx >> 6) & 7;           \
        int hl = idx >> 9;                                                     \
        if (NPASS3 || hl == 0) {                                               \
            const uint4* src = (hl ? Alo : Ahi)                                \
                + ((size_t)(bm8 + mt) * TILEK + k2 + kt) * 32 + ln;            \
            cp16(smem_u32(st + hl * 512 + mt * 64 + kt * 32 + ln), src);       \
        }                                                                      \
    }                                                                          \
_Pragma("unroll")                                                              \
    for (int b = 0; b < 8; b++) {                                              \
        int idx = tid + b * 256;                                               \
        int ln = idx & 31, kt = (idx >> 5) & 1, nt = (idx >> 6) & 15;          \
        int hl = idx >> 10;                                                    \
        const uint4* src = (hl ? Blo : Bhi)                                    \
            + ((size_t)(bn16 + nt) * TILEK + k2 + kt) * 32 + ln;               \
        cp16(smem_u32(st + 1024 + hl * 1024 + nt * 64 + kt * 32 + ln), src);   \
    }                                                                          \
    CP_COMMIT();                                                               \
} while (0)

    const int NC = TILEK / 2;   // 48
    LOAD_STAGE(0, 0);
    LOAD_STAGE(1, 1);

    for (int ck = 0; ck < NC; ck++) {
        const int slot = ck % 3;
        if (ck + 2 < NC) { CP_WAIT(1); } else { CP_WAIT(0); }
        __syncthreads();
        if (ck + 2 < NC) LOAD_STAGE((ck + 2) % 3, ck + 2);

        const uint4* st = sm + slot * STG_U4;
#pragma unroll
        for (int kt = 0; kt < 2; kt++) {
            uint4 Ah[4], Al[4], Bh[4], Bl[4];
#pragma unroll
            for (int i = 0; i < 4; i++) {
                Ah[i] = st[(wmt + i) * 64 + kt * 32 + lane];
                if (NPASS3) Al[i] = st[512 + (wmt + i) * 64 + kt * 32 + lane];
            }
#pragma unroll
            for (int j = 0; j < 4; j++) {
                Bh[j] = st[1024 + (wnt + j) * 64 + kt * 32 + lane];
                Bl[j] = st[2048 + (wnt + j) * 64 + kt * 32 + lane];
            }
#pragma unroll
            for (int i = 0; i < 4; i++) {
                uint32_t ah[4] = {Ah[i].x, Ah[i].y, Ah[i].z, Ah[i].w};
#pragma unroll
                for (int j = 0; j < 4; j++) {
                    mma16816(c[i][j*2],   ah, Bh[j].x, Bh[j].y);
                    mma16816(c[i][j*2+1], ah, Bh[j].z, Bh[j].w);
                    mma16816(c[i][j*2],   ah, Bl[j].x, Bl[j].y);
                    mma16816(c[i][j*2+1], ah, Bl[j].z, Bl[j].w);
                }
                if (NPASS3) {
                    uint32_t al[4] = {Al[i].x, Al[i].y, Al[i].z, Al[i].w};
#pragma unroll
                    for (int j = 0; j < 4; j++) {
                        mma16816(c[i][j*2],   al, Bh[j].x, Bh[j].y);
                        mma16816(c[i][j*2+1], al, Bh[j].z, Bh[j].w);
                    }
                }
            }
        }
    }

#pragma unroll
    for (int i = 0; i < 4; i++) {
        int row0 = (bm8 + wmt + i) * 16 + g;
#pragma unroll
        for (int j = 0; j < 8; j++) {
            int col = (bn16 + wnt + (j >> 1)) * 16 + (j & 1) * 8 + 2 * tg;
            float b0 = bias[col], b1 = bias[col + 1];
            float2 v0 = make_float2(c[i][j][0] + b0, c[i][j][1] + b1);
            float2 v1 = make_float2(c[i][j][2] + b0, c[i][j][3] + b1);
            *(float2*)&C[(size_t)row0 * N + col] = v0;
            *(float2*)&C[(size_t)(row0 + 8) * N + col] = v1;
        }
    }
}

// ---------------- fused RMSNorm + RoPE -> frag-layout fp16 Q / K ------------
__global__ __launch_bounds__(256) void normrope_kernel(
    const float* __restrict__ qkv,
    const float* __restrict__ freqs,
    const float* __restrict__ nqw, const float* __restrict__ nkw,
    uint4* __restrict__ qA, uint4* __restrict__ kB)
{
    const int t = blockIdx.x;
    const int f  = t / FS_C;
    const int rm = t % FS_C;
    const int hh = rm / W_C;
    const int ww = rm % W_C;
    const int tid = threadIdx.x;
    const int grp = tid >> 7;
    const int gt  = tid & 127;

    __shared__ float fr[64], fi[64];
    __shared__ float red[8];

    if (tid < 64) {
        int c = tid;
        int row = (c < 22) ? f : ((c < 43) ? hh : ww);
        fr[c] = freqs[row * 128 + c * 2 + 0];
        fi[c] = freqs[row * 128 + c * 2 + 1];
    }

    const float* ptr = qkv + (size_t)t * QKV_N + grp * 1536;
    const float* w = grp ? nkw : nqw;
    uint4* frag = grp ? kB : qA;

    float v[12], wv[12];
    const int c0 = gt * 12;
#pragma unroll
    for (int j = 0; j < 3; j++) {
        float4 a = *(const float4*)&ptr[c0 + j * 4];
        float4 b = *(const float4*)&w[c0 + j * 4];
        v[j*4+0] = a.x; v[j*4+1] = a.y; v[j*4+2] = a.z; v[j*4+3] = a.w;
        wv[j*4+0] = b.x; wv[j*4+1] = b.y; wv[j*4+2] = b.z; wv[j*4+3] = b.w;
    }
    float ss = 0.f;
#pragma unroll
    for (int j = 0; j < 12; j++) ss += v[j] * v[j];
    {
        int lane = tid & 31, wd = tid >> 5;
#pragma unroll
        for (int o = 16; o > 0; o >>= 1) ss += __shfl_xor_sync(0xffffffffu, ss, o);
        if (lane == 0) red[wd] = ss;
    }
    __syncthreads();
    float tot = red[grp * 4 + 0] + red[grp * 4 + 1]
              + red[grp * 4 + 2] + red[grp * 4 + 3];
    float rn = rsqrtf(tot * (1.0f / DIM_C) + EPS_C);

    const int t16 = t >> 4;
    const int bit = (t >> 3) & 1;
    const int gg  = t & 7;

#pragma unroll
    for (int j = 0; j < 6; j++) {
        int p = gt * 6 + j;
        int c = 2 * p;
        int cf = p & 63;
        float a = v[2*j]     * rn * wv[2*j];
        float b = v[2*j + 1] * rn * wv[2*j + 1];
        __half2 hv = __floats2half2_rn(a * fr[cf] - b * fi[cf],
                                       a * fi[cf] + b * fr[cf]);
        int h = c >> 7, ch = c & 127;
        int kt = ch >> 4, low = ch & 15;
        int colbit = low >> 3, tg = (low >> 1) & 3;
        int lane = gg * 4 + tg;
        int byteoff = grp ? (bit * 8 + colbit * 4) : (bit * 4 + colbit * 8);
        char* dst = (char*)frag
            + (size_t)(h * 1536 + t16 * 8 + kt) * 512 + lane * 16 + byteoff;
        *(__half2*)dst = hv;
    }
}

// ================= V fragment conversion =================
__global__ __launch_bounds__(256) void convV_kernel(
    const float* __restrict__ qkv, uint4* __restrict__ hi, uint4* __restrict__ lo)
{
    int gid = blockIdx.x * 256 + threadIdx.x;
    int tile = gid >> 5, lane = gid & 31;
    int h = tile / 1536, r = tile - h * 1536;
    int nt2 = r / 192, kt = r - nt2 * 192;
    int g = lane >> 2, tg = lane & 3;
    const float* V = qkv + 3072;      // v section, row stride QKV_N
    U8h H, L;
#pragma unroll
    for (int s2 = 0; s2 < 4; s2++) {
        int j = s2 >> 1, reg = s2 & 1;
        int dim = nt2 * 16 + j * 8 + g;
        int key = kt * 16 + reg * 8 + 2 * tg;
        float2 v = *(const float2*)&V[(size_t)key * QKV_N + h * HD_C + dim - 0];
        // NOTE: consecutive elements along KEY are NOT contiguous in memory;
        // the contiguous axis is dim. Load scalars instead for correctness.
        (void)v;
        float va = V[(size_t)key * QKV_N + h * HD_C + dim];
        float vb = V[(size_t)(key + 1) * QKV_N + h * HD_C + dim];
        __half ax = __float2half_rn(va), ay = __float2half_rn(vb);
        H.h[s2 * 2]     = ax;
        H.h[s2 * 2 + 1] = ay;
        L.h[s2 * 2]     = __float2half_rn(va - __half2float(ax));
        L.h[s2 * 2 + 1] = __float2half_rn(vb - __half2float(ay));
    }
    hi[tile * 32 + lane] = H.v;
    lo[tile * 32 + lane] = L.v;
}

// ================= tensor-core flash attention (cp.async double-buffer) =====
#define ATTN_SMEM (2 * 3 * 1024 * 16)   // 2 buffers x (Ks,Vh,Vl) x 16KB

__global__ __launch_bounds__(256) void attn_fp16(
    const uint4* __restrict__ qA, const uint4* __restrict__ kB,
    const uint4* __restrict__ vHi, const uint4* __restrict__ vLo,
    uint4* __restrict__ aHi, uint4* __restrict__ aLo)
{
    extern __shared__ uint4 smA[];
    // layout per buffer: Ks[1024], Vh[1024], Vl[1024]
    const int bi = blockIdx.x;
    const int h  = bi % HEADS_C;
    const int qb = QBMAP[bi / HEADS_C];
    const int tid = threadIdx.x, wid = tid >> 5, lane = tid & 31;
    const int mt = qb * 8 + wid;
    const float scale = 0.08838834764831844f;

    uint32_t qf_[8][4];
#pragma unroll
    for (int kt = 0; kt < 8; kt++) {
        uint4 qv = qA[((size_t)(h * 192 + mt) * 8 + kt) * 32 + lane];
        qf_[kt][0] = qv.x; qf_[kt][1] = qv.y; qf_[kt][2] = qv.z; qf_[kt][3] = qv.w;
    }

    float oacc[16][4];
#pragma unroll
    for (int i = 0; i < 16; i++)
#pragma unroll
        for (int j = 0; j < 4; j++) oacc[i][j] = 0.f;
    float m0 = -1e30f, m1 = -1e30f, l0 = 0.f, l1 = 0.f;

    const int qfr   = qb / 3;
    const int sinkT = (qfr >= 5) ? 6 : 0;
    const int mainF = (qfr >= 5) ? (qfr - 4) * 6 : 0;
    const int mainT = (qfr >= 5) ? 30 : (qfr + 1) * 6;
    const int ntile = sinkT + mainT;

#define ATTN_LOAD(buf, kt0) do {                                               \
    uint4* bb = smA + (buf) * 3072;                                            \
    const uint4* kbase = kB + ((size_t)(h * 192 + (kt0) * 4) * 8) * 32;        \
_Pragma("unroll")                                                              \
    for (int j = 0; j < 4; j++) {                                              \
        int idx = tid + j * 256;                                               \
        cp16(smem_u32(bb + idx), kbase + idx);                                 \
    }                                                                          \
_Pragma("unroll")                                                              \
    for (int j = 0; j < 4; j++) {                                              \
        int idx = tid + j * 256;                                               \
        int nt2 = idx >> 7, rem = idx & 127, jj = rem >> 5, ln = rem & 31;     \
        size_t a = ((size_t)(h * 8 + nt2) * 192 + (kt0) * 4 + jj) * 32 + ln;   \
        cp16(smem_u32(bb + 1024 + idx), vHi + a);                              \
        cp16(smem_u32(bb + 2048 + idx), vLo + a);                              \
    }                                                                          \
    CP_COMMIT();                                                               \
} while (0)

    {
        const int kt0 = (0 < sinkT) ? 0 : mainF;
        ATTN_LOAD(0, kt0);
    }

    for (int t = 0; t < ntile; t++) {
        __syncthreads();   // everyone done reading buffer (t+1)&1 from iter t-1
        if (t + 1 < ntile) {
            const int ktn = (t + 1 < sinkT) ? (t + 1) : mainF + (t + 1 - sinkT);
            ATTN_LOAD((t + 1) & 1, ktn);
            CP_WAIT(1);
        } else {
            CP_WAIT(0);
        }
        __syncthreads();   // tile t's cp.async data visible to all

        const uint4* Ks = smA + (t & 1) * 3072;
        const uint4* Vh = Ks + 1024;
        const uint4* Vl = Ks + 2048;

        float sacc[8][4];
#pragma unroll
        for (int i = 0; i < 8; i++)
#pragma unroll
            for (int j = 0; j < 4; j++) sacc[i][j] = 0.f;

#pragma unroll
        for (int kt = 0; kt < 8; kt++) {
#pragma unroll
            for (int n2 = 0; n2 < 4; n2++) {
                uint4 b = Ks[(n2 * 8 + kt) * 32 + lane];
                mma16816(sacc[n2*2],   qf_[kt], b.x, b.y);
                mma16816(sacc[n2*2+1], qf_[kt], b.z, b.w);
            }
        }

        float rm0 = -1e30f, rm1 = -1e30f;
#pragma unroll
        for (int nt = 0; nt < 8; nt++) {
            sacc[nt][0] *= scale; sacc[nt][1] *= scale;
            sacc[nt][2] *= scale; sacc[nt][3] *= scale;
            rm0 = fmaxf(rm0, fmaxf(sacc[nt][0], sacc[nt][1]));
            rm1 = fmaxf(rm1, fmaxf(sacc[nt][2], sacc[nt][3]));
        }
        rm0 = fmaxf(rm0, __shfl_xor_sync(0xffffffffu, rm0, 1));
        rm0 = fmaxf(rm0, __shfl_xor_sync(0xffffffffu, rm0, 2));
        rm1 = fmaxf(rm1, __shfl_xor_sync(0xffffffffu, rm1, 1));
        rm1 = fmaxf(rm1, __shfl_xor_sync(0xffffffffu, rm1, 2));

        float mn0 = fmaxf(m0, rm0), mn1 = fmaxf(m1, rm1);
        float al0 = __expf(m0 - mn0), al1 = __expf(m1 - mn1);
        m0 = mn0; m1 = mn1;

        float rs0 = 0.f, rs1 = 0.f;
        uint32_t ph0[8], ph1[8];
#pragma unroll
        for (int nt = 0; nt < 8; nt++) {
            float e0 = __expf(sacc[nt][0] - mn0);
            float e1 = __expf(sacc[nt][1] - mn0);
            float e2 = __expf(sacc[nt][2] - mn1);
            float e3 = __expf(sacc[nt][3] - mn1);
            rs0 += e0 + e1; rs1 += e2 + e3;
            __half2 p0 = __floats2half2_rn(e0, e1);
            __half2 p1 = __floats2half2_rn(e2, e3);
            ph0[nt] = *(uint32_t*)&p0;
            ph1[nt] = *(uint32_t*)&p1;
        }
        rs0 += __shfl_xor_sync(0xffffffffu, rs0, 1);
        rs0 += __shfl_xor_sync(0xffffffffu, rs0, 2);
        rs1 += __shfl_xor_sync(0xffffffffu, rs1, 1);
        rs1 += __shfl_xor_sync(0xffffffffu, rs1, 2);
        l0 = l0 * al0 + rs0;
        l1 = l1 * al1 + rs1;

#pragma unroll
        for (int nt = 0; nt < 16; nt++) {
            oacc[nt][0] *= al0; oacc[nt][1] *= al0;
            oacc[nt][2] *= al1; oacc[nt][3] *= al1;
        }

#pragma unroll
        for (int ks = 0; ks < 4; ks++) {
            uint32_t A_[4] = {ph0[2*ks], ph1[2*ks], ph0[2*ks+1], ph1[2*ks+1]};
#pragma unroll
            for (int n2 = 0; n2 < 8; n2++) {
                uint4 bh = Vh[(n2 * 4 + ks) * 32 + lane];
                mma16816(oacc[n2*2],   A_, bh.x, bh.y);
                mma16816(oacc[n2*2+1], A_, bh.z, bh.w);
                uint4 bl = Vl[(n2 * 4 + ks) * 32 + lane];
                mma16816(oacc[n2*2],   A_, bl.x, bl.y);
                mma16816(oacc[n2*2+1], A_, bl.z, bl.w);
            }
        }
    }

    float inv0 = 1.f / l0, inv1 = 1.f / l1;
#pragma unroll
    for (int nt2 = 0; nt2 < 8; nt2++) {
        float v00 = oacc[nt2*2][0]   * inv0, v01 = oacc[nt2*2][1]   * inv0;
        float v02 = oacc[nt2*2][2]   * inv1, v03 = oacc[nt2*2][3]   * inv1;
        float v10 = oacc[nt2*2+1][0] * inv0, v11 = oacc[nt2*2+1][1] * inv0;
        float v12 = oacc[nt2*2+1][2] * inv1, v13 = oacc[nt2*2+1][3] * inv1;
        __half h00 = __float2half_rn(v00), h01 = __float2half_rn(v01);
        __half h02 = __float2half_rn(v02), h03 = __float2half_rn(v03);
        __half h10 = __float2half_rn(v10), h11 = __float2half_rn(v11);
        __half h12 = __float2half_rn(v12), h13 = __float2half_rn(v13);
        U8h H, L;
        H.h[0] = h00; H.h[1] = h01; H.h[2] = h02; H.h[3] = h03;
        H.h[4] = h10; H.h[5] = h11; H.h[6] = h12; H.h[7] = h13;
        L.h[0] = __float2half_rn(v00 - __half2float(h00));
        L.h[1] = __float2half_rn(v01 - __half2float(h01));
        L.h[2] = __float2half_rn(v02 - __half2float(h02));
        L.h[3] = __float2half_rn(v03 - __half2float(h03));
        L.h[4] = __float2half_rn(v10 - __half2float(h10));
        L.h[5] = __float2half_rn(v11 - __half2float(h11));
        L.h[6] = __float2half_rn(v12 - __half2float(h12));
        L.h[7] = __float2half_rn(v13 - __half2float(h13));
        size_t tt = ((size_t)mt * TILEK + h * 8 + nt2) * 32 + lane;
        aHi[tt] = H.v;
        aLo[tt] = L.v;
    }
}

// ---------------- launch ----------------
extern "C" void kernel_launch(void* const* d_in, const int* in_sizes, int n_in,
                              void* d_out, int out_size)
{
    const float* x     = (const float*)d_in[0];
    const float* freqs = (const float*)d_in[3];
    const float* wq    = (const float*)d_in[4];
    const float* bq    = (const float*)d_in[5];
    const float* wk    = (const float*)d_in[6];
    const float* bk    = (const float*)d_in[7];
    const float* wv    = (const float*)d_in[8];
    const float* bv    = (const float*)d_in[9];
    const float* wo    = (const float*)d_in[10];
    const float* bo    = (const float*)d_in[11];
    const float* nqw   = (const float*)d_in[12];
    const float* nkw   = (const float*)d_in[13];
    float* out = (float*)d_out;

    float *qkv, *bias;
    uint4 *xhi, *xlo, *whi, *wlo, *qA, *kB, *vHi, *vLo;
    cudaGetSymbolAddress((void**)&qkv,  g_qkv);
    cudaGetSymbolAddress((void**)&bias, g_bias);
    cudaGetSymbolAddress((void**)&xhi, g_xhi);
    cudaGetSymbolAddress((void**)&xlo, g_xlo);
    cudaGetSymbolAddress((void**)&whi, g_whi);
    cudaGetSymbolAddress((void**)&wlo, g_wlo);
    cudaGetSymbolAddress((void**)&qA,  g_qA);
    cudaGetSymbolAddress((void**)&kB,  g_kB);
    cudaGetSymbolAddress((void**)&vHi, g_vHi);
    cudaGetSymbolAddress((void**)&vLo, g_vLo);

    cudaFuncSetAttribute(gemm_fp16t<1>,
                         cudaFuncAttributeMaxDynamicSharedMemorySize, GEMM_SMEM);
    cudaFuncSetAttribute(gemm_fp16t<0>,
                         cudaFuncAttributeMaxDynamicSharedMemorySize, GEMM_SMEM);
    cudaFuncSetAttribute(attn_fp16,
                         cudaFuncAttributeMaxDynamicSharedMemorySize, ATTN_SMEM);

    const int blkA = L_TOK * DIM_C / 8 / 256;       // 2304
    const int blkW = 4 * DIM_C * DIM_C / 8 / 256;   // 4608

    splitA_kernel<<<blkA, 256>>>(x, xhi, xlo);
    splitW4_kernel<<<blkW, 256>>>(wq, wk, wv, wo, whi, wlo);
    concat_bias<<<(QKV_N + 255) / 256, 256>>>(bq, bk, bv, bias);

    // fused QKV projection: N = 4608, B-frags are contiguous across wq|wk|wv
    dim3 gqkv(QKV_N / 256, L_TOK / 128);            // (18, 24)
    gemm_fp16t<1><<<gqkv, 256, GEMM_SMEM>>>(xhi, xlo, whi, wlo, bias, qkv, QKV_N);

    normrope_kernel<<<L_TOK, 256>>>(qkv, freqs, nqw, nkw, qA, kB);
    convV_kernel<<<blkA, 256>>>(qkv, vHi, vLo);

    attn_fp16<<<(L_TOK / 128) * HEADS_C, 256, ATTN_SMEM>>>(qA, kB, vHi, vLo, xhi, xlo);

    dim3 gout(DIM_C / 256, L_TOK / 128);            // (6, 24)
    gemm_fp16t<0><<<gout, 256, GEMM_SMEM>>>(xhi, xlo, whi + 3 * WTSZ, wlo + 3 * WTSZ, bo, out, DIM_C);
}

// round 10
// speedup vs baseline: 4.9252x; 1.0070x over previous
#include <cuda_runtime.h>
#include <cuda_fp16.h>
#include <cuda_bf16.h>
#include <math.h>
#include <stdint.h>

#define L_TOK   3072
#define DIM_C   1536
#define QKV_N   4608
#define HEADS_C 12
#define HD_C    128
#define FS_C    384
#define W_C     24
#define EPS_C   1e-6f
#define TILEK   96
#define WTSZ    (DIM_C * DIM_C / 8)

// ---------------- scratch ----------------
__device__ float g_qkv[L_TOK * QKV_N];
__device__ float g_bias[QKV_N];
__device__ uint4 g_xhi[L_TOK * DIM_C / 8];
__device__ uint4 g_xlo[L_TOK * DIM_C / 8];
__device__ uint4 g_whi[4 * WTSZ];
__device__ uint4 g_wlo[4 * WTSZ];
__device__ uint4 g_qA [L_TOK * DIM_C / 8];
__device__ uint4 g_kB [L_TOK * DIM_C / 8];
__device__ uint4 g_vHi[L_TOK * DIM_C / 8];
__device__ uint4 g_vLo[L_TOK * DIM_C / 8];

__device__ __constant__ int QBMAP[24] =
    {15,16,17,18,19,20,21,22,23, 12,13,14, 9,10,11, 6,7,8, 3,4,5, 0,1,2};

union U8h { uint4 v; __half h[8]; };

__device__ __forceinline__ uint32_t smem_u32(const void* p) {
    uint32_t a;
    asm("{ .reg .u64 t; cvta.to.shared.u64 t, %1; cvt.u32.u64 %0, t; }"
        : "=r"(a) : "l"(p));
    return a;
}
__device__ __forceinline__ void cp16(uint32_t dst, const void* src) {
    asm volatile("cp.async.cg.shared.global [%0], [%1], 16;"
                 :: "r"(dst), "l"(src) : "memory");
}
#define CP_COMMIT() asm volatile("cp.async.commit_group;" ::: "memory")
#define CP_WAIT(n)  asm volatile("cp.async.wait_group %0;" :: "n"(n) : "memory")

__device__ __forceinline__ void mma16816(float c[4], const uint32_t a[4],
                                         uint32_t b0, uint32_t b1) {
    asm volatile(
        "mma.sync.aligned.m16n8k16.row.col.f32.f16.f16.f32 "
        "{%0,%1,%2,%3}, {%4,%5,%6,%7}, {%8,%9}, {%0,%1,%2,%3};"
        : "+f"(c[0]), "+f"(c[1]), "+f"(c[2]), "+f"(c[3])
        : "r"(a[0]), "r"(a[1]), "r"(a[2]), "r"(a[3]), "r"(b0), "r"(b1));
}

// ============== bias concat ==============
__global__ void concat_bias(const float* __restrict__ bq,
                            const float* __restrict__ bk,
                            const float* __restrict__ bv,
                            float* __restrict__ out)
{
    int i = blockIdx.x * 256 + threadIdx.x;
    if (i < QKV_N)
        out[i] = (i < 1536) ? bq[i] : (i < 3072 ? bk[i - 1536] : bv[i - 3072]);
}

// ============== operand pre-permute kernels ==============
__global__ __launch_bounds__(256) void splitA_kernel(
    const float* __restrict__ A, uint4* __restrict__ hi, uint4* __restrict__ lo)
{
    int gid = blockIdx.x * 256 + threadIdx.x;
    int tile = gid >> 5, lane = gid & 31;
    int mt = tile / TILEK, kt = tile - mt * TILEK;
    int g = lane >> 2, tg = lane & 3;
    U8h H, L;
#pragma unroll
    for (int s2 = 0; s2 < 4; s2++) {
        int reg = s2;
        int row = mt * 16 + g + ((reg & 1) << 3);
        int col = kt * 16 + ((reg & 2) << 2) + 2 * tg;
        float2 v = *(const float2*)&A[(size_t)row * DIM_C + col];
        __half ax = __float2half_rn(v.x), ay = __float2half_rn(v.y);
        H.h[s2 * 2]     = ax;
        H.h[s2 * 2 + 1] = ay;
        L.h[s2 * 2]     = __float2half_rn(v.x - __half2float(ax));
        L.h[s2 * 2 + 1] = __float2half_rn(v.y - __half2float(ay));
    }
    hi[tile * 32 + lane] = H.v;
    lo[tile * 32 + lane] = L.v;
}

__global__ __launch_bounds__(256) void splitW4_kernel(
    const float* __restrict__ w0, const float* __restrict__ w1,
    const float* __restrict__ w2, const float* __restrict__ w3,
    uint4* __restrict__ hi, uint4* __restrict__ lo)
{
    int gid = blockIdx.x * 256 + threadIdx.x;
    int tile = gid >> 5, lane = gid & 31;
    int widx = tile / (TILEK * TILEK);
    int r = tile - widx * (TILEK * TILEK);
    int nt2 = r / TILEK, kt = r - nt2 * TILEK;
    const float* W = (widx == 0) ? w0 : (widx == 1) ? w1 : (widx == 2) ? w2 : w3;
    int g = lane >> 2, tg = lane & 3;
    U8h H, L;
#pragma unroll
    for (int s2 = 0; s2 < 4; s2++) {
        int j = s2 >> 1, reg = s2 & 1;
        int n = nt2 * 16 + j * 8 + g;
        int k = kt * 16 + reg * 8 + 2 * tg;
        float2 v = *(const float2*)&W[(size_t)n * DIM_C + k];
        __half ax = __float2half_rn(v.x), ay = __float2half_rn(v.y);
        H.h[s2 * 2]     = ax;
        H.h[s2 * 2 + 1] = ay;
        L.h[s2 * 2]     = __float2half_rn(v.x - __half2float(ax));
        L.h[s2 * 2 + 1] = __float2half_rn(v.y - __half2float(ay));
    }
    hi[tile * 32 + lane] = H.v;
    lo[tile * 32 + lane] = L.v;
}

// ============== GEMM: 4-stage pipeline, compile-time pass count ==============
#define STG_U4 3072
#define GEMM_SMEM (4 * STG_U4 * 16)   // 196608 B

template<int NPASS3>
__global__ __launch_bounds__(256, 1) void gemm_fp16t(
    const uint4* __restrict__ Ahi, const uint4* __restrict__ Alo,
    const uint4* __restrict__ Bhi, const uint4* __restrict__ Blo,
    const float* __restrict__ bias, float* __restrict__ C, int N)
{
    extern __shared__ uint4 sm[];
    const int tid = threadIdx.x, wid = tid >> 5, lane = tid & 31;
    const int g = lane >> 2, tg = lane & 3;
    const int bm8  = blockIdx.y * 8;
    const int bn16 = blockIdx.x * 16;
    const int wmt = (wid >> 2) * 4;
    const int wnt = (wid & 3) * 4;

    float c[4][8][4];
#pragma unroll
    for (int i = 0; i < 4; i++)
#pragma unroll
        for (int j = 0; j < 8; j++)
#pragma unroll
            for (int t = 0; t < 4; t++) c[i][j][t] = 0.f;

#define LOAD_STAGE(slot, chunk) do {                                           \
    uint4* st = sm + (slot) * STG_U4;                                          \
    const int k2 = (chunk) * 2;                                                \
_Pragma("unroll")                                                              \
    for (int a = 0; a < 4; a++) {                                              \
        int idx = tid + a * 256;                                               \
        int ln = idx & 31, kt = (idx >> 5) & 1, mt = (idx >> 6) & 7;           \
        int hl = idx >> 9;                                                     \
        if (NPASS3 || hl == 0) {                                               \
            const uint4* src = (hl ? Alo : Ahi)                                \
                + ((size_t)(bm8 + mt) * TILEK + k2 + kt) * 32 + ln;            \
            cp16(smem_u32(st + hl * 512 + mt * 64 + kt * 32 + ln), src);       \
        }                                                                      \
    }                                                                          \
_Pragma("unroll")                                                              \
    for (int b = 0; b < 8; b++) {                                              \
        int idx = tid + b * 256;                                               \
        int ln = idx & 31, kt = (idx >> 5) & 1, nt = (idx >> 6) & 15;          \
        int hl = idx >> 10;                                                    \
        const uint4* src = (hl ? Blo : Bhi)                                    \
            + ((size_t)(bn16 + nt) * TILEK + k2 + kt) * 32 + ln;               \
        cp16(smem_u32(st + 1024 + hl * 1024 + nt * 64 + kt * 32 + ln), src);   \
    }                                                                          \
    CP_COMMIT();                                                               \
} while (0)

    const int NC = TILEK / 2;   // 48
    LOAD_STAGE(0, 0);
    LOAD_STAGE(1, 1);
    LOAD_STAGE(2, 2);

    for (int ck = 0; ck < NC; ck++) {
        const int slot = ck & 3;
        if (ck + 3 < NC) { CP_WAIT(2); } else { CP_WAIT(0); }
        __syncthreads();
        if (ck + 3 < NC) LOAD_STAGE((ck + 3) & 3, ck + 3);

        const uint4* st = sm + slot * STG_U4;
#pragma unroll
        for (int kt = 0; kt < 2; kt++) {
            uint4 Ah[4], Al[4], Bh[4], Bl[4];
#pragma unroll
            for (int i = 0; i < 4; i++) {
                Ah[i] = st[(wmt + i) * 64 + kt * 32 + lane];
                if (NPASS3) Al[i] = st[512 + (wmt + i) * 64 + kt * 32 + lane];
            }
#pragma unroll
            for (int j = 0; j < 4; j++) {
                Bh[j] = st[1024 + (wnt + j) * 64 + kt * 32 + lane];
                Bl[j] = st[2048 + (wnt + j) * 64 + kt * 32 + lane];
            }
#pragma unroll
            for (int i = 0; i < 4; i++) {
                uint32_t ah[4] = {Ah[i].x, Ah[i].y, Ah[i].z, Ah[i].w};
#pragma unroll
                for (int j = 0; j < 4; j++) {
                    mma16816(c[i][j*2],   ah, Bh[j].x, Bh[j].y);
                    mma16816(c[i][j*2+1], ah, Bh[j].z, Bh[j].w);
                    mma16816(c[i][j*2],   ah, Bl[j].x, Bl[j].y);
                    mma16816(c[i][j*2+1], ah, Bl[j].z, Bl[j].w);
                }
                if (NPASS3) {
                    uint32_t al[4] = {Al[i].x, Al[i].y, Al[i].z, Al[i].w};
#pragma unroll
                    for (int j = 0; j < 4; j++) {
                        mma16816(c[i][j*2],   al, Bh[j].x, Bh[j].y);
                        mma16816(c[i][j*2+1], al, Bh[j].z, Bh[j].w);
                    }
                }
            }
        }
    }

#pragma unroll
    for (int i = 0; i < 4; i++) {
        int row0 = (bm8 + wmt + i) * 16 + g;
#pragma unroll
        for (int j = 0; j < 8; j++) {
            int col = (bn16 + wnt + (j >> 1)) * 16 + (j & 1) * 8 + 2 * tg;
            float b0 = bias[col], b1 = bias[col + 1];
            float2 v0 = make_float2(c[i][j][0] + b0, c[i][j][1] + b1);
            float2 v1 = make_float2(c[i][j][2] + b0, c[i][j][3] + b1);
            *(float2*)&C[(size_t)row0 * N + col] = v0;
            *(float2*)&C[(size_t)(row0 + 8) * N + col] = v1;
        }
    }
}

// ---------------- fused RMSNorm + RoPE -> frag-layout fp16 Q / K ------------
__global__ __launch_bounds__(256) void normrope_kernel(
    const float* __restrict__ qkv,
    const float* __restrict__ freqs,
    const float* __restrict__ nqw, const float* __restrict__ nkw,
    uint4* __restrict__ qA, uint4* __restrict__ kB)
{
    const int t = blockIdx.x;
    const int f  = t / FS_C;
    const int rm = t % FS_C;
    const int hh = rm / W_C;
    const int ww = rm % W_C;
    const int tid = threadIdx.x;
    const int grp = tid >> 7;
    const int gt  = tid & 127;

    __shared__ float fr[64], fi[64];
    __shared__ float red[8];

    if (tid < 64) {
        int c = tid;
        int row = (c < 22) ? f : ((c < 43) ? hh : ww);
        fr[c] = freqs[row * 128 + c * 2 + 0];
        fi[c] = freqs[row * 128 + c * 2 + 1];
    }

    const float* ptr = qkv + (size_t)t * QKV_N + grp * 1536;
    const float* w = grp ? nkw : nqw;
    uint4* frag = grp ? kB : qA;

    float v[12], wv[12];
    const int c0 = gt * 12;
#pragma unroll
    for (int j = 0; j < 3; j++) {
        float4 a = *(const float4*)&ptr[c0 + j * 4];
        float4 b = *(const float4*)&w[c0 + j * 4];
        v[j*4+0] = a.x; v[j*4+1] = a.y; v[j*4+2] = a.z; v[j*4+3] = a.w;
        wv[j*4+0] = b.x; wv[j*4+1] = b.y; wv[j*4+2] = b.z; wv[j*4+3] = b.w;
    }
    float ss = 0.f;
#pragma unroll
    for (int j = 0; j < 12; j++) ss += v[j] * v[j];
    {
        int lane = tid & 31, wd = tid >> 5;
#pragma unroll
        for (int o = 16; o > 0; o >>= 1) ss += __shfl_xor_sync(0xffffffffu, ss, o);
        if (lane == 0) red[wd] = ss;
    }
    __syncthreads();
    float tot = red[grp * 4 + 0] + red[grp * 4 + 1]
              + red[grp * 4 + 2] + red[grp * 4 + 3];
    float rn = rsqrtf(tot * (1.0f / DIM_C) + EPS_C);

    const int t16 = t >> 4;
    const int bit = (t >> 3) & 1;
    const int gg  = t & 7;

#pragma unroll
    for (int j = 0; j < 6; j++) {
        int p = gt * 6 + j;
        int c = 2 * p;
        int cf = p & 63;
        float a = v[2*j]     * rn * wv[2*j];
        float b = v[2*j + 1] * rn * wv[2*j + 1];
        __half2 hv = __floats2half2_rn(a * fr[cf] - b * fi[cf],
                                       a * fi[cf] + b * fr[cf]);
        int h = c >> 7, ch = c & 127;
        int kt = ch >> 4, low = ch & 15;
        int colbit = low >> 3, tg = (low >> 1) & 3;
        int lane = gg * 4 + tg;
        int byteoff = grp ? (bit * 8 + colbit * 4) : (bit * 4 + colbit * 8);
        char* dst = (char*)frag
            + (size_t)(h * 1536 + t16 * 8 + kt) * 512 + lane * 16 + byteoff;
        *(__half2*)dst = hv;
    }
}

// ================= V fragment conversion (smem-staged, coalesced) ==========
// block = one (head h, key16 group kt); stage 16x128 V tile in padded smem.
__global__ __launch_bounds__(256) void convV_kernel(
    const float* __restrict__ qkv, uint4* __restrict__ hi, uint4* __restrict__ lo)
{
    __shared__ float vs[16 * 132];   // pad 132 -> conflict-free gather
    const int b = blockIdx.x;
    const int h = b / 192, kt = b - h * 192;
    const int tid = threadIdx.x;
    const float* V = qkv + 3072 + (size_t)kt * 16 * QKV_N + h * HD_C;

    // coalesced load: 16 rows x 128 cols = 512 float4, 2 per thread
#pragma unroll
    for (int it = 0; it < 2; it++) {
        int idx = tid + it * 256;          // float4 index
        int row = idx >> 5, col4 = idx & 31;
        float4 x = *(const float4*)&V[(size_t)row * QKV_N + col4 * 4];
        *(float4*)&vs[row * 132 + col4 * 4] = x;
    }
    __syncthreads();

    // gather frags: warp = nt2 (dim/16 tile), lane fixed by frag layout
    const int nt2 = tid >> 5, lane = tid & 31;
    const int g = lane >> 2, tg = lane & 3;
    U8h H, L;
#pragma unroll
    for (int s2 = 0; s2 < 4; s2++) {
        int j = s2 >> 1, reg = s2 & 1;
        int dim = nt2 * 16 + j * 8 + g;
        int key = reg * 8 + 2 * tg;
        float va = vs[key * 132 + dim];
        float vb = vs[(key + 1) * 132 + dim];
        __half ax = __float2half_rn(va), ay = __float2half_rn(vb);
        H.h[s2 * 2]     = ax;
        H.h[s2 * 2 + 1] = ay;
        L.h[s2 * 2]     = __float2half_rn(va - __half2float(ax));
        L.h[s2 * 2 + 1] = __float2half_rn(vb - __half2float(ay));
    }
    size_t tile = (size_t)h * 1536 + nt2 * 192 + kt;
    hi[tile * 32 + lane] = H.v;
    lo[tile * 32 + lane] = L.v;
}

// ================= tensor-core flash attention (cp.async double-buffer) =====
#define ATTN_SMEM (2 * 3 * 1024 * 16)

__global__ __launch_bounds__(256) void attn_fp16(
    const uint4* __restrict__ qA, const uint4* __restrict__ kB,
    const uint4* __restrict__ vHi, const uint4* __restrict__ vLo,
    uint4* __restrict__ aHi, uint4* __restrict__ aLo)
{
    extern __shared__ uint4 smA[];
    const int bi = blockIdx.x;
    const int h  = bi % HEADS_C;
    const int qb = QBMAP[bi / HEADS_C];
    const int tid = threadIdx.x, wid = tid >> 5, lane = tid & 31;
    const int mt = qb * 8 + wid;
    const float scale = 0.08838834764831844f;

    uint32_t qf_[8][4];
#pragma unroll
    for (int kt = 0; kt < 8; kt++) {
        uint4 qv = qA[((size_t)(h * 192 + mt) * 8 + kt) * 32 + lane];
        qf_[kt][0] = qv.x; qf_[kt][1] = qv.y; qf_[kt][2] = qv.z; qf_[kt][3] = qv.w;
    }

    float oacc[16][4];
#pragma unroll
    for (int i = 0; i < 16; i++)
#pragma unroll
        for (int j = 0; j < 4; j++) oacc[i][j] = 0.f;
    float m0 = -1e30f, m1 = -1e30f, l0 = 0.f, l1 = 0.f;

    const int qfr   = qb / 3;
    const int sinkT = (qfr >= 5) ? 6 : 0;
    const int mainF = (qfr >= 5) ? (qfr - 4) * 6 : 0;
    const int mainT = (qfr >= 5) ? 30 : (qfr + 1) * 6;
    const int ntile = sinkT + mainT;

#define ATTN_LOAD(buf, kt0) do {                                               \
    uint4* bb = smA + (buf) * 3072;                                            \
    const uint4* kbase = kB + ((size_t)(h * 192 + (kt0) * 4) * 8) * 32;        \
_Pragma("unroll")                                                              \
    for (int j = 0; j < 4; j++) {                                              \
        int idx = tid + j * 256;                                               \
        cp16(smem_u32(bb + idx), kbase + idx);                                 \
    }                                                                          \
_Pragma("unroll")                                                              \
    for (int j = 0; j < 4; j++) {                                              \
        int idx = tid + j * 256;                                               \
        int nt2 = idx >> 7, rem = idx & 127, jj = rem >> 5, ln = rem & 31;     \
        size_t a = ((size_t)(h * 8 + nt2) * 192 + (kt0) * 4 + jj) * 32 + ln;   \
        cp16(smem_u32(bb + 1024 + idx), vHi + a);                              \
        cp16(smem_u32(bb + 2048 + idx), vLo + a);                              \
    }                                                                          \
    CP_COMMIT();                                                               \
} while (0)

    {
        const int kt0 = (0 < sinkT) ? 0 : mainF;
        ATTN_LOAD(0, kt0);
    }

    for (int t = 0; t < ntile; t++) {
        __syncthreads();
        if (t + 1 < ntile) {
            const int ktn = (t + 1 < sinkT) ? (t + 1) : mainF + (t + 1 - sinkT);
            ATTN_LOAD((t + 1) & 1, ktn);
            CP_WAIT(1);
        } else {
            CP_WAIT(0);
        }
        __syncthreads();

        const uint4* Ks = smA + (t & 1) * 3072;
        const uint4* Vh = Ks + 1024;
        const uint4* Vl = Ks + 2048;

        float sacc[8][4];
#pragma unroll
        for (int i = 0; i < 8; i++)
#pragma unroll
            for (int j = 0; j < 4; j++) sacc[i][j] = 0.f;

#pragma unroll
        for (int kt = 0; kt < 8; kt++) {
#pragma unroll
            for (int n2 = 0; n2 < 4; n2++) {
                uint4 b = Ks[(n2 * 8 + kt) * 32 + lane];
                mma16816(sacc[n2*2],   qf_[kt], b.x, b.y);
                mma16816(sacc[n2*2+1], qf_[kt], b.z, b.w);
            }
        }

        float rm0 = -1e30f, rm1 = -1e30f;
#pragma unroll
        for (int nt = 0; nt < 8; nt++) {
            sacc[nt][0] *= scale; sacc[nt][1] *= scale;
            sacc[nt][2] *= scale; sacc[nt][3] *= scale;
            rm0 = fmaxf(rm0, fmaxf(sacc[nt][0], sacc[nt][1]));
            rm1 = fmaxf(rm1, fmaxf(sacc[nt][2], sacc[nt][3]));
        }
        rm0 = fmaxf(rm0, __shfl_xor_sync(0xffffffffu, rm0, 1));
        rm0 = fmaxf(rm0, __shfl_xor_sync(0xffffffffu, rm0, 2));
        rm1 = fmaxf(rm1, __shfl_xor_sync(0xffffffffu, rm1, 1));
        rm1 = fmaxf(rm1, __shfl_xor_sync(0xffffffffu, rm1, 2));

        float mn0 = fmaxf(m0, rm0), mn1 = fmaxf(m1, rm1);
        float al0 = __expf(m0 - mn0), al1 = __expf(m1 - mn1);
        m0 = mn0; m1 = mn1;

        float rs0 = 0.f, rs1 = 0.f;
        uint32_t ph0[8], ph1[8];
#pragma unroll
        for (int nt = 0; nt < 8; nt++) {
            float e0 = __expf(sacc[nt][0] - mn0);
            float e1 = __expf(sacc[nt][1] - mn0);
            float e2 = __expf(sacc[nt][2] - mn1);
            float e3 = __expf(sacc[nt][3] - mn1);
            rs0 += e0 + e1; rs1 += e2 + e3;
            __half2 p0 = __floats2half2_rn(e0, e1);
            __half2 p1 = __floats2half2_rn(e2, e3);
            ph0[nt] = *(uint32_t*)&p0;
            ph1[nt] = *(uint32_t*)&p1;
        }
        rs0 += __shfl_xor_sync(0xffffffffu, rs0, 1);
        rs0 += __shfl_xor_sync(0xffffffffu, rs0, 2);
        rs1 += __shfl_xor_sync(0xffffffffu, rs1, 1);
        rs1 += __shfl_xor_sync(0xffffffffu, rs1, 2);
        l0 = l0 * al0 + rs0;
        l1 = l1 * al1 + rs1;

#pragma unroll
        for (int nt = 0; nt < 16; nt++) {
            oacc[nt][0] *= al0; oacc[nt][1] *= al0;
            oacc[nt][2] *= al1; oacc[nt][3] *= al1;
        }

#pragma unroll
        for (int ks = 0; ks < 4; ks++) {
            uint32_t A_[4] = {ph0[2*ks], ph1[2*ks], ph0[2*ks+1], ph1[2*ks+1]};
#pragma unroll
            for (int n2 = 0; n2 < 8; n2++) {
                uint4 bh = Vh[(n2 * 4 + ks) * 32 + lane];
                mma16816(oacc[n2*2],   A_, bh.x, bh.y);
                mma16816(oacc[n2*2+1], A_, bh.z, bh.w);
                uint4 bl = Vl[(n2 * 4 + ks) * 32 + lane];
                mma16816(oacc[n2*2],   A_, bl.x, bl.y);
                mma16816(oacc[n2*2+1], A_, bl.z, bl.w);
            }
        }
    }

    float inv0 = 1.f / l0, inv1 = 1.f / l1;
#pragma unroll
    for (int nt2 = 0; nt2 < 8; nt2++) {
        float v00 = oacc[nt2*2][0]   * inv0, v01 = oacc[nt2*2][1]   * inv0;
        float v02 = oacc[nt2*2][2]   * inv1, v03 = oacc[nt2*2][3]   * inv1;
        float v10 = oacc[nt2*2+1][0] * inv0, v11 = oacc[nt2*2+1][1] * inv0;
        float v12 = oacc[nt2*2+1][2] * inv1, v13 = oacc[nt2*2+1][3] * inv1;
        __half h00 = __float2half_rn(v00), h01 = __float2half_rn(v01);
        __half h02 = __float2half_rn(v02), h03 = __float2half_rn(v03);
        __half h10 = __float2half_rn(v10), h11 = __float2half_rn(v11);
        __half h12 = __float2half_rn(v12), h13 = __float2half_rn(v13);
        U8h H, L;
        H.h[0] = h00; H.h[1] = h01; H.h[2] = h02; H.h[3] = h03;
        H.h[4] = h10; H.h[5] = h11; H.h[6] = h12; H.h[7] = h13;
        L.h[0] = __float2half_rn(v00 - __half2float(h00));
        L.h[1] = __float2half_rn(v01 - __half2float(h01));
        L.h[2] = __float2half_rn(v02 - __half2float(h02));
        L.h[3] = __float2half_rn(v03 - __half2float(h03));
        L.h[4] = __float2half_rn(v10 - __half2float(h10));
        L.h[5] = __float2half_rn(v11 - __half2float(h11));
        L.h[6] = __float2half_rn(v12 - __half2float(h12));
        L.h[7] = __float2half_rn(v13 - __half2float(h13));
        size_t tt = ((size_t)mt * TILEK + h * 8 + nt2) * 32 + lane;
        aHi[tt] = H.v;
        aLo[tt] = L.v;
    }
}

// ---------------- launch ----------------
extern "C" void kernel_launch(void* const* d_in, const int* in_sizes, int n_in,
                              void* d_out, int out_size)
{
    const float* x     = (const float*)d_in[0];
    const float* freqs = (const float*)d_in[3];
    const float* wq    = (const float*)d_in[4];
    const float* bq    = (const float*)d_in[5];
    const float* wk    = (const float*)d_in[6];
    const float* bk    = (const float*)d_in[7];
    const float* wv    = (const float*)d_in[8];
    const float* bv    = (const float*)d_in[9];
    const float* wo    = (const float*)d_in[10];
    const float* bo    = (const float*)d_in[11];
    const float* nqw   = (const float*)d_in[12];
    const float* nkw   = (const float*)d_in[13];
    float* out = (float*)d_out;

    float *qkv, *bias;
    uint4 *xhi, *xlo, *whi, *wlo, *qA, *kB, *vHi, *vLo;
    cudaGetSymbolAddress((void**)&qkv,  g_qkv);
    cudaGetSymbolAddress((void**)&bias, g_bias);
    cudaGetSymbolAddress((void**)&xhi, g_xhi);
    cudaGetSymbolAddress((void**)&xlo, g_xlo);
    cudaGetSymbolAddress((void**)&whi, g_whi);
    cudaGetSymbolAddress((void**)&wlo, g_wlo);
    cudaGetSymbolAddress((void**)&qA,  g_qA);
    cudaGetSymbolAddress((void**)&kB,  g_kB);
    cudaGetSymbolAddress((void**)&vHi, g_vHi);
    cudaGetSymbolAddress((void**)&vLo, g_vLo);

    cudaFuncSetAttribute(gemm_fp16t<1>,
                         cudaFuncAttributeMaxDynamicSharedMemorySize, GEMM_SMEM);
    cudaFuncSetAttribute(gemm_fp16t<0>,
                         cudaFuncAttributeMaxDynamicSharedMemorySize, GEMM_SMEM);
    cudaFuncSetAttribute(attn_fp16,
                         cudaFuncAttributeMaxDynamicSharedMemorySize, ATTN_SMEM);

    const int blkA = L_TOK * DIM_C / 8 / 256;       // 2304
    const int blkW = 4 * DIM_C * DIM_C / 8 / 256;   // 4608

    splitA_kernel<<<blkA, 256>>>(x, xhi, xlo);
    splitW4_kernel<<<blkW, 256>>>(wq, wk, wv, wo, whi, wlo);
    concat_bias<<<(QKV_N + 255) / 256, 256>>>(bq, bk, bv, bias);

    dim3 gqkv(QKV_N / 256, L_TOK / 128);            // (18, 24)
    gemm_fp16t<1><<<gqkv, 256, GEMM_SMEM>>>(xhi, xlo, whi, wlo, bias, qkv, QKV_N);

    normrope_kernel<<<L_TOK, 256>>>(qkv, freqs, nqw, nkw, qA, kB);
    convV_kernel<<<HEADS_C * 192, 256>>>(qkv, vHi, vLo);

    attn_fp16<<<(L_TOK / 128) * HEADS_C, 256, ATTN_SMEM>>>(qA, kB, vHi, vLo, xhi, xlo);

    dim3 gout(DIM_C / 256, L_TOK / 128);            // (6, 24)
    gemm_fp16t<0><<<gout, 256, GEMM_SMEM>>>(xhi, xlo, whi + 3 * WTSZ, wlo + 3 * WTSZ, bo, out, DIM_C);
}

// round 11
// speedup vs baseline: 5.8785x; 1.1936x over previous
#include <cuda_runtime.h>
#include <cuda_fp16.h>
#include <cuda_bf16.h>
#include <math.h>
#include <stdint.h>

#define L_TOK   3072
#define DIM_C   1536
#define QKV_N   4608
#define HEADS_C 12
#define HD_C    128
#define FS_C    384
#define W_C     24
#define EPS_C   1e-6f
#define TILEK   96
#define WTSZ    (DIM_C * DIM_C / 8)

// ---------------- scratch ----------------
__device__ float g_qkv[L_TOK * QKV_N];
__device__ float g_bias[QKV_N];
__device__ uint4 g_xhi[L_TOK * DIM_C / 8];
__device__ uint4 g_whi[4 * WTSZ];
__device__ uint4 g_wlo[4 * WTSZ];
__device__ uint4 g_qA [L_TOK * DIM_C / 8];
__device__ uint4 g_kB [L_TOK * DIM_C / 8];
__device__ uint4 g_vHi[L_TOK * DIM_C / 8];
__device__ uint4 g_vLo[L_TOK * DIM_C / 8];

__device__ __constant__ int QBMAP[24] =
    {15,16,17,18,19,20,21,22,23, 12,13,14, 9,10,11, 6,7,8, 3,4,5, 0,1,2};

union U8h { uint4 v; __half h[8]; };

__device__ __forceinline__ uint32_t smem_u32(const void* p) {
    uint32_t a;
    asm("{ .reg .u64 t; cvta.to.shared.u64 t, %1; cvt.u32.u64 %0, t; }"
        : "=r"(a) : "l"(p));
    return a;
}
__device__ __forceinline__ void cp16(uint32_t dst, const void* src) {
    asm volatile("cp.async.cg.shared.global [%0], [%1], 16;"
                 :: "r"(dst), "l"(src) : "memory");
}
#define CP_COMMIT() asm volatile("cp.async.commit_group;" ::: "memory")
#define CP_WAIT(n)  asm volatile("cp.async.wait_group %0;" :: "n"(n) : "memory")

__device__ __forceinline__ void mma16816(float c[4], const uint32_t a[4],
                                         uint32_t b0, uint32_t b1) {
    asm volatile(
        "mma.sync.aligned.m16n8k16.row.col.f32.f16.f16.f32 "
        "{%0,%1,%2,%3}, {%4,%5,%6,%7}, {%8,%9}, {%0,%1,%2,%3};"
        : "+f"(c[0]), "+f"(c[1]), "+f"(c[2]), "+f"(c[3])
        : "r"(a[0]), "r"(a[1]), "r"(a[2]), "r"(a[3]), "r"(b0), "r"(b1));
}

// ============== bias concat ==============
__global__ void concat_bias(const float* __restrict__ bq,
                            const float* __restrict__ bk,
                            const float* __restrict__ bv,
                            float* __restrict__ out)
{
    int i = blockIdx.x * 256 + threadIdx.x;
    if (i < QKV_N)
        out[i] = (i < 1536) ? bq[i] : (i < 3072 ? bk[i - 1536] : bv[i - 3072]);
}

// ============== operand pre-permute kernels ==============
// hi only — no consumer of A-lo remains (both GEMMs are 2-pass on A).
__global__ __launch_bounds__(256) void splitA_kernel(
    const float* __restrict__ A, uint4* __restrict__ hi)
{
    int gid = blockIdx.x * 256 + threadIdx.x;
    int tile = gid >> 5, lane = gid & 31;
    int mt = tile / TILEK, kt = tile - mt * TILEK;
    int g = lane >> 2, tg = lane & 3;
    U8h H;
#pragma unroll
    for (int s2 = 0; s2 < 4; s2++) {
        int reg = s2;
        int row = mt * 16 + g + ((reg & 1) << 3);
        int col = kt * 16 + ((reg & 2) << 2) + 2 * tg;
        float2 v = *(const float2*)&A[(size_t)row * DIM_C + col];
        H.h[s2 * 2]     = __float2half_rn(v.x);
        H.h[s2 * 2 + 1] = __float2half_rn(v.y);
    }
    hi[tile * 32 + lane] = H.v;
}

__global__ __launch_bounds__(256) void splitW4_kernel(
    const float* __restrict__ w0, const float* __restrict__ w1,
    const float* __restrict__ w2, const float* __restrict__ w3,
    uint4* __restrict__ hi, uint4* __restrict__ lo)
{
    int gid = blockIdx.x * 256 + threadIdx.x;
    int tile = gid >> 5, lane = gid & 31;
    int widx = tile / (TILEK * TILEK);
    int r = tile - widx * (TILEK * TILEK);
    int nt2 = r / TILEK, kt = r - nt2 * TILEK;
    const float* W = (widx == 0) ? w0 : (widx == 1) ? w1 : (widx == 2) ? w2 : w3;
    int g = lane >> 2, tg = lane & 3;
    U8h H, L;
#pragma unroll
    for (int s2 = 0; s2 < 4; s2++) {
        int j = s2 >> 1, reg = s2 & 1;
        int n = nt2 * 16 + j * 8 + g;
        int k = kt * 16 + reg * 8 + 2 * tg;
        float2 v = *(const float2*)&W[(size_t)n * DIM_C + k];
        __half ax = __float2half_rn(v.x), ay = __float2half_rn(v.y);
        H.h[s2 * 2]     = ax;
        H.h[s2 * 2 + 1] = ay;
        L.h[s2 * 2]     = __float2half_rn(v.x - __half2float(ax));
        L.h[s2 * 2 + 1] = __float2half_rn(v.y - __half2float(ay));
    }
    hi[tile * 32 + lane] = H.v;
    lo[tile * 32 + lane] = L.v;
}

// ============== GEMM: 2-pass hi/lo (AhiBhi + AhiBlo), 4-stage =============
#define STG_U4 2560          // A_hi 512 + B_hi 1024 + B_lo 1024
#define GEMM_SMEM (4 * STG_U4 * 16)   // 163840 B

__global__ __launch_bounds__(256, 1) void gemm_fp16t(
    const uint4* __restrict__ Ahi,
    const uint4* __restrict__ Bhi, const uint4* __restrict__ Blo,
    const float* __restrict__ bias, float* __restrict__ C, int N)
{
    extern __shared__ uint4 sm[];
    const int tid = threadIdx.x, wid = tid >> 5, lane = tid & 31;
    const int g = lane >> 2, tg = lane & 3;
    const int bm8  = blockIdx.y * 8;
    const int bn16 = blockIdx.x * 16;
    const int wmt = (wid >> 2) * 4;
    const int wnt = (wid & 3) * 4;

    float c[4][8][4];
#pragma unroll
    for (int i = 0; i < 4; i++)
#pragma unroll
        for (int j = 0; j < 8; j++)
#pragma unroll
            for (int t = 0; t < 4; t++) c[i][j][t] = 0.f;

#define LOAD_STAGE(slot, chunk) do {                                           \
    uint4* st = sm + (slot) * STG_U4;                                          \
    const int k2 = (chunk) * 2;                                                \
_Pragma("unroll")                                                              \
    for (int a = 0; a < 2; a++) {                                              \
        int idx = tid + a * 256;                                               \
        int ln = idx & 31, kt = (idx >> 5) & 1, mt = (idx >> 6) & 7;           \
        const uint4* src = Ahi                                                 \
            + ((size_t)(bm8 + mt) * TILEK + k2 + kt) * 32 + ln;                \
        cp16(smem_u32(st + mt * 64 + kt * 32 + ln), src);                      \
    }                                                                          \
_Pragma("unroll")                                                              \
    for (int b = 0; b < 8; b++) {                                              \
        int idx = tid + b * 256;                                               \
        int ln = idx & 31, kt = (idx >> 5) & 1, nt = (idx >> 6) & 15;          \
        int hl = idx >> 10;                                                    \
        const uint4* src = (hl ? Blo : Bhi)                                    \
            + ((size_t)(bn16 + nt) * TILEK + k2 + kt) * 32 + ln;               \
        cp16(smem_u32(st + 512 + hl * 1024 + nt * 64 + kt * 32 + ln), src);    \
    }                                                                          \
    CP_COMMIT();                                                               \
} while (0)

    const int NC = TILEK / 2;   // 48
    LOAD_STAGE(0, 0);
    LOAD_STAGE(1, 1);
    LOAD_STAGE(2, 2);

    for (int ck = 0; ck < NC; ck++) {
        const int slot = ck & 3;
        if (ck + 3 < NC) { CP_WAIT(2); } else { CP_WAIT(0); }
        __syncthreads();
        if (ck + 3 < NC) LOAD_STAGE((ck + 3) & 3, ck + 3);

        const uint4* st = sm + slot * STG_U4;
#pragma unroll
        for (int kt = 0; kt < 2; kt++) {
            uint4 Ah[4], Bh[4], Bl[4];
#pragma unroll
            for (int i = 0; i < 4; i++)
                Ah[i] = st[(wmt + i) * 64 + kt * 32 + lane];
#pragma unroll
            for (int j = 0; j < 4; j++) {
                Bh[j] = st[512  + (wnt + j) * 64 + kt * 32 + lane];
                Bl[j] = st[1536 + (wnt + j) * 64 + kt * 32 + lane];
            }
#pragma unroll
            for (int i = 0; i < 4; i++) {
                uint32_t ah[4] = {Ah[i].x, Ah[i].y, Ah[i].z, Ah[i].w};
#pragma unroll
                for (int j = 0; j < 4; j++) {
                    mma16816(c[i][j*2],   ah, Bh[j].x, Bh[j].y);
                    mma16816(c[i][j*2+1], ah, Bh[j].z, Bh[j].w);
                    mma16816(c[i][j*2],   ah, Bl[j].x, Bl[j].y);
                    mma16816(c[i][j*2+1], ah, Bl[j].z, Bl[j].w);
                }
            }
        }
    }

#pragma unroll
    for (int i = 0; i < 4; i++) {
        int row0 = (bm8 + wmt + i) * 16 + g;
#pragma unroll
        for (int j = 0; j < 8; j++) {
            int col = (bn16 + wnt + (j >> 1)) * 16 + (j & 1) * 8 + 2 * tg;
            float b0 = bias[col], b1 = bias[col + 1];
            float2 v0 = make_float2(c[i][j][0] + b0, c[i][j][1] + b1);
            float2 v1 = make_float2(c[i][j][2] + b0, c[i][j][3] + b1);
            *(float2*)&C[(size_t)row0 * N + col] = v0;
            *(float2*)&C[(size_t)(row0 + 8) * N + col] = v1;
        }
    }
}

// ---------------- fused RMSNorm + RoPE -> frag-layout fp16 Q / K ------------
__global__ __launch_bounds__(256) void normrope_kernel(
    const float* __restrict__ qkv,
    const float* __restrict__ freqs,
    const float* __restrict__ nqw, const float* __restrict__ nkw,
    uint4* __restrict__ qA, uint4* __restrict__ kB)
{
    const int t = blockIdx.x;
    const int f  = t / FS_C;
    const int rm = t % FS_C;
    const int hh = rm / W_C;
    const int ww = rm % W_C;
    const int tid = threadIdx.x;
    const int grp = tid >> 7;
    const int gt  = tid & 127;

    __shared__ float fr[64], fi[64];
    __shared__ float red[8];

    if (tid < 64) {
        int c = tid;
        int row = (c < 22) ? f : ((c < 43) ? hh : ww);
        fr[c] = freqs[row * 128 + c * 2 + 0];
        fi[c] = freqs[row * 128 + c * 2 + 1];
    }

    const float* ptr = qkv + (size_t)t * QKV_N + grp * 1536;
    const float* w = grp ? nkw : nqw;
    uint4* frag = grp ? kB : qA;

    float v[12], wv[12];
    const int c0 = gt * 12;
#pragma unroll
    for (int j = 0; j < 3; j++) {
        float4 a = *(const float4*)&ptr[c0 + j * 4];
        float4 b = *(const float4*)&w[c0 + j * 4];
        v[j*4+0] = a.x; v[j*4+1] = a.y; v[j*4+2] = a.z; v[j*4+3] = a.w;
        wv[j*4+0] = b.x; wv[j*4+1] = b.y; wv[j*4+2] = b.z; wv[j*4+3] = b.w;
    }
    float ss = 0.f;
#pragma unroll
    for (int j = 0; j < 12; j++) ss += v[j] * v[j];
    {
        int lane = tid & 31, wd = tid >> 5;
#pragma unroll
        for (int o = 16; o > 0; o >>= 1) ss += __shfl_xor_sync(0xffffffffu, ss, o);
        if (lane == 0) red[wd] = ss;
    }
    __syncthreads();
    float tot = red[grp * 4 + 0] + red[grp * 4 + 1]
              + red[grp * 4 + 2] + red[grp * 4 + 3];
    float rn = rsqrtf(tot * (1.0f / DIM_C) + EPS_C);

    const int t16 = t >> 4;
    const int bit = (t >> 3) & 1;
    const int gg  = t & 7;

#pragma unroll
    for (int j = 0; j < 6; j++) {
        int p = gt * 6 + j;
        int c = 2 * p;
        int cf = p & 63;
        float a = v[2*j]     * rn * wv[2*j];
        float b = v[2*j + 1] * rn * wv[2*j + 1];
        __half2 hv = __floats2half2_rn(a * fr[cf] - b * fi[cf],
                                       a * fi[cf] + b * fr[cf]);
        int h = c >> 7, ch = c & 127;
        int kt = ch >> 4, low = ch & 15;
        int colbit = low >> 3, tg = (low >> 1) & 3;
        int lane = gg * 4 + tg;
        int byteoff = grp ? (bit * 8 + colbit * 4) : (bit * 4 + colbit * 8);
        char* dst = (char*)frag
            + (size_t)(h * 1536 + t16 * 8 + kt) * 512 + lane * 16 + byteoff;
        *(__half2*)dst = hv;
    }
}

// ================= V fragment conversion (smem-staged, coalesced) ==========
__global__ __launch_bounds__(256) void convV_kernel(
    const float* __restrict__ qkv, uint4* __restrict__ hi, uint4* __restrict__ lo)
{
    __shared__ float vs[16 * 132];
    const int b = blockIdx.x;
    const int h = b / 192, kt = b - h * 192;
    const int tid = threadIdx.x;
    const float* V = qkv + 3072 + (size_t)kt * 16 * QKV_N + h * HD_C;

#pragma unroll
    for (int it = 0; it < 2; it++) {
        int idx = tid + it * 256;
        int row = idx >> 5, col4 = idx & 31;
        float4 x = *(const float4*)&V[(size_t)row * QKV_N + col4 * 4];
        *(float4*)&vs[row * 132 + col4 * 4] = x;
    }
    __syncthreads();

    const int nt2 = tid >> 5, lane = tid & 31;
    const int g = lane >> 2, tg = lane & 3;
    U8h H, L;
#pragma unroll
    for (int s2 = 0; s2 < 4; s2++) {
        int j = s2 >> 1, reg = s2 & 1;
        int dim = nt2 * 16 + j * 8 + g;
        int key = reg * 8 + 2 * tg;
        float va = vs[key * 132 + dim];
        float vb = vs[(key + 1) * 132 + dim];
        __half ax = __float2half_rn(va), ay = __float2half_rn(vb);
        H.h[s2 * 2]     = ax;
        H.h[s2 * 2 + 1] = ay;
        L.h[s2 * 2]     = __float2half_rn(va - __half2float(ax));
        L.h[s2 * 2 + 1] = __float2half_rn(vb - __half2float(ay));
    }
    size_t tile = (size_t)h * 1536 + nt2 * 192 + kt;
    hi[tile * 32 + lane] = H.v;
    lo[tile * 32 + lane] = L.v;
}

// ================= tensor-core flash attention (cp.async double-buffer) =====
#define ATTN_SMEM (2 * 3 * 1024 * 16)

__global__ __launch_bounds__(256) void attn_fp16(
    const uint4* __restrict__ qA, const uint4* __restrict__ kB,
    const uint4* __restrict__ vHi, const uint4* __restrict__ vLo,
    uint4* __restrict__ aHi)
{
    extern __shared__ uint4 smA[];
    const int bi = blockIdx.x;
    const int h  = bi % HEADS_C;
    const int qb = QBMAP[bi / HEADS_C];
    const int tid = threadIdx.x, wid = tid >> 5, lane = tid & 31;
    const int mt = qb * 8 + wid;
    const float scale = 0.08838834764831844f;

    uint32_t qf_[8][4];
#pragma unroll
    for (int kt = 0; kt < 8; kt++) {
        uint4 qv = qA[((size_t)(h * 192 + mt) * 8 + kt) * 32 + lane];
        qf_[kt][0] = qv.x; qf_[kt][1] = qv.y; qf_[kt][2] = qv.z; qf_[kt][3] = qv.w;
    }

    float oacc[16][4];
#pragma unroll
    for (int i = 0; i < 16; i++)
#pragma unroll
        for (int j = 0; j < 4; j++) oacc[i][j] = 0.f;
    float m0 = -1e30f, m1 = -1e30f, l0 = 0.f, l1 = 0.f;

    const int qfr   = qb / 3;
    const int sinkT = (qfr >= 5) ? 6 : 0;
    const int mainF = (qfr >= 5) ? (qfr - 4) * 6 : 0;
    const int mainT = (qfr >= 5) ? 30 : (qfr + 1) * 6;
    const int ntile = sinkT + mainT;

#define ATTN_LOAD(buf, kt0) do {                                               \
    uint4* bb = smA + (buf) * 3072;                                            \
    const uint4* kbase = kB + ((size_t)(h * 192 + (kt0) * 4) * 8) * 32;        \
_Pragma("unroll")                                                              \
    for (int j = 0; j < 4; j++) {                                              \
        int idx = tid + j * 256;                                               \
        cp16(smem_u32(bb + idx), kbase + idx);                                 \
    }                                                                          \
_Pragma("unroll")                                                              \
    for (int j = 0; j < 4; j++) {                                              \
        int idx = tid + j * 256;                                               \
        int nt2 = idx >> 7, rem = idx & 127, jj = rem >> 5, ln = rem & 31;     \
        size_t a = ((size_t)(h * 8 + nt2) * 192 + (kt0) * 4 + jj) * 32 + ln;   \
        cp16(smem_u32(bb + 1024 + idx), vHi + a);                              \
        cp16(smem_u32(bb + 2048 + idx), vLo + a);                              \
    }                                                                          \
    CP_COMMIT();                                                               \
} while (0)

    {
        const int kt0 = (0 < sinkT) ? 0 : mainF;
        ATTN_LOAD(0, kt0);
    }

    for (int t = 0; t < ntile; t++) {
        __syncthreads();
        if (t + 1 < ntile) {
            const int ktn = (t + 1 < sinkT) ? (t + 1) : mainF + (t + 1 - sinkT);
            ATTN_LOAD((t + 1) & 1, ktn);
            CP_WAIT(1);
        } else {
            CP_WAIT(0);
        }
        __syncthreads();

        const uint4* Ks = smA + (t & 1) * 3072;
        const uint4* Vh = Ks + 1024;
        const uint4* Vl = Ks + 2048;

        float sacc[8][4];
#pragma unroll
        for (int i = 0; i < 8; i++)
#pragma unroll
            for (int j = 0; j < 4; j++) sacc[i][j] = 0.f;

#pragma unroll
        for (int kt = 0; kt < 8; kt++) {
#pragma unroll
            for (int n2 = 0; n2 < 4; n2++) {
                uint4 b = Ks[(n2 * 8 + kt) * 32 + lane];
                mma16816(sacc[n2*2],   qf_[kt], b.x, b.y);
                mma16816(sacc[n2*2+1], qf_[kt], b.z, b.w);
            }
        }

        float rm0 = -1e30f, rm1 = -1e30f;
#pragma unroll
        for (int nt = 0; nt < 8; nt++) {
            sacc[nt][0] *= scale; sacc[nt][1] *= scale;
            sacc[nt][2] *= scale; sacc[nt][3] *= scale;
            rm0 = fmaxf(rm0, fmaxf(sacc[nt][0], sacc[nt][1]));
            rm1 = fmaxf(rm1, fmaxf(sacc[nt][2], sacc[nt][3]));
        }
        rm0 = fmaxf(rm0, __shfl_xor_sync(0xffffffffu, rm0, 1));
        rm0 = fmaxf(rm0, __shfl_xor_sync(0xffffffffu, rm0, 2));
        rm1 = fmaxf(rm1, __shfl_xor_sync(0xffffffffu, rm1, 1));
        rm1 = fmaxf(rm1, __shfl_xor_sync(0xffffffffu, rm1, 2));

        float mn0 = fmaxf(m0, rm0), mn1 = fmaxf(m1, rm1);
        float al0 = __expf(m0 - mn0), al1 = __expf(m1 - mn1);
        m0 = mn0; m1 = mn1;

        float rs0 = 0.f, rs1 = 0.f;
        uint32_t ph0[8], ph1[8];
#pragma unroll
        for (int nt = 0; nt < 8; nt++) {
            float e0 = __expf(sacc[nt][0] - mn0);
            float e1 = __expf(sacc[nt][1] - mn0);
            float e2 = __expf(sacc[nt][2] - mn1);
            float e3 = __expf(sacc[nt][3] - mn1);
            rs0 += e0 + e1; rs1 += e2 + e3;
            __half2 p0 = __floats2half2_rn(e0, e1);
            __half2 p1 = __floats2half2_rn(e2, e3);
            ph0[nt] = *(uint32_t*)&p0;
            ph1[nt] = *(uint32_t*)&p1;
        }
        rs0 += __shfl_xor_sync(0xffffffffu, rs0, 1);
        rs0 += __shfl_xor_sync(0xffffffffu, rs0, 2);
        rs1 += __shfl_xor_sync(0xffffffffu, rs1, 1);
        rs1 += __shfl_xor_sync(0xffffffffu, rs1, 2);
        l0 = l0 * al0 + rs0;
        l1 = l1 * al1 + rs1;

#pragma unroll
        for (int nt = 0; nt < 16; nt++) {
            oacc[nt][0] *= al0; oacc[nt][1] *= al0;
            oacc[nt][2] *= al1; oacc[nt][3] *= al1;
        }

#pragma unroll
        for (int ks = 0; ks < 4; ks++) {
            uint32_t A_[4] = {ph0[2*ks], ph1[2*ks], ph0[2*ks+1], ph1[2*ks+1]};
#pragma unroll
            for (int n2 = 0; n2 < 8; n2++) {
                uint4 bh = Vh[(n2 * 4 + ks) * 32 + lane];
                mma16816(oacc[n2*2],   A_, bh.x, bh.y);
                mma16816(oacc[n2*2+1], A_, bh.z, bh.w);
                uint4 bl = Vl[(n2 * 4 + ks) * 32 + lane];
                mma16816(oacc[n2*2],   A_, bl.x, bl.y);
                mma16816(oacc[n2*2+1], A_, bl.z, bl.w);
            }
        }
    }

    // epilogue: hi-frags only (out-proj is 2-pass on A)
    float inv0 = 1.f / l0, inv1 = 1.f / l1;
#pragma unroll
    for (int nt2 = 0; nt2 < 8; nt2++) {
        U8h H;
        H.h[0] = __float2half_rn(oacc[nt2*2][0]   * inv0);
        H.h[1] = __float2half_rn(oacc[nt2*2][1]   * inv0);
        H.h[2] = __float2half_rn(oacc[nt2*2][2]   * inv1);
        H.h[3] = __float2half_rn(oacc[nt2*2][3]   * inv1);
        H.h[4] = __float2half_rn(oacc[nt2*2+1][0] * inv0);
        H.h[5] = __float2half_rn(oacc[nt2*2+1][1] * inv0);
        H.h[6] = __float2half_rn(oacc[nt2*2+1][2] * inv1);
        H.h[7] = __float2half_rn(oacc[nt2*2+1][3] * inv1);
        size_t tt = ((size_t)mt * TILEK + h * 8 + nt2) * 32 + lane;
        aHi[tt] = H.v;
    }
}

// ---------------- launch ----------------
extern "C" void kernel_launch(void* const* d_in, const int* in_sizes, int n_in,
                              void* d_out, int out_size)
{
    const float* x     = (const float*)d_in[0];
    const float* freqs = (const float*)d_in[3];
    const float* wq    = (const float*)d_in[4];
    const float* bq    = (const float*)d_in[5];
    const float* wk    = (const float*)d_in[6];
    const float* bk    = (const float*)d_in[7];
    const float* wv    = (const float*)d_in[8];
    const float* bv    = (const float*)d_in[9];
    const float* wo    = (const float*)d_in[10];
    const float* bo    = (const float*)d_in[11];
    const float* nqw   = (const float*)d_in[12];
    const float* nkw   = (const float*)d_in[13];
    float* out = (float*)d_out;

    float *qkv, *bias;
    uint4 *xhi, *whi, *wlo, *qA, *kB, *vHi, *vLo;
    cudaGetSymbolAddress((void**)&qkv,  g_qkv);
    cudaGetSymbolAddress((void**)&bias, g_bias);
    cudaGetSymbolAddress((void**)&xhi, g_xhi);
    cudaGetSymbolAddress((void**)&whi, g_whi);
    cudaGetSymbolAddress((void**)&wlo, g_wlo);
    cudaGetSymbolAddress((void**)&qA,  g_qA);
    cudaGetSymbolAddress((void**)&kB,  g_kB);
    cudaGetSymbolAddress((void**)&vHi, g_vHi);
    cudaGetSymbolAddress((void**)&vLo, g_vLo);

    cudaFuncSetAttribute(gemm_fp16t,
                         cudaFuncAttributeMaxDynamicSharedMemorySize, GEMM_SMEM);
    cudaFuncSetAttribute(attn_fp16,
                         cudaFuncAttributeMaxDynamicSharedMemorySize, ATTN_SMEM);

    const int blkA = L_TOK * DIM_C / 8 / 256;       // 2304
    const int blkW = 4 * DIM_C * DIM_C / 8 / 256;   // 4608

    splitA_kernel<<<blkA, 256>>>(x, xhi);
    splitW4_kernel<<<blkW, 256>>>(wq, wk, wv, wo, whi, wlo);
    concat_bias<<<(QKV_N + 255) / 256, 256>>>(bq, bk, bv, bias);

    dim3 gqkv(QKV_N / 256, L_TOK / 128);            // (18, 24)
    gemm_fp16t<<<gqkv, 256, GEMM_SMEM>>>(xhi, whi, wlo, bias, qkv, QKV_N);

    normrope_kernel<<<L_TOK, 256>>>(qkv, freqs, nqw, nkw, qA, kB);
    convV_kernel<<<HEADS_C * 192, 256>>>(qkv, vHi, vLo);

    attn_fp16<<<(L_TOK / 128) * HEADS_C, 256, ATTN_SMEM>>>(qA, kB, vHi, vLo, xhi);

    dim3 gout(DIM_C / 256, L_TOK / 128);            // (6, 24)
    gemm_fp16t<<<gout, 256, GEMM_SMEM>>>(xhi, whi + 3 * WTSZ, wlo + 3 * WTSZ, bo, out, DIM_C);
}